// round 3
// baseline (speedup 1.0000x reference)
#include <cuda_runtime.h>
#include <cuda_bf16.h>
#include <math.h>

// ---------------- problem constants ----------------
#define B_     2
#define I_     2048
#define J_     2048
#define DIM_   1024
#define H_     16
#define DH_    64
#define INNER_ 1024
#define EPS_   1e-5f
#define SCALE_ 0.125f   // DH^-0.5

// ---------------- scratch (device globals; allocation-free) ----------------
__device__ float g_xn [B_ * I_ * DIM_];
__device__ float g_cn [B_ * J_ * DIM_];
__device__ float g_qk [B_ * I_ * INNER_];
__device__ float g_cqk[B_ * J_ * INNER_];
__device__ float g_v  [B_ * I_ * INNER_];
__device__ float g_cv [B_ * J_ * INNER_];
__device__ float g_sim  [134217728];         // [B,H,I,J] 512 MB
__device__ float g_attn [134217728];
__device__ float g_cattn[134217728];
__device__ float g_rm[B_ * H_ * I_];
__device__ float g_rs[B_ * H_ * I_];
__device__ float g_cm[B_ * H_ * J_];
__device__ float g_cs[B_ * H_ * J_];
__device__ float g_o1[B_ * I_ * INNER_];
__device__ float g_o2[B_ * J_ * INNER_];

// ---------------- LayerNorm ----------------
__global__ void ln_kernel(const float* __restrict__ x,
                          const float* __restrict__ gw,
                          const float* __restrict__ bw,
                          float* __restrict__ out) {
    int row = blockIdx.x;
    const float* xr = x + (size_t)row * DIM_;
    float* orow = out + (size_t)row * DIM_;
    int t = threadIdx.x;

    float v[4]; float s = 0.f, sq = 0.f;
#pragma unroll
    for (int k = 0; k < 4; k++) {
        v[k] = xr[t + 256 * k];
        s += v[k]; sq += v[k] * v[k];
    }
    __shared__ float sh[64];
#pragma unroll
    for (int o = 16; o > 0; o >>= 1) {
        s  += __shfl_down_sync(0xffffffffu, s,  o);
        sq += __shfl_down_sync(0xffffffffu, sq, o);
    }
    if ((t & 31) == 0) { sh[t >> 5] = s; sh[32 + (t >> 5)] = sq; }
    __syncthreads();
    if (t < 32) {
        float a  = (t < 8) ? sh[t]      : 0.f;
        float b2 = (t < 8) ? sh[32 + t] : 0.f;
#pragma unroll
        for (int o = 4; o > 0; o >>= 1) {
            a  += __shfl_down_sync(0xffffffffu, a,  o);
            b2 += __shfl_down_sync(0xffffffffu, b2, o);
        }
        if (t == 0) { sh[0] = a; sh[1] = b2; }
    }
    __syncthreads();
    float mu   = sh[0] * (1.f / DIM_);
    float var  = sh[1] * (1.f / DIM_) - mu * mu;
    float rstd = rsqrtf(var + EPS_);
#pragma unroll
    for (int k = 0; k < 4; k++) {
        int c = t + 256 * k;
        orow[c] = (v[k] - mu) * rstd * gw[c] + bw[c];
    }
}

// ================= bf16-split tensor-core GEMM =================
// C = alpha * A(.T) @ B(.T) (+bias), fp32 in/out, internal bf16 hi/lo split:
//   A ~= Ah + Al, B ~= Bh + Bl; C ~= AhBh + AhBl + AlBh (drop AlBl ~ 2^-16)
// mma.sync.aligned.m16n8k16.row.col.f32.bf16.bf16.f32

__device__ __forceinline__ void mma_bf16(float* c, const unsigned* a,
                                         const unsigned* b) {
    asm volatile(
        "mma.sync.aligned.m16n8k16.row.col.f32.bf16.bf16.f32 "
        "{%0,%1,%2,%3}, {%4,%5,%6,%7}, {%8,%9}, {%0,%1,%2,%3};\n"
        : "+f"(c[0]), "+f"(c[1]), "+f"(c[2]), "+f"(c[3])
        : "r"(a[0]), "r"(a[1]), "r"(a[2]), "r"(a[3]),
          "r"(b[0]), "r"(b[1]));
}

__device__ __forceinline__ unsigned packsplit(float x, float y, unsigned& lo) {
    __nv_bfloat16 hx = __float2bfloat16(x);
    __nv_bfloat16 hy = __float2bfloat16(y);
    float lx = x - __bfloat162float(hx);
    float ly = y - __bfloat162float(hy);
    __nv_bfloat162 l2 = __floats2bfloat162_rn(lx, ly);
    lo = *(unsigned*)&l2;
    __nv_bfloat162 h2 = __halves2bfloat162(hx, hy);
    return *(unsigned*)&h2;
}

__device__ __forceinline__ void split1(float x, __nv_bfloat16& h,
                                       __nv_bfloat16& l) {
    h = __float2bfloat16(x);
    l = __float2bfloat16(x - __bfloat162float(h));
}

// ATR=false: A[m][k] at A[m*lda+k];  ATR=true: A[k][m] at A[k*lda+m]
// BNMAJ=true: B[n][k] at B[n*ldb+k]; false: B[k][n] at B[k*ldb+n]
template <int BN, bool ATR, bool BNMAJ>
__device__ __forceinline__ void tgemm_body(const float* __restrict__ A, int lda,
                                           const float* __restrict__ B, int ldb,
                                           float* __restrict__ C, int ldc,
                                           int K, const float* __restrict__ bias,
                                           float alpha) {
    constexpr int BM = 128, BK = 16;
    constexpr int LDA = 24, LDB = 24;   // (row*12+col) bijective mod 32 -> no LDS conflicts
    constexpr int NT = BN / 16;         // n-tiles per warp (warp tile 32 x BN/2)

    __shared__ __align__(16) __nv_bfloat16 sAh[2][BM * LDA];
    __shared__ __align__(16) __nv_bfloat16 sAl[2][BM * LDA];
    __shared__ __align__(16) __nv_bfloat16 sBh[2][BN * LDB];
    __shared__ __align__(16) __nv_bfloat16 sBl[2][BN * LDB];

    const int t    = threadIdx.x;
    const int lane = t & 31, warp = t >> 5;
    const int gi = lane >> 2, gj = lane & 3;
    const int wm = (warp >> 1) * 32;        // 4 warps along m
    const int wn = (warp & 1) * (BN / 2);   // 2 warps along n
    const int m0 = blockIdx.y * BM;
    const int n0 = blockIdx.x * BN;

    float acc[2][NT][4];
#pragma unroll
    for (int a0 = 0; a0 < 2; a0++)
#pragma unroll
        for (int a1 = 0; a1 < NT; a1++)
#pragma unroll
            for (int a2 = 0; a2 < 4; a2++) acc[a0][a1][a2] = 0.f;

    float av[8], bv[8];

    auto gload = [&](int k0) {
        if (!ATR) {
            int ar = t >> 1, ac = (t & 1) * 8;
            const float* p = A + (size_t)(m0 + ar) * lda + k0 + ac;
            *(float4*)av       = *(const float4*)p;
            *(float4*)(av + 4) = *(const float4*)(p + 4);
        } else {
            int kr = t >> 4, mc = (t & 15) * 8;
            const float* p = A + (size_t)(k0 + kr) * lda + m0 + mc;
            *(float4*)av       = *(const float4*)p;
            *(float4*)(av + 4) = *(const float4*)(p + 4);
        }
        if (BNMAJ) {
            int nr = t >> 1, kc = (t & 1) * 8;
            const float* p = B + (size_t)(n0 + nr) * ldb + k0 + kc;
            *(float4*)bv       = *(const float4*)p;
            *(float4*)(bv + 4) = *(const float4*)(p + 4);
        } else if (BN == 128) {
            int kr = t >> 4, nc = (t & 15) * 8;
            const float* p = B + (size_t)(k0 + kr) * ldb + n0 + nc;
            *(float4*)bv       = *(const float4*)p;
            *(float4*)(bv + 4) = *(const float4*)(p + 4);
        } else {                          // BN==64
            if (t < 128) {
                int kr = t >> 3, nc = (t & 7) * 8;
                const float* p = B + (size_t)(k0 + kr) * ldb + n0 + nc;
                *(float4*)bv       = *(const float4*)p;
                *(float4*)(bv + 4) = *(const float4*)(p + 4);
            }
        }
    };

    auto sstore = [&](int buf) {
        if (!ATR) {
            int ar = t >> 1, ac = (t & 1) * 8;
            unsigned hp[4], lp[4];
#pragma unroll
            for (int q = 0; q < 4; q++) hp[q] = packsplit(av[2 * q], av[2 * q + 1], lp[q]);
            *(uint4*)&sAh[buf][ar * LDA + ac] = *(uint4*)hp;
            *(uint4*)&sAl[buf][ar * LDA + ac] = *(uint4*)lp;
        } else {
            int kr = t >> 4, mc = (t & 15) * 8;
#pragma unroll
            for (int q = 0; q < 8; q++) {
                __nv_bfloat16 h, l; split1(av[q], h, l);
                sAh[buf][(mc + q) * LDA + kr] = h;
                sAl[buf][(mc + q) * LDA + kr] = l;
            }
        }
        if (BNMAJ) {
            int nr = t >> 1, kc = (t & 1) * 8;
            unsigned hp[4], lp[4];
#pragma unroll
            for (int q = 0; q < 4; q++) hp[q] = packsplit(bv[2 * q], bv[2 * q + 1], lp[q]);
            *(uint4*)&sBh[buf][nr * LDB + kc] = *(uint4*)hp;
            *(uint4*)&sBl[buf][nr * LDB + kc] = *(uint4*)lp;
        } else if (BN == 128) {
            int kr = t >> 4, nc = (t & 15) * 8;
#pragma unroll
            for (int q = 0; q < 8; q++) {
                __nv_bfloat16 h, l; split1(bv[q], h, l);
                sBh[buf][(nc + q) * LDB + kr] = h;
                sBl[buf][(nc + q) * LDB + kr] = l;
            }
        } else {
            if (t < 128) {
                int kr = t >> 3, nc = (t & 7) * 8;
#pragma unroll
                for (int q = 0; q < 8; q++) {
                    __nv_bfloat16 h, l; split1(bv[q], h, l);
                    sBh[buf][(nc + q) * LDB + kr] = h;
                    sBl[buf][(nc + q) * LDB + kr] = l;
                }
            }
        }
    };

    gload(0);
    sstore(0);
    __syncthreads();
    int buf = 0;

    for (int k0 = 0; k0 < K; k0 += BK) {
        bool nxt = (k0 + BK) < K;
        if (nxt) gload(k0 + BK);

        unsigned aH[2][4], aL[2][4];
#pragma unroll
        for (int mt = 0; mt < 2; mt++) {
            int r = wm + mt * 16 + gi;
            aH[mt][0] = *(unsigned*)&sAh[buf][(r)     * LDA + 2 * gj];
            aH[mt][1] = *(unsigned*)&sAh[buf][(r + 8) * LDA + 2 * gj];
            aH[mt][2] = *(unsigned*)&sAh[buf][(r)     * LDA + 2 * gj + 8];
            aH[mt][3] = *(unsigned*)&sAh[buf][(r + 8) * LDA + 2 * gj + 8];
            aL[mt][0] = *(unsigned*)&sAl[buf][(r)     * LDA + 2 * gj];
            aL[mt][1] = *(unsigned*)&sAl[buf][(r + 8) * LDA + 2 * gj];
            aL[mt][2] = *(unsigned*)&sAl[buf][(r)     * LDA + 2 * gj + 8];
            aL[mt][3] = *(unsigned*)&sAl[buf][(r + 8) * LDA + 2 * gj + 8];
        }
        unsigned bH[NT][2], bL[NT][2];
#pragma unroll
        for (int nt = 0; nt < NT; nt++) {
            int n = wn + nt * 8 + gi;
            bH[nt][0] = *(unsigned*)&sBh[buf][n * LDB + 2 * gj];
            bH[nt][1] = *(unsigned*)&sBh[buf][n * LDB + 2 * gj + 8];
            bL[nt][0] = *(unsigned*)&sBl[buf][n * LDB + 2 * gj];
            bL[nt][1] = *(unsigned*)&sBl[buf][n * LDB + 2 * gj + 8];
        }
#pragma unroll
        for (int mt = 0; mt < 2; mt++)
#pragma unroll
            for (int nt = 0; nt < NT; nt++) {
                mma_bf16(acc[mt][nt], aH[mt], bH[nt]);
                mma_bf16(acc[mt][nt], aH[mt], bL[nt]);
                mma_bf16(acc[mt][nt], aL[mt], bH[nt]);
            }

        if (nxt) {
            sstore(buf ^ 1);
            __syncthreads();
            buf ^= 1;
        }
    }

#pragma unroll
    for (int mt = 0; mt < 2; mt++)
#pragma unroll
        for (int nt = 0; nt < NT; nt++) {
            int r = m0 + wm + mt * 16 + gi;
            int c = n0 + wn + nt * 8 + 2 * gj;
            float b0 = 0.f, b1 = 0.f;
            if (bias) { b0 = bias[c]; b1 = bias[c + 1]; }
            float2 v;
            v.x = acc[mt][nt][0] * alpha + b0;
            v.y = acc[mt][nt][1] * alpha + b1;
            *(float2*)&C[(size_t)r * ldc + c] = v;
            v.x = acc[mt][nt][2] * alpha + b0;
            v.y = acc[mt][nt][3] * alpha + b1;
            *(float2*)&C[(size_t)(r + 8) * ldc + c] = v;
        }
}

// projections / output projections: [M,1024] @ [1024,1024] (+bias)
__global__ void __launch_bounds__(256) k_proj(const float* __restrict__ A,
                                              const float* __restrict__ W,
                                              const float* __restrict__ bias,
                                              float* __restrict__ C) {
    tgemm_body<128, false, false>(A, 1024, W, 1024, C, 1024, 1024, bias, 1.0f);
}

// sim: per (b,h): C[i,j] = scale * sum_d Q[i,d] * K[j,d]   (B is [n=j][k=d])
__global__ void __launch_bounds__(256) k_sim() {
    int z = blockIdx.z, b = z >> 4, h = z & 15;
    tgemm_body<128, false, true>(
        g_qk  + (size_t)b * I_ * INNER_ + h * DH_, INNER_,
        g_cqk + (size_t)b * J_ * INNER_ + h * DH_, INNER_,
        g_sim + (size_t)z * I_ * J_, J_, DH_, nullptr, SCALE_);
}

// out: per (b,h): C[i,d] = sum_j attn[i,j] * ctx_v[j,d]
__global__ void __launch_bounds__(256) k_av() {
    int z = blockIdx.z, b = z >> 4, h = z & 15;
    tgemm_body<64, false, false>(
        g_attn + (size_t)z * I_ * J_, J_,
        g_cv + (size_t)b * J_ * INNER_ + h * DH_, INNER_,
        g_o1 + (size_t)b * I_ * INNER_ + h * DH_, INNER_,
        J_, nullptr, 1.0f);
}

// ctx_out: per (b,h): C[j,d] = sum_i cattn[i,j] * v[i,d]   (A transposed)
__global__ void __launch_bounds__(256) k_avt() {
    int z = blockIdx.z, b = z >> 4, h = z & 15;
    tgemm_body<64, true, false>(
        g_cattn + (size_t)z * I_ * J_, J_,
        g_v  + (size_t)b * I_ * INNER_ + h * DH_, INNER_,
        g_o2 + (size_t)b * J_ * INNER_ + h * DH_, INNER_,
        I_, nullptr, 1.0f);
}

// ---------------- row stats ----------------
__global__ void rowstat_kernel() {
    size_t row = blockIdx.x;
    const float* sr = g_sim + row * (size_t)J_;
    int t = threadIdx.x;
    float v[8]; float mx = -1e30f;
#pragma unroll
    for (int k = 0; k < 8; k++) { v[k] = sr[t + 256 * k]; mx = fmaxf(mx, v[k]); }
    __shared__ float sh[8];
    __shared__ float smax;
#pragma unroll
    for (int o = 16; o > 0; o >>= 1)
        mx = fmaxf(mx, __shfl_xor_sync(0xffffffffu, mx, o));
    if ((t & 31) == 0) sh[t >> 5] = mx;
    __syncthreads();
    if (t == 0) {
        float m = sh[0];
        for (int q = 1; q < 8; q++) m = fmaxf(m, sh[q]);
        smax = m;
    }
    __syncthreads();
    mx = smax;
    float s = 0.f;
#pragma unroll
    for (int k = 0; k < 8; k++) s += __expf(v[k] - mx);
#pragma unroll
    for (int o = 16; o > 0; o >>= 1)
        s += __shfl_xor_sync(0xffffffffu, s, o);
    if ((t & 31) == 0) sh[t >> 5] = s;
    __syncthreads();
    if (t == 0) {
        float a = 0.f;
        for (int q = 0; q < 8; q++) a += sh[q];
        g_rm[row] = mx;
        g_rs[row] = 1.f / a;
    }
}

// ---------------- col stats ----------------
__global__ void colstat_kernel() {
    int z  = blockIdx.y;
    int j0 = blockIdx.x * 32;
    const float* S = g_sim + (size_t)z * I_ * J_;
    int t = threadIdx.x;
    int c = t & 31, p = t >> 5;

    float m = -1e30f, s = 0.f;
    for (int i = p; i < I_; i += 8) {
        float x = S[(size_t)i * J_ + j0 + c];
        float nm = fmaxf(m, x);
        s = s * __expf(m - nm) + __expf(x - nm);
        m = nm;
    }
    __shared__ float shm[8][33], shs[8][33];
    shm[p][c] = m; shs[p][c] = s;
    __syncthreads();
    if (p == 0) {
        float M = m, Sv = s;
#pragma unroll
        for (int q = 1; q < 8; q++) {
            float m2 = shm[q][c], s2 = shs[q][c];
            float nm = fmaxf(M, m2);
            Sv = Sv * __expf(M - nm) + s2 * __expf(m2 - nm);
            M = nm;
        }
        g_cm[(size_t)z * J_ + j0 + c] = M;
        g_cs[(size_t)z * J_ + j0 + c] = 1.f / Sv;
    }
}

// ------- fused softmax-normalize + talking-heads mix (both directions) ----
__global__ void mix_kernel(const float* __restrict__ thw,
                           const float* __restrict__ cthw) {
    int b = blockIdx.z;
    int i = blockIdx.y;
    int j = blockIdx.x * 256 + threadIdx.x;
    int t = threadIdx.x;

    __shared__ float wR[16][16], wC[16][16], rm[16], ri[16];
    wR[t >> 4][t & 15] = thw[t];
    wC[t >> 4][t & 15] = cthw[t];
    if (t < 16) {
        rm[t] = g_rm[((size_t)(b * H_ + t)) * I_ + i];
        ri[t] = g_rs[((size_t)(b * H_ + t)) * I_ + i];
    }
    __syncthreads();

    float pr[16], pc[16];
#pragma unroll
    for (int h = 0; h < 16; h++) {
        size_t zi = (size_t)(b * H_ + h);
        float sv = g_sim[(zi * I_ + i) * J_ + j];
        pr[h] = __expf(sv - rm[h]) * ri[h];
        float cm = g_cm[zi * J_ + j];
        float ci = g_cs[zi * J_ + j];
        pc[h] = __expf(sv - cm) * ci;
    }
#pragma unroll
    for (int g = 0; g < 16; g++) {
        float aR = 0.f, aC = 0.f;
#pragma unroll
        for (int h = 0; h < 16; h++) {
            aR += wR[g][h] * pr[h];
            aC += wC[g][h] * pc[h];
        }
        size_t zo = (size_t)(b * H_ + g);
        g_attn [(zo * I_ + i) * J_ + j] = aR;
        g_cattn[(zo * I_ + i) * J_ + j] = aC;
    }
}

// ---------------- launch ----------------
extern "C" void kernel_launch(void* const* d_in, const int* in_sizes, int n_in,
                              void* d_out, int out_size) {
    const float* x     = (const float*)d_in[0];
    const float* ctx   = (const float*)d_in[1];
    const float* ln_g  = (const float*)d_in[2];
    const float* ln_b  = (const float*)d_in[3];
    const float* cln_g = (const float*)d_in[4];
    const float* cln_b = (const float*)d_in[5];
    const float* W_qk  = (const float*)d_in[6];
    const float* W_cqk = (const float*)d_in[7];
    const float* W_v   = (const float*)d_in[8];
    const float* W_cv  = (const float*)d_in[9];
    const float* W_out = (const float*)d_in[10];
    const float* b_out = (const float*)d_in[11];
    const float* W_cout= (const float*)d_in[12];
    const float* b_cout= (const float*)d_in[13];
    const float* thw   = (const float*)d_in[14];
    const float* cthw  = (const float*)d_in[15];
    float* out = (float*)d_out;

    float *p_xn, *p_cn, *p_qk, *p_cqk, *p_v, *p_cv, *p_o1, *p_o2;
    cudaGetSymbolAddress((void**)&p_xn,  g_xn);
    cudaGetSymbolAddress((void**)&p_cn,  g_cn);
    cudaGetSymbolAddress((void**)&p_qk,  g_qk);
    cudaGetSymbolAddress((void**)&p_cqk, g_cqk);
    cudaGetSymbolAddress((void**)&p_v,   g_v);
    cudaGetSymbolAddress((void**)&p_cv,  g_cv);
    cudaGetSymbolAddress((void**)&p_o1,  g_o1);
    cudaGetSymbolAddress((void**)&p_o2,  g_o2);

    // 1) layernorms
    ln_kernel<<<B_ * I_, 256>>>(x,   ln_g,  ln_b,  p_xn);
    ln_kernel<<<B_ * J_, 256>>>(ctx, cln_g, cln_b, p_cn);

    // 2) projections: [4096,1024] @ [1024,1024], 128x128 tensor tiles
    dim3 gp(DIM_ / 128, (B_ * I_) / 128);
    k_proj<<<gp, 256>>>(p_xn, W_qk,  nullptr, p_qk);
    k_proj<<<gp, 256>>>(p_xn, W_v,   nullptr, p_v);
    k_proj<<<gp, 256>>>(p_cn, W_cqk, nullptr, p_cqk);
    k_proj<<<gp, 256>>>(p_cn, W_cv,  nullptr, p_cv);

    // 3) sim = Q @ K^T * scale, batched over (b,h)
    k_sim<<<dim3(J_ / 128, I_ / 128, B_ * H_), 256>>>();

    // 4) softmax statistics
    rowstat_kernel<<<B_ * H_ * I_, 256>>>();
    colstat_kernel<<<dim3(J_ / 32, B_ * H_), 256>>>();

    // 5) fused normalize + talking-heads mix
    mix_kernel<<<dim3(J_ / 256, I_, B_), 256>>>(thw, cthw);

    // 6) attention-weighted values
    k_av <<<dim3(1, I_ / 128, B_ * H_), 256>>>();
    k_avt<<<dim3(1, J_ / 128, B_ * H_), 256>>>();

    // 7) output projections straight into d_out
    k_proj<<<gp, 256>>>(p_o1, W_out,  b_out,  out);
    k_proj<<<gp, 256>>>(p_o2, W_cout, b_cout, out + (size_t)B_ * I_ * DIM_);
}

// round 4
// speedup vs baseline: 1.8824x; 1.8824x over previous
#include <cuda_runtime.h>
#include <cuda_bf16.h>
#include <math.h>

typedef __nv_bfloat16 bf16;

// ---------------- problem constants ----------------
#define B_     2
#define I_     2048
#define J_     2048
#define DIM_   1024
#define H_     16
#define DH_    64
#define INNER_ 1024
#define EPS_   1e-5f
#define SCALE_ 0.125f   // DH^-0.5
#define SIMN   134217728   // B*H*I*J

// ---------------- scratch (device globals; allocation-free) ----------------
__device__ bf16 g_xnh[B_ * I_ * DIM_],  g_xnl[B_ * I_ * DIM_];
__device__ bf16 g_cnh[B_ * J_ * DIM_],  g_cnl[B_ * J_ * DIM_];
__device__ bf16 g_qkh[B_ * I_ * INNER_], g_qkl[B_ * I_ * INNER_];
__device__ bf16 g_ckh[B_ * J_ * INNER_], g_ckl[B_ * J_ * INNER_];
__device__ bf16 g_vh [B_ * I_ * INNER_], g_vl [B_ * I_ * INNER_];
__device__ bf16 g_cvh[B_ * J_ * INNER_], g_cvl[B_ * J_ * INNER_];
__device__ bf16 g_o1h[B_ * I_ * INNER_], g_o1l[B_ * I_ * INNER_];
__device__ bf16 g_o2h[B_ * J_ * INNER_], g_o2l[B_ * J_ * INNER_];
__device__ bf16 g_wh[6][DIM_ * INNER_], g_wl[6][DIM_ * INNER_];
__device__ float g_sim[SIMN];                       // 512 MB fp32
__device__ bf16 g_ath[SIMN], g_atl[SIMN];           // attn planes
__device__ bf16 g_cth[SIMN], g_ctl[SIMN];           // ctx attn planes
__device__ float g_rm[B_ * H_ * I_], g_rs[B_ * H_ * I_];
__device__ float g_cm[B_ * H_ * J_], g_cs[B_ * H_ * J_];

// ---------------- helpers ----------------
__device__ __forceinline__ unsigned packsplit(float x, float y, unsigned& lo) {
    bf16 hx = __float2bfloat16(x);
    bf16 hy = __float2bfloat16(y);
    float lx = x - __bfloat162float(hx);
    float ly = y - __bfloat162float(hy);
    __nv_bfloat162 l2 = __floats2bfloat162_rn(lx, ly);
    lo = *(unsigned*)&l2;
    __nv_bfloat162 h2 = __halves2bfloat162(hx, hy);
    return *(unsigned*)&h2;
}
__device__ __forceinline__ void split1(float x, bf16& h, bf16& l) {
    h = __float2bfloat16(x);
    l = __float2bfloat16(x - __bfloat162float(h));
}
__device__ __forceinline__ void mma_bf16(float* c, const unsigned* a,
                                         const unsigned* b) {
    asm volatile(
        "mma.sync.aligned.m16n8k16.row.col.f32.bf16.bf16.f32 "
        "{%0,%1,%2,%3}, {%4,%5,%6,%7}, {%8,%9}, {%0,%1,%2,%3};\n"
        : "+f"(c[0]), "+f"(c[1]), "+f"(c[2]), "+f"(c[3])
        : "r"(a[0]), "r"(a[1]), "r"(a[2]), "r"(a[3]), "r"(b[0]), "r"(b[1]));
}
__device__ __forceinline__ void ldsm4(unsigned* d, unsigned a) {
    asm volatile("ldmatrix.sync.aligned.m8n8.x4.shared.b16 {%0,%1,%2,%3},[%4];\n"
                 : "=r"(d[0]), "=r"(d[1]), "=r"(d[2]), "=r"(d[3]) : "r"(a));
}
__device__ __forceinline__ void ldsm4t(unsigned* d, unsigned a) {
    asm volatile("ldmatrix.sync.aligned.m8n8.x4.trans.shared.b16 {%0,%1,%2,%3},[%4];\n"
                 : "=r"(d[0]), "=r"(d[1]), "=r"(d[2]), "=r"(d[3]) : "r"(a));
}
__device__ __forceinline__ void cp16(void* smp, const void* gp) {
    unsigned sa = (unsigned)__cvta_generic_to_shared(smp);
    asm volatile("cp.async.cg.shared.global [%0], [%1], 16;\n" :: "r"(sa), "l"(gp));
}
__device__ __forceinline__ unsigned shaddr(const void* p) {
    return (unsigned)__cvta_generic_to_shared(p);
}

// ---------------- LayerNorm -> bf16 hi/lo planes ----------------
__global__ void ln_kernel(const float* __restrict__ x,
                          const float* __restrict__ gw,
                          const float* __restrict__ bw,
                          bf16* __restrict__ oh, bf16* __restrict__ ol) {
    int row = blockIdx.x;
    const float* xr = x + (size_t)row * DIM_;
    int t = threadIdx.x;
    int c = t * 4;

    float4 v = *(const float4*)(xr + c);
    float s = v.x + v.y + v.z + v.w;
    float sq = v.x * v.x + v.y * v.y + v.z * v.z + v.w * v.w;
    __shared__ float sh[64];
#pragma unroll
    for (int o = 16; o > 0; o >>= 1) {
        s  += __shfl_down_sync(0xffffffffu, s,  o);
        sq += __shfl_down_sync(0xffffffffu, sq, o);
    }
    if ((t & 31) == 0) { sh[t >> 5] = s; sh[32 + (t >> 5)] = sq; }
    __syncthreads();
    if (t < 32) {
        float a  = (t < 8) ? sh[t]      : 0.f;
        float b2 = (t < 8) ? sh[32 + t] : 0.f;
#pragma unroll
        for (int o = 4; o > 0; o >>= 1) {
            a  += __shfl_down_sync(0xffffffffu, a,  o);
            b2 += __shfl_down_sync(0xffffffffu, b2, o);
        }
        if (t == 0) { sh[0] = a; sh[1] = b2; }
    }
    __syncthreads();
    float mu   = sh[0] * (1.f / DIM_);
    float var  = sh[1] * (1.f / DIM_) - mu * mu;
    float rstd = rsqrtf(var + EPS_);
    float y0 = (v.x - mu) * rstd * gw[c + 0] + bw[c + 0];
    float y1 = (v.y - mu) * rstd * gw[c + 1] + bw[c + 1];
    float y2 = (v.z - mu) * rstd * gw[c + 2] + bw[c + 2];
    float y3 = (v.w - mu) * rstd * gw[c + 3] + bw[c + 3];
    size_t o0 = (size_t)row * DIM_ + c;
    unsigned lo, hi;
    hi = packsplit(y0, y1, lo);
    *(unsigned*)&oh[o0] = hi; *(unsigned*)&ol[o0] = lo;
    hi = packsplit(y2, y3, lo);
    *(unsigned*)&oh[o0 + 2] = hi; *(unsigned*)&ol[o0 + 2] = lo;
}

// ---------------- weight fp32 -> bf16 hi/lo ----------------
__global__ void wconv_kernel(const float* __restrict__ W,
                             bf16* __restrict__ Wh, bf16* __restrict__ Wl) {
    size_t i = ((size_t)blockIdx.x * 256 + threadIdx.x) * 2;
    float2 v = *(const float2*)(W + i);
    unsigned lo, hi = packsplit(v.x, v.y, lo);
    *(unsigned*)&Wh[i] = hi;
    *(unsigned*)&Wl[i] = lo;
}

// ================= bf16 hi/lo tensor-core GEMM =================
// A storage: ATR ? [K][M] : [M][K].  B storage: BTRK ? [K][N] : [N][K].
// C = alpha*A@B (+bias) fp32, or hi/lo bf16 planes if OSPLIT.
template <int BN, bool ATR, bool BTRK, bool OSPLIT>
__device__ __forceinline__ void tgemm(const bf16* __restrict__ Ah,
                                      const bf16* __restrict__ Al, int lda,
                                      const bf16* __restrict__ Bh,
                                      const bf16* __restrict__ Bl, int ldb,
                                      float* __restrict__ C,
                                      bf16* __restrict__ Ch,
                                      bf16* __restrict__ Cl, int ldc, int K,
                                      const float* __restrict__ bias,
                                      float alpha) {
    constexpr int BM = 128, BK = 32;
    constexpr int SAS = ATR ? (BM + 8) : (BK + 8);       // 136 / 40
    constexpr int SBS = BTRK ? (BN + 8) : (BK + 8);      // BN+8 / 40
    constexpr int ASZ = (ATR ? BK : BM) * SAS;
    constexpr int BSZ = (BTRK ? BK : BN) * SBS;
    constexpr int NT8 = BN / 16;    // n8 tiles per warp
    constexpr int NG  = BN / 32;    // n16 groups per warp
    constexpr int CB  = BN * 4;     // B 16B-chunks per plane

    extern __shared__ bf16 sm[];
    const int t = threadIdx.x, lane = t & 31, warp = t >> 5;
    const int gi = lane >> 2, gj = lane & 3;
    const int wm = (warp >> 1) * 32, wn = (warp & 1) * (BN / 2);
    const int m0 = blockIdx.y * BM, n0 = blockIdx.x * BN;

    float acc[2][NT8][4];
#pragma unroll
    for (int a = 0; a < 2; a++)
#pragma unroll
        for (int b = 0; b < NT8; b++)
#pragma unroll
            for (int q = 0; q < 4; q++) acc[a][b][q] = 0.f;

    auto cpA = [&](int kc, int bufi) {
        const bf16* src;
        bf16* dst;
#pragma unroll
        for (int p = 0; p < 2; p++) {
            src = p ? Al : Ah;
            dst = sm + p * 2 * ASZ + bufi * ASZ;
            if (!ATR) {
#pragma unroll
                for (int q = t; q < 512; q += 256) {
                    int row = q >> 2, c = (q & 3) * 8;
                    cp16(dst + row * SAS + c,
                         src + (size_t)(m0 + row) * lda + kc * BK + c);
                }
            } else {
#pragma unroll
                for (int q = t; q < 512; q += 256) {
                    int row = q >> 4, c = (q & 15) * 8;
                    cp16(dst + row * SAS + c,
                         src + (size_t)(kc * BK + row) * lda + m0 + c);
                }
            }
        }
    };
    auto cpB = [&](int kc, int bufi) {
        const bf16* src;
        bf16* dst;
#pragma unroll
        for (int p = 0; p < 2; p++) {
            src = p ? Bl : Bh;
            dst = sm + 4 * ASZ + p * 2 * BSZ + bufi * BSZ;
            if (BTRK) {
#pragma unroll
                for (int q = t; q < CB; q += 256) {
                    int row = q / (BN / 8), c = (q % (BN / 8)) * 8;
                    cp16(dst + row * SBS + c,
                         src + (size_t)(kc * BK + row) * ldb + n0 + c);
                }
            } else {
#pragma unroll
                for (int q = t; q < CB; q += 256) {
                    int row = q >> 2, c = (q & 3) * 8;
                    cp16(dst + row * SBS + c,
                         src + (size_t)(n0 + row) * ldb + kc * BK + c);
                }
            }
        }
    };

    const int NK = K / BK;
    cpA(0, 0); cpB(0, 0);
    asm volatile("cp.async.commit_group;\n");
    int buf = 0;

    for (int kc = 0; kc < NK; kc++) {
        if (kc + 1 < NK) {
            cpA(kc + 1, buf ^ 1); cpB(kc + 1, buf ^ 1);
            asm volatile("cp.async.commit_group;\n");
            asm volatile("cp.async.wait_group 1;\n");
        } else {
            asm volatile("cp.async.wait_group 0;\n");
        }
        __syncthreads();

        const bf16* sAh = sm + buf * ASZ;
        const bf16* sAl = sm + 2 * ASZ + buf * ASZ;
        const bf16* sBh = sm + 4 * ASZ + buf * BSZ;
        const bf16* sBl = sm + 4 * ASZ + 2 * BSZ + buf * BSZ;

#pragma unroll
        for (int ks = 0; ks < 2; ks++) {
            const int kofs = ks * 16;
            unsigned aH[2][4], aL[2][4];
            if (!ATR) {
                int r = lane & 15, c = (lane >> 4) * 8;
#pragma unroll
                for (int mt = 0; mt < 2; mt++) {
                    int off = (wm + mt * 16 + r) * SAS + kofs + c;
                    ldsm4(aH[mt], shaddr(sAh + off));
                    ldsm4(aL[mt], shaddr(sAl + off));
                }
            } else {
                int kr = kofs + (lane & 7) + ((lane >> 4) << 3);
#pragma unroll
                for (int mt = 0; mt < 2; mt++) {
                    int mc = wm + mt * 16 + (lane & 8);
                    int off = kr * SAS + mc;
                    ldsm4t(aH[mt], shaddr(sAh + off));
                    ldsm4t(aL[mt], shaddr(sAl + off));
                }
            }
#pragma unroll
            for (int g = 0; g < NG; g++) {
                unsigned bH[4], bL[4];
                int nb = wn + g * 16;
                if (BTRK) {
                    int kr = kofs + (lane & 7) + ((lane & 8) ? 8 : 0);
                    int nc = nb + ((lane & 16) ? 8 : 0);
                    int off = kr * SBS + nc;
                    ldsm4t(bH, shaddr(sBh + off));
                    ldsm4t(bL, shaddr(sBl + off));
                } else {
                    int nr = nb + (lane & 7) + ((lane & 16) ? 8 : 0);
                    int kc2 = kofs + ((lane & 8) ? 8 : 0);
                    int off = nr * SBS + kc2;
                    ldsm4(bH, shaddr(sBh + off));
                    ldsm4(bL, shaddr(sBl + off));
                }
#pragma unroll
                for (int mt = 0; mt < 2; mt++) {
                    mma_bf16(acc[mt][2 * g],     aH[mt], bH);
                    mma_bf16(acc[mt][2 * g],     aH[mt], bL);
                    mma_bf16(acc[mt][2 * g],     aL[mt], bH);
                    mma_bf16(acc[mt][2 * g + 1], aH[mt], bH + 2);
                    mma_bf16(acc[mt][2 * g + 1], aH[mt], bL + 2);
                    mma_bf16(acc[mt][2 * g + 1], aL[mt], bH + 2);
                }
            }
        }
        __syncthreads();
        buf ^= 1;
    }

#pragma unroll
    for (int mt = 0; mt < 2; mt++)
#pragma unroll
        for (int nt = 0; nt < NT8; nt++) {
            int r = m0 + wm + mt * 16 + gi;
            int c = n0 + wn + nt * 8 + 2 * gj;
            const float* a = acc[mt][nt];
            if (!OSPLIT) {
                float b0 = bias ? bias[c] : 0.f;
                float b1 = bias ? bias[c + 1] : 0.f;
                float2 v0 = {a[0] * alpha + b0, a[1] * alpha + b1};
                float2 v1 = {a[2] * alpha + b0, a[3] * alpha + b1};
                *(float2*)&C[(size_t)r * ldc + c] = v0;
                *(float2*)&C[(size_t)(r + 8) * ldc + c] = v1;
            } else {
                unsigned lo, hi;
                hi = packsplit(a[0], a[1], lo);
                *(unsigned*)&Ch[(size_t)r * ldc + c] = hi;
                *(unsigned*)&Cl[(size_t)r * ldc + c] = lo;
                hi = packsplit(a[2], a[3], lo);
                *(unsigned*)&Ch[(size_t)(r + 8) * ldc + c] = hi;
                *(unsigned*)&Cl[(size_t)(r + 8) * ldc + c] = lo;
            }
        }
}

// ---- kernel wrappers ----
// projection with split output: xn/cn planes @ weight planes -> qk/v planes
__global__ void __launch_bounds__(256) k_projS(const bf16* Ah, const bf16* Al,
                                               const bf16* Bh, const bf16* Bl,
                                               bf16* Ch, bf16* Cl) {
    tgemm<128, false, true, true>(Ah, Al, DIM_, Bh, Bl, INNER_,
                                  nullptr, Ch, Cl, INNER_, DIM_, nullptr, 1.f);
}
// final projection: o planes @ weight planes -> fp32 out (+bias)
__global__ void __launch_bounds__(256) k_projF(const bf16* Ah, const bf16* Al,
                                               const bf16* Bh, const bf16* Bl,
                                               float* C, const float* bias) {
    tgemm<128, false, true, false>(Ah, Al, INNER_, Bh, Bl, DIM_,
                                   C, nullptr, nullptr, DIM_, INNER_, bias, 1.f);
}
// sim: Q @ K^T * scale -> fp32
__global__ void __launch_bounds__(256) k_sim() {
    int z = blockIdx.z, b = z >> 4, h = z & 15;
    size_t qo = (size_t)b * I_ * INNER_ + h * DH_;
    size_t ko = (size_t)b * J_ * INNER_ + h * DH_;
    tgemm<128, false, false, false>(g_qkh + qo, g_qkl + qo, INNER_,
                                    g_ckh + ko, g_ckl + ko, INNER_,
                                    g_sim + (size_t)z * I_ * J_, nullptr,
                                    nullptr, J_, DH_, nullptr, SCALE_);
}
// out: attn @ ctx_v  -> o1 planes (merged heads)
__global__ void __launch_bounds__(256) k_av() {
    int z = blockIdx.z, b = z >> 4, h = z & 15;
    size_t ao = (size_t)z * I_ * J_;
    size_t vo = (size_t)b * J_ * INNER_ + h * DH_;
    size_t oo = (size_t)b * I_ * INNER_ + h * DH_;
    tgemm<64, false, true, true>(g_ath + ao, g_atl + ao, J_,
                                 g_cvh + vo, g_cvl + vo, INNER_,
                                 nullptr, g_o1h + oo, g_o1l + oo, INNER_,
                                 J_, nullptr, 1.f);
}
// ctx_out: cattn^T @ v -> o2 planes
__global__ void __launch_bounds__(256) k_avt() {
    int z = blockIdx.z, b = z >> 4, h = z & 15;
    size_t ao = (size_t)z * I_ * J_;
    size_t vo = (size_t)b * I_ * INNER_ + h * DH_;
    size_t oo = (size_t)b * J_ * INNER_ + h * DH_;
    tgemm<64, true, true, true>(g_cth + ao, g_ctl + ao, J_,
                                g_vh + vo, g_vl + vo, INNER_,
                                nullptr, g_o2h + oo, g_o2l + oo, INNER_,
                                I_, nullptr, 1.f);
}

// ---------------- row stats ----------------
__global__ void rowstat_kernel() {
    size_t row = blockIdx.x;
    const float* sr = g_sim + row * (size_t)J_;
    int t = threadIdx.x;
    float v[8]; float mx = -1e30f;
#pragma unroll
    for (int k = 0; k < 8; k++) { v[k] = sr[t + 256 * k]; mx = fmaxf(mx, v[k]); }
    __shared__ float sh[8];
    __shared__ float smax;
#pragma unroll
    for (int o = 16; o > 0; o >>= 1)
        mx = fmaxf(mx, __shfl_xor_sync(0xffffffffu, mx, o));
    if ((t & 31) == 0) sh[t >> 5] = mx;
    __syncthreads();
    if (t == 0) {
        float m = sh[0];
        for (int q = 1; q < 8; q++) m = fmaxf(m, sh[q]);
        smax = m;
    }
    __syncthreads();
    mx = smax;
    float s = 0.f;
#pragma unroll
    for (int k = 0; k < 8; k++) s += __expf(v[k] - mx);
#pragma unroll
    for (int o = 16; o > 0; o >>= 1)
        s += __shfl_xor_sync(0xffffffffu, s, o);
    if ((t & 31) == 0) sh[t >> 5] = s;
    __syncthreads();
    if (t == 0) {
        float a = 0.f;
        for (int q = 0; q < 8; q++) a += sh[q];
        g_rm[row] = mx;
        g_rs[row] = 1.f / a;
    }
}

// ---------------- col stats ----------------
__global__ void colstat_kernel() {
    int z  = blockIdx.y;
    int j0 = blockIdx.x * 32;
    const float* S = g_sim + (size_t)z * I_ * J_;
    int t = threadIdx.x;
    int c = t & 31, p = t >> 5;

    float m = -1e30f, s = 0.f;
    for (int i = p; i < I_; i += 8) {
        float x = S[(size_t)i * J_ + j0 + c];
        float nm = fmaxf(m, x);
        s = s * __expf(m - nm) + __expf(x - nm);
        m = nm;
    }
    __shared__ float shm[8][33], shs[8][33];
    shm[p][c] = m; shs[p][c] = s;
    __syncthreads();
    if (p == 0) {
        float M = m, Sv = s;
#pragma unroll
        for (int q = 1; q < 8; q++) {
            float m2 = shm[q][c], s2 = shs[q][c];
            float nm = fmaxf(M, m2);
            Sv = Sv * __expf(M - nm) + s2 * __expf(m2 - nm);
            M = nm;
        }
        g_cm[(size_t)z * J_ + j0 + c] = M;
        g_cs[(size_t)z * J_ + j0 + c] = 1.f / Sv;
    }
}

// ------- fused softmax-normalize + talking-heads mix -> bf16 planes -------
__global__ void mix_kernel(const float* __restrict__ thw,
                           const float* __restrict__ cthw) {
    int b = blockIdx.z;
    int i = blockIdx.y;
    int j = blockIdx.x * 256 + threadIdx.x;
    int t = threadIdx.x;

    __shared__ float wR[16][16], wC[16][16], rm[16], ri[16];
    wR[t >> 4][t & 15] = thw[t];
    wC[t >> 4][t & 15] = cthw[t];
    if (t < 16) {
        rm[t] = g_rm[((size_t)(b * H_ + t)) * I_ + i];
        ri[t] = g_rs[((size_t)(b * H_ + t)) * I_ + i];
    }
    __syncthreads();

    float pr[16], pc[16];
#pragma unroll
    for (int h = 0; h < 16; h++) {
        size_t zi = (size_t)(b * H_ + h);
        float sv = g_sim[(zi * I_ + i) * J_ + j];
        pr[h] = __expf(sv - rm[h]) * ri[h];
        float cm = g_cm[zi * J_ + j];
        float ci = g_cs[zi * J_ + j];
        pc[h] = __expf(sv - cm) * ci;
    }
#pragma unroll
    for (int g = 0; g < 16; g++) {
        float aR = 0.f, aC = 0.f;
#pragma unroll
        for (int h = 0; h < 16; h++) {
            aR += wR[g][h] * pr[h];
            aC += wC[g][h] * pc[h];
        }
        size_t idx = (((size_t)(b * H_ + g)) * I_ + i) * J_ + j;
        bf16 hh, ll;
        split1(aR, hh, ll);
        g_ath[idx] = hh; g_atl[idx] = ll;
        split1(aC, hh, ll);
        g_cth[idx] = hh; g_ctl[idx] = ll;
    }
}

// ---------------- launch ----------------
extern "C" void kernel_launch(void* const* d_in, const int* in_sizes, int n_in,
                              void* d_out, int out_size) {
    const float* x     = (const float*)d_in[0];
    const float* ctx   = (const float*)d_in[1];
    const float* ln_g  = (const float*)d_in[2];
    const float* ln_b  = (const float*)d_in[3];
    const float* cln_g = (const float*)d_in[4];
    const float* cln_b = (const float*)d_in[5];
    const float* W_qk  = (const float*)d_in[6];
    const float* W_cqk = (const float*)d_in[7];
    const float* W_v   = (const float*)d_in[8];
    const float* W_cv  = (const float*)d_in[9];
    const float* W_out = (const float*)d_in[10];
    const float* b_out = (const float*)d_in[11];
    const float* W_cout= (const float*)d_in[12];
    const float* b_cout= (const float*)d_in[13];
    const float* thw   = (const float*)d_in[14];
    const float* cthw  = (const float*)d_in[15];
    float* out = (float*)d_out;

    // resolve device-symbol addresses
    bf16 *xnh, *xnl, *cnh, *cnl, *qkh, *qkl, *ckh, *ckl, *vh, *vl, *cvh, *cvl;
    bf16 *o1h, *o1l, *o2h, *o2l, *wh, *wl;
    cudaGetSymbolAddress((void**)&xnh, g_xnh); cudaGetSymbolAddress((void**)&xnl, g_xnl);
    cudaGetSymbolAddress((void**)&cnh, g_cnh); cudaGetSymbolAddress((void**)&cnl, g_cnl);
    cudaGetSymbolAddress((void**)&qkh, g_qkh); cudaGetSymbolAddress((void**)&qkl, g_qkl);
    cudaGetSymbolAddress((void**)&ckh, g_ckh); cudaGetSymbolAddress((void**)&ckl, g_ckl);
    cudaGetSymbolAddress((void**)&vh,  g_vh);  cudaGetSymbolAddress((void**)&vl,  g_vl);
    cudaGetSymbolAddress((void**)&cvh, g_cvh); cudaGetSymbolAddress((void**)&cvl, g_cvl);
    cudaGetSymbolAddress((void**)&o1h, g_o1h); cudaGetSymbolAddress((void**)&o1l, g_o1l);
    cudaGetSymbolAddress((void**)&o2h, g_o2h); cudaGetSymbolAddress((void**)&o2l, g_o2l);
    cudaGetSymbolAddress((void**)&wh,  g_wh);  cudaGetSymbolAddress((void**)&wl,  g_wl);

    // dynamic smem opt-in (idempotent)
    constexpr int SM_PROJ = (4 * 128 * 40 + 4 * 32 * 136) * 2;   // 75776 B
    constexpr int SM_SIM  = (4 * 128 * 40 + 4 * 128 * 40) * 2;   // 81920 B
    constexpr int SM_AV   = (4 * 128 * 40 + 4 * 32 * 72) * 2;    // 59392 B
    constexpr int SM_AVT  = (4 * 32 * 136 + 4 * 32 * 72) * 2;    // 53248 B
    cudaFuncSetAttribute(k_projS, cudaFuncAttributeMaxDynamicSharedMemorySize, SM_PROJ);
    cudaFuncSetAttribute(k_projF, cudaFuncAttributeMaxDynamicSharedMemorySize, SM_PROJ);
    cudaFuncSetAttribute(k_sim,   cudaFuncAttributeMaxDynamicSharedMemorySize, SM_SIM);
    cudaFuncSetAttribute(k_av,    cudaFuncAttributeMaxDynamicSharedMemorySize, SM_AV);
    cudaFuncSetAttribute(k_avt,   cudaFuncAttributeMaxDynamicSharedMemorySize, SM_AVT);

    const size_t WSZ = (size_t)DIM_ * INNER_;

    // 1) layernorms -> bf16 planes ; weights -> bf16 planes
    ln_kernel<<<B_ * I_, 256>>>(x,   ln_g,  ln_b,  xnh, xnl);
    ln_kernel<<<B_ * J_, 256>>>(ctx, cln_g, cln_b, cnh, cnl);
    const float* ws[6] = {W_qk, W_cqk, W_v, W_cv, W_out, W_cout};
    for (int w = 0; w < 6; w++)
        wconv_kernel<<<2048, 256>>>(ws[w], wh + w * WSZ, wl + w * WSZ);

    // 2) projections (split outputs)
    dim3 gp(DIM_ / 128, (B_ * I_) / 128);
    k_projS<<<gp, 256, SM_PROJ>>>(xnh, xnl, wh + 0 * WSZ, wl + 0 * WSZ, qkh, qkl);
    k_projS<<<gp, 256, SM_PROJ>>>(cnh, cnl, wh + 1 * WSZ, wl + 1 * WSZ, ckh, ckl);
    k_projS<<<gp, 256, SM_PROJ>>>(xnh, xnl, wh + 2 * WSZ, wl + 2 * WSZ, vh,  vl);
    k_projS<<<gp, 256, SM_PROJ>>>(cnh, cnl, wh + 3 * WSZ, wl + 3 * WSZ, cvh, cvl);

    // 3) sim = Q @ K^T * scale
    k_sim<<<dim3(J_ / 128, I_ / 128, B_ * H_), 256, SM_SIM>>>();

    // 4) softmax statistics
    rowstat_kernel<<<B_ * H_ * I_, 256>>>();
    colstat_kernel<<<dim3(J_ / 32, B_ * H_), 256>>>();

    // 5) fused normalize + talking-heads mix -> bf16 planes
    mix_kernel<<<dim3(J_ / 256, I_, B_), 256>>>(thw, cthw);

    // 6) attention-weighted values -> merged-head planes
    k_av <<<dim3(1, I_ / 128, B_ * H_), 256, SM_AV >>>();
    k_avt<<<dim3(1, J_ / 128, B_ * H_), 256, SM_AVT>>>();

    // 7) output projections -> d_out
    k_projF<<<gp, 256, SM_PROJ>>>(o1h, o1l, wh + 4 * WSZ, wl + 4 * WSZ, out, b_out);
    k_projF<<<gp, 256, SM_PROJ>>>(o2h, o2l, wh + 5 * WSZ, wl + 5 * WSZ,
                                  out + (size_t)B_ * I_ * DIM_, b_cout);
}

// round 5
// speedup vs baseline: 2.4752x; 1.3149x over previous
#include <cuda_runtime.h>
#include <cuda_bf16.h>
#include <cuda_fp16.h>
#include <math.h>

typedef __nv_bfloat16 bf16;

// ---------------- problem constants ----------------
#define B_     2
#define I_     2048
#define J_     2048
#define DIM_   1024
#define H_     16
#define DH_    64
#define INNER_ 1024
#define EPS_   1e-5f
#define SCALE_ 0.125f   // DH^-0.5
#define SIMN   134217728   // B*H*I*J
#define NZ_    32          // B*H

// ---------------- scratch (device globals; allocation-free) ----------------
__device__ bf16 g_xnh[B_ * I_ * DIM_],  g_xnl[B_ * I_ * DIM_];
__device__ bf16 g_cnh[B_ * J_ * DIM_],  g_cnl[B_ * J_ * DIM_];
__device__ bf16 g_qkh[B_ * I_ * INNER_], g_qkl[B_ * I_ * INNER_];
__device__ bf16 g_ckh[B_ * J_ * INNER_], g_ckl[B_ * J_ * INNER_];
__device__ half g_vh [B_ * I_ * INNER_], g_vl [B_ * I_ * INNER_];
__device__ half g_cvh[B_ * J_ * INNER_], g_cvl[B_ * J_ * INNER_];
__device__ bf16 g_o1h[B_ * I_ * INNER_], g_o1l[B_ * I_ * INNER_];
__device__ bf16 g_o2h[B_ * J_ * INNER_], g_o2l[B_ * J_ * INNER_];
__device__ bf16 g_wh[6][DIM_ * INNER_], g_wl[6][DIM_ * INNER_];
__device__ float g_sim[SIMN];                 // exp(scale*QK) fp32, 512 MB
__device__ half g_at16[SIMN], g_ct16[SIMN];   // mixed attn, fp16
__device__ float g_rp[NZ_ * I_ * 16], g_cp[NZ_ * J_ * 16];  // tile partial sums
__device__ float g_rs[NZ_ * I_], g_cs[NZ_ * J_];            // 1/rowsum, 1/colsum

// ---------------- helpers ----------------
__device__ __forceinline__ unsigned packsplit(float x, float y, unsigned& lo) {
    bf16 hx = __float2bfloat16(x);
    bf16 hy = __float2bfloat16(y);
    float lx = x - __bfloat162float(hx);
    float ly = y - __bfloat162float(hy);
    __nv_bfloat162 l2 = __floats2bfloat162_rn(lx, ly);
    lo = *(unsigned*)&l2;
    __nv_bfloat162 h2 = __halves2bfloat162(hx, hy);
    return *(unsigned*)&h2;
}
__device__ __forceinline__ unsigned packsplit_h(float x, float y, unsigned& lo) {
    half hx = __float2half(x);
    half hy = __float2half(y);
    float lx = x - __half2float(hx);
    float ly = y - __half2float(hy);
    half2 l2 = __floats2half2_rn(lx, ly);
    lo = *(unsigned*)&l2;
    half2 h2 = __halves2half2(hx, hy);
    return *(unsigned*)&h2;
}
template <class T> struct Mma;
template <> struct Mma<bf16> {
    static __device__ __forceinline__ void op(float* c, const unsigned* a,
                                              const unsigned* b) {
        asm volatile(
            "mma.sync.aligned.m16n8k16.row.col.f32.bf16.bf16.f32 "
            "{%0,%1,%2,%3}, {%4,%5,%6,%7}, {%8,%9}, {%0,%1,%2,%3};\n"
            : "+f"(c[0]), "+f"(c[1]), "+f"(c[2]), "+f"(c[3])
            : "r"(a[0]), "r"(a[1]), "r"(a[2]), "r"(a[3]), "r"(b[0]), "r"(b[1]));
    }
};
template <> struct Mma<half> {
    static __device__ __forceinline__ void op(float* c, const unsigned* a,
                                              const unsigned* b) {
        asm volatile(
            "mma.sync.aligned.m16n8k16.row.col.f32.f16.f16.f32 "
            "{%0,%1,%2,%3}, {%4,%5,%6,%7}, {%8,%9}, {%0,%1,%2,%3};\n"
            : "+f"(c[0]), "+f"(c[1]), "+f"(c[2]), "+f"(c[3])
            : "r"(a[0]), "r"(a[1]), "r"(a[2]), "r"(a[3]), "r"(b[0]), "r"(b[1]));
    }
};
__device__ __forceinline__ void ldsm4(unsigned* d, unsigned a) {
    asm volatile("ldmatrix.sync.aligned.m8n8.x4.shared.b16 {%0,%1,%2,%3},[%4];\n"
                 : "=r"(d[0]), "=r"(d[1]), "=r"(d[2]), "=r"(d[3]) : "r"(a));
}
__device__ __forceinline__ void ldsm4t(unsigned* d, unsigned a) {
    asm volatile("ldmatrix.sync.aligned.m8n8.x4.trans.shared.b16 {%0,%1,%2,%3},[%4];\n"
                 : "=r"(d[0]), "=r"(d[1]), "=r"(d[2]), "=r"(d[3]) : "r"(a));
}
__device__ __forceinline__ void cp16(void* smp, const void* gp) {
    unsigned sa = (unsigned)__cvta_generic_to_shared(smp);
    asm volatile("cp.async.cg.shared.global [%0], [%1], 16;\n" :: "r"(sa), "l"(gp));
}
__device__ __forceinline__ unsigned shaddr(const void* p) {
    return (unsigned)__cvta_generic_to_shared(p);
}

// ---------------- LayerNorm -> bf16 hi/lo planes ----------------
__global__ void ln_kernel(const float* __restrict__ x,
                          const float* __restrict__ gw,
                          const float* __restrict__ bw,
                          bf16* __restrict__ oh, bf16* __restrict__ ol) {
    int row = blockIdx.x;
    const float* xr = x + (size_t)row * DIM_;
    int t = threadIdx.x;
    int c = t * 4;

    float4 v = *(const float4*)(xr + c);
    float s = v.x + v.y + v.z + v.w;
    float sq = v.x * v.x + v.y * v.y + v.z * v.z + v.w * v.w;
    __shared__ float sh[64];
#pragma unroll
    for (int o = 16; o > 0; o >>= 1) {
        s  += __shfl_down_sync(0xffffffffu, s,  o);
        sq += __shfl_down_sync(0xffffffffu, sq, o);
    }
    if ((t & 31) == 0) { sh[t >> 5] = s; sh[32 + (t >> 5)] = sq; }
    __syncthreads();
    if (t < 32) {
        float a  = (t < 8) ? sh[t]      : 0.f;
        float b2 = (t < 8) ? sh[32 + t] : 0.f;
#pragma unroll
        for (int o = 4; o > 0; o >>= 1) {
            a  += __shfl_down_sync(0xffffffffu, a,  o);
            b2 += __shfl_down_sync(0xffffffffu, b2, o);
        }
        if (t == 0) { sh[0] = a; sh[1] = b2; }
    }
    __syncthreads();
    float mu   = sh[0] * (1.f / DIM_);
    float var  = sh[1] * (1.f / DIM_) - mu * mu;
    float rstd = rsqrtf(var + EPS_);
    float y0 = (v.x - mu) * rstd * gw[c + 0] + bw[c + 0];
    float y1 = (v.y - mu) * rstd * gw[c + 1] + bw[c + 1];
    float y2 = (v.z - mu) * rstd * gw[c + 2] + bw[c + 2];
    float y3 = (v.w - mu) * rstd * gw[c + 3] + bw[c + 3];
    size_t o0 = (size_t)row * DIM_ + c;
    unsigned lo, hi;
    hi = packsplit(y0, y1, lo);
    *(unsigned*)&oh[o0] = hi; *(unsigned*)&ol[o0] = lo;
    hi = packsplit(y2, y3, lo);
    *(unsigned*)&oh[o0 + 2] = hi; *(unsigned*)&ol[o0 + 2] = lo;
}

// ---------------- weight fp32 -> bf16 hi/lo ----------------
__global__ void wconv_kernel(const float* __restrict__ W,
                             bf16* __restrict__ Wh, bf16* __restrict__ Wl) {
    size_t i = ((size_t)blockIdx.x * 256 + threadIdx.x) * 2;
    float2 v = *(const float2*)(W + i);
    unsigned lo, hi = packsplit(v.x, v.y, lo);
    *(unsigned*)&Wh[i] = hi;
    *(unsigned*)&Wl[i] = lo;
}

// ================= hi/lo split tensor-core GEMM =================
// DT: bf16 or half.  A: ATR ? [K][M] : [M][K].  B: BKN ? [K][N] : [N][K].
// APL: # of A planes (1 or 2); B always 2 planes.
// OMODE: 0 = fp32 + bias; 1 = bf16 hi/lo planes; 2 = exp + softmax-stat
//        partials (sim); 3 = fp16 hi/lo planes.
template <class DT, int BN, bool ATR, bool BKN, int APL, int OMODE>
__device__ __forceinline__ void tgemm(const DT* __restrict__ Ah,
                                      const DT* __restrict__ Al, int lda,
                                      const DT* __restrict__ Bh,
                                      const DT* __restrict__ Bl, int ldb,
                                      float* __restrict__ C,
                                      bf16* __restrict__ Ch,
                                      bf16* __restrict__ Cl,
                                      half* __restrict__ Fh,
                                      half* __restrict__ Fl,
                                      int ldc, int K,
                                      const float* __restrict__ bias,
                                      float alpha) {
    constexpr int BM = 128, BK = 32;
    constexpr int SAS = ATR ? (BM + 8) : (BK + 8);
    constexpr int SBS = BKN ? (BN + 8) : (BK + 8);
    constexpr int ASZ = (ATR ? BK : BM) * SAS;
    constexpr int BSZ = (BKN ? BK : BN) * SBS;
    constexpr int NT8 = BN / 16;
    constexpr int NG  = BN / 32;
    constexpr int CB  = BN * 4;

    extern __shared__ unsigned char smraw[];
    DT* sm = (DT*)smraw;
    const int t = threadIdx.x, lane = t & 31, warp = t >> 5;
    const int gi = lane >> 2, gj = lane & 3;
    const int wm = (warp >> 1) * 32, wn = (warp & 1) * (BN / 2);
    const int m0 = blockIdx.y * BM, n0 = blockIdx.x * BN;

    float acc[2][NT8][4];
#pragma unroll
    for (int a = 0; a < 2; a++)
#pragma unroll
        for (int b = 0; b < NT8; b++)
#pragma unroll
            for (int q = 0; q < 4; q++) acc[a][b][q] = 0.f;

    auto cpA = [&](int kc, int bufi) {
#pragma unroll
        for (int p = 0; p < APL; p++) {
            const DT* src = p ? Al : Ah;
            DT* dst = sm + p * 2 * ASZ + bufi * ASZ;
            if (!ATR) {
#pragma unroll
                for (int q = t; q < 512; q += 256) {
                    int row = q >> 2, c = (q & 3) * 8;
                    cp16(dst + row * SAS + c,
                         src + (size_t)(m0 + row) * lda + kc * BK + c);
                }
            } else {
#pragma unroll
                for (int q = t; q < 512; q += 256) {
                    int row = q >> 4, c = (q & 15) * 8;
                    cp16(dst + row * SAS + c,
                         src + (size_t)(kc * BK + row) * lda + m0 + c);
                }
            }
        }
    };
    auto cpB = [&](int kc, int bufi) {
#pragma unroll
        for (int p = 0; p < 2; p++) {
            const DT* src = p ? Bl : Bh;
            DT* dst = sm + APL * 2 * ASZ + p * 2 * BSZ + bufi * BSZ;
            if (BKN) {
#pragma unroll
                for (int q = t; q < CB; q += 256) {
                    int row = q / (BN / 8), c = (q % (BN / 8)) * 8;
                    cp16(dst + row * SBS + c,
                         src + (size_t)(kc * BK + row) * ldb + n0 + c);
                }
            } else {
#pragma unroll
                for (int q = t; q < CB; q += 256) {
                    int row = q >> 2, c = (q & 3) * 8;
                    cp16(dst + row * SBS + c,
                         src + (size_t)(n0 + row) * ldb + kc * BK + c);
                }
            }
        }
    };

    const int NK = K / BK;
    cpA(0, 0); cpB(0, 0);
    asm volatile("cp.async.commit_group;\n");
    int buf = 0;

    for (int kc = 0; kc < NK; kc++) {
        if (kc + 1 < NK) {
            cpA(kc + 1, buf ^ 1); cpB(kc + 1, buf ^ 1);
            asm volatile("cp.async.commit_group;\n");
            asm volatile("cp.async.wait_group 1;\n");
        } else {
            asm volatile("cp.async.wait_group 0;\n");
        }
        __syncthreads();

        const DT* sAh = sm + buf * ASZ;
        const DT* sAl = sm + 2 * ASZ + buf * ASZ;   // valid only if APL==2
        const DT* sBh = sm + APL * 2 * ASZ + buf * BSZ;
        const DT* sBl = sm + APL * 2 * ASZ + 2 * BSZ + buf * BSZ;

#pragma unroll
        for (int ks = 0; ks < 2; ks++) {
            const int kofs = ks * 16;
            unsigned aH[2][4], aL[2][4];
            if (!ATR) {
                int r = lane & 15, c = (lane >> 4) * 8;
#pragma unroll
                for (int mt = 0; mt < 2; mt++) {
                    int off = (wm + mt * 16 + r) * SAS + kofs + c;
                    ldsm4(aH[mt], shaddr(sAh + off));
                    if (APL == 2) ldsm4(aL[mt], shaddr(sAl + off));
                }
            } else {
                int kr = kofs + (lane & 7) + ((lane >> 4) << 3);
#pragma unroll
                for (int mt = 0; mt < 2; mt++) {
                    int mc = wm + mt * 16 + (lane & 8);
                    int off = kr * SAS + mc;
                    ldsm4t(aH[mt], shaddr(sAh + off));
                    if (APL == 2) ldsm4t(aL[mt], shaddr(sAl + off));
                }
            }
#pragma unroll
            for (int g = 0; g < NG; g++) {
                unsigned bH[4], bL[4];
                int nb = wn + g * 16;
                if (BKN) {
                    int kr = kofs + (lane & 7) + ((lane & 8) ? 8 : 0);
                    int nc = nb + ((lane & 16) ? 8 : 0);
                    int off = kr * SBS + nc;
                    ldsm4t(bH, shaddr(sBh + off));
                    ldsm4t(bL, shaddr(sBl + off));
                } else {
                    int nr = nb + (lane & 7) + ((lane & 16) ? 8 : 0);
                    int kc2 = kofs + ((lane & 8) ? 8 : 0);
                    int off = nr * SBS + kc2;
                    ldsm4(bH, shaddr(sBh + off));
                    ldsm4(bL, shaddr(sBl + off));
                }
#pragma unroll
                for (int mt = 0; mt < 2; mt++) {
                    Mma<DT>::op(acc[mt][2 * g], aH[mt], bH);
                    Mma<DT>::op(acc[mt][2 * g], aH[mt], bL);
                    if (APL == 2) Mma<DT>::op(acc[mt][2 * g], aL[mt], bH);
                    Mma<DT>::op(acc[mt][2 * g + 1], aH[mt], bH + 2);
                    Mma<DT>::op(acc[mt][2 * g + 1], aH[mt], bL + 2);
                    if (APL == 2) Mma<DT>::op(acc[mt][2 * g + 1], aL[mt], bH + 2);
                }
            }
        }
        __syncthreads();
        buf ^= 1;
    }

    if constexpr (OMODE == 2) {
        // exp + deterministic per-tile softmax partial sums (BN==128 assumed)
        __shared__ float rsm[2][128];
        __shared__ float csm[4][128];
        float rsum[2][2] = {};
        float csum[NT8][2] = {};
#pragma unroll
        for (int mt = 0; mt < 2; mt++)
#pragma unroll
            for (int nt = 0; nt < NT8; nt++) {
                int r = m0 + wm + mt * 16 + gi;
                int c = n0 + wn + nt * 8 + 2 * gj;
                float e0 = __expf(acc[mt][nt][0] * alpha);
                float e1 = __expf(acc[mt][nt][1] * alpha);
                float e2 = __expf(acc[mt][nt][2] * alpha);
                float e3 = __expf(acc[mt][nt][3] * alpha);
                float2 v0 = {e0, e1}, v1 = {e2, e3};
                *(float2*)&C[(size_t)r * ldc + c] = v0;
                *(float2*)&C[(size_t)(r + 8) * ldc + c] = v1;
                rsum[mt][0] += e0 + e1;
                rsum[mt][1] += e2 + e3;
                csum[nt][0] += e0 + e2;
                csum[nt][1] += e1 + e3;
            }
        // row partials: reduce over gj (lane bits 0-1)
#pragma unroll
        for (int mt = 0; mt < 2; mt++)
#pragma unroll
            for (int rh = 0; rh < 2; rh++) {
                float v = rsum[mt][rh];
                v += __shfl_xor_sync(0xffffffffu, v, 1);
                v += __shfl_xor_sync(0xffffffffu, v, 2);
                if (gj == 0) rsm[warp & 1][wm + mt * 16 + gi + rh * 8] = v;
            }
        // col partials: reduce over gi (lane bits 2-4)
#pragma unroll
        for (int nt = 0; nt < NT8; nt++)
#pragma unroll
            for (int q = 0; q < 2; q++) {
                float v = csum[nt][q];
                v += __shfl_xor_sync(0xffffffffu, v, 4);
                v += __shfl_xor_sync(0xffffffffu, v, 8);
                v += __shfl_xor_sync(0xffffffffu, v, 16);
                if (gi == 0) csm[warp >> 1][wn + nt * 8 + 2 * gj + q] = v;
            }
        __syncthreads();
        if (t < 128) {
            float rtot = rsm[0][t] + rsm[1][t];
            g_rp[((size_t)blockIdx.z * I_ + m0 + t) * 16 + blockIdx.x] = rtot;
            float ctot = csm[0][t] + csm[1][t] + csm[2][t] + csm[3][t];
            g_cp[((size_t)blockIdx.z * J_ + n0 + t) * 16 + blockIdx.y] = ctot;
        }
        return;
    }

#pragma unroll
    for (int mt = 0; mt < 2; mt++)
#pragma unroll
        for (int nt = 0; nt < NT8; nt++) {
            int r = m0 + wm + mt * 16 + gi;
            int c = n0 + wn + nt * 8 + 2 * gj;
            const float* a = acc[mt][nt];
            if constexpr (OMODE == 0) {
                float b0 = bias ? bias[c] : 0.f;
                float b1 = bias ? bias[c + 1] : 0.f;
                float2 v0 = {a[0] * alpha + b0, a[1] * alpha + b1};
                float2 v1 = {a[2] * alpha + b0, a[3] * alpha + b1};
                *(float2*)&C[(size_t)r * ldc + c] = v0;
                *(float2*)&C[(size_t)(r + 8) * ldc + c] = v1;
            } else if constexpr (OMODE == 1) {
                unsigned lo, hi;
                hi = packsplit(a[0], a[1], lo);
                *(unsigned*)&Ch[(size_t)r * ldc + c] = hi;
                *(unsigned*)&Cl[(size_t)r * ldc + c] = lo;
                hi = packsplit(a[2], a[3], lo);
                *(unsigned*)&Ch[(size_t)(r + 8) * ldc + c] = hi;
                *(unsigned*)&Cl[(size_t)(r + 8) * ldc + c] = lo;
            } else {   // OMODE == 3: fp16 hi/lo planes
                unsigned lo, hi;
                hi = packsplit_h(a[0], a[1], lo);
                *(unsigned*)&Fh[(size_t)r * ldc + c] = hi;
                *(unsigned*)&Fl[(size_t)r * ldc + c] = lo;
                hi = packsplit_h(a[2], a[3], lo);
                *(unsigned*)&Fh[(size_t)(r + 8) * ldc + c] = hi;
                *(unsigned*)&Fl[(size_t)(r + 8) * ldc + c] = lo;
            }
        }
}

// ---- kernel wrappers ----
__global__ void __launch_bounds__(256) k_projQ(const bf16* Ah, const bf16* Al,
                                               const bf16* Bh, const bf16* Bl,
                                               bf16* Ch, bf16* Cl) {
    tgemm<bf16, 128, false, true, 2, 1>(Ah, Al, DIM_, Bh, Bl, INNER_,
                                        nullptr, Ch, Cl, nullptr, nullptr,
                                        INNER_, DIM_, nullptr, 1.f);
}
__global__ void __launch_bounds__(256) k_projV(const bf16* Ah, const bf16* Al,
                                               const bf16* Bh, const bf16* Bl,
                                               half* Fh, half* Fl) {
    tgemm<bf16, 128, false, true, 2, 3>(Ah, Al, DIM_, Bh, Bl, INNER_,
                                        nullptr, nullptr, nullptr, Fh, Fl,
                                        INNER_, DIM_, nullptr, 1.f);
}
__global__ void __launch_bounds__(256) k_projF(const bf16* Ah, const bf16* Al,
                                               const bf16* Bh, const bf16* Bl,
                                               float* C, const float* bias) {
    tgemm<bf16, 128, false, true, 2, 0>(Ah, Al, INNER_, Bh, Bl, DIM_,
                                        C, nullptr, nullptr, nullptr, nullptr,
                                        DIM_, INNER_, bias, 1.f);
}
// sim epilogue: store exp(scale*QK) fp32 + softmax stat partials
__global__ void __launch_bounds__(256) k_sim() {
    int z = blockIdx.z, b = z >> 4, h = z & 15;
    size_t qo = (size_t)b * I_ * INNER_ + h * DH_;
    size_t ko = (size_t)b * J_ * INNER_ + h * DH_;
    tgemm<bf16, 128, false, false, 2, 2>(g_qkh + qo, g_qkl + qo, INNER_,
                                         g_ckh + ko, g_ckl + ko, INNER_,
                                         g_sim + (size_t)z * I_ * J_,
                                         nullptr, nullptr, nullptr, nullptr,
                                         J_, DH_, nullptr, SCALE_);
}
// out: attn(fp16) @ ctx_v(fp16 hi/lo) -> o1 bf16 planes (merged heads)
__global__ void __launch_bounds__(256) k_av() {
    int z = blockIdx.z, b = z >> 4, h = z & 15;
    size_t ao = (size_t)z * I_ * J_;
    size_t vo = (size_t)b * J_ * INNER_ + h * DH_;
    size_t oo = (size_t)b * I_ * INNER_ + h * DH_;
    tgemm<half, 64, false, true, 1, 1>(g_at16 + ao, nullptr, J_,
                                       g_cvh + vo, g_cvl + vo, INNER_,
                                       nullptr, g_o1h + oo, g_o1l + oo,
                                       nullptr, nullptr, INNER_, J_, nullptr, 1.f);
}
// ctx_out: cattn^T(fp16) @ v(fp16 hi/lo) -> o2 bf16 planes
__global__ void __launch_bounds__(256) k_avt() {
    int z = blockIdx.z, b = z >> 4, h = z & 15;
    size_t ao = (size_t)z * I_ * J_;
    size_t vo = (size_t)b * I_ * INNER_ + h * DH_;
    size_t oo = (size_t)b * J_ * INNER_ + h * DH_;
    tgemm<half, 64, true, true, 1, 1>(g_ct16 + ao, nullptr, J_,
                                      g_vh + vo, g_vl + vo, INNER_,
                                      nullptr, g_o2h + oo, g_o2l + oo,
                                      nullptr, nullptr, INNER_, I_, nullptr, 1.f);
}

// ---------------- stat partial reduction: 1/sum ----------------
__global__ void statreduce() {
    int idx = blockIdx.x * 256 + threadIdx.x;   // (z*2048 + pos)
    const float* src = blockIdx.y ? g_cp : g_rp;
    float s = 0.f;
#pragma unroll
    for (int q = 0; q < 16; q++) s += src[(size_t)idx * 16 + q];
    (blockIdx.y ? g_cs : g_rs)[idx] = 1.f / s;
}

// ------- fused softmax-normalize + talking-heads mix -> fp16 attn ---------
__global__ void mix_kernel(const float* __restrict__ thw,
                           const float* __restrict__ cthw) {
    int b = blockIdx.z;
    int i = blockIdx.y;
    int j = blockIdx.x * 256 + threadIdx.x;
    int t = threadIdx.x;

    __shared__ float wR[16][16], wC[16][16], ri[16];
    wR[t >> 4][t & 15] = thw[t];
    wC[t >> 4][t & 15] = cthw[t];
    if (t < 16) ri[t] = g_rs[((size_t)(b * H_ + t)) * I_ + i];
    __syncthreads();

    float pr[16], pc[16];
#pragma unroll
    for (int h = 0; h < 16; h++) {
        size_t zi = (size_t)(b * H_ + h);
        float e = g_sim[(zi * I_ + i) * J_ + j];
        pr[h] = e * ri[h];
        pc[h] = e * g_cs[zi * J_ + j];
    }
#pragma unroll
    for (int g = 0; g < 16; g++) {
        float aR = 0.f, aC = 0.f;
#pragma unroll
        for (int h = 0; h < 16; h++) {
            aR += wR[g][h] * pr[h];
            aC += wC[g][h] * pc[h];
        }
        size_t idx = (((size_t)(b * H_ + g)) * I_ + i) * J_ + j;
        g_at16[idx] = __float2half(aR);
        g_ct16[idx] = __float2half(aC);
    }
}

// ---------------- launch ----------------
extern "C" void kernel_launch(void* const* d_in, const int* in_sizes, int n_in,
                              void* d_out, int out_size) {
    const float* x     = (const float*)d_in[0];
    const float* ctx   = (const float*)d_in[1];
    const float* ln_g  = (const float*)d_in[2];
    const float* ln_b  = (const float*)d_in[3];
    const float* cln_g = (const float*)d_in[4];
    const float* cln_b = (const float*)d_in[5];
    const float* W_qk  = (const float*)d_in[6];
    const float* W_cqk = (const float*)d_in[7];
    const float* W_v   = (const float*)d_in[8];
    const float* W_cv  = (const float*)d_in[9];
    const float* W_out = (const float*)d_in[10];
    const float* b_out = (const float*)d_in[11];
    const float* W_cout= (const float*)d_in[12];
    const float* b_cout= (const float*)d_in[13];
    const float* thw   = (const float*)d_in[14];
    const float* cthw  = (const float*)d_in[15];
    float* out = (float*)d_out;

    bf16 *xnh, *xnl, *cnh, *cnl, *qkh, *qkl, *ckh, *ckl, *o1h, *o1l, *o2h, *o2l, *wh, *wl;
    half *vh, *vl, *cvh, *cvl;
    cudaGetSymbolAddress((void**)&xnh, g_xnh); cudaGetSymbolAddress((void**)&xnl, g_xnl);
    cudaGetSymbolAddress((void**)&cnh, g_cnh); cudaGetSymbolAddress((void**)&cnl, g_cnl);
    cudaGetSymbolAddress((void**)&qkh, g_qkh); cudaGetSymbolAddress((void**)&qkl, g_qkl);
    cudaGetSymbolAddress((void**)&ckh, g_ckh); cudaGetSymbolAddress((void**)&ckl, g_ckl);
    cudaGetSymbolAddress((void**)&vh,  g_vh);  cudaGetSymbolAddress((void**)&vl,  g_vl);
    cudaGetSymbolAddress((void**)&cvh, g_cvh); cudaGetSymbolAddress((void**)&cvl, g_cvl);
    cudaGetSymbolAddress((void**)&o1h, g_o1h); cudaGetSymbolAddress((void**)&o1l, g_o1l);
    cudaGetSymbolAddress((void**)&o2h, g_o2h); cudaGetSymbolAddress((void**)&o2l, g_o2l);
    cudaGetSymbolAddress((void**)&wh,  g_wh);  cudaGetSymbolAddress((void**)&wl,  g_wl);

    // dynamic smem sizes (bytes)
    constexpr int SM_PROJ = (2 * 2 * 128 * 40 + 2 * 2 * 32 * 136) * 2;  // 75776
    constexpr int SM_SIM  = (2 * 2 * 128 * 40 + 2 * 2 * 128 * 40) * 2;  // 81920
    constexpr int SM_AV   = (1 * 2 * 128 * 40 + 2 * 2 * 32 * 72) * 2;   // 38912
    constexpr int SM_AVT  = (1 * 2 * 32 * 136 + 2 * 2 * 32 * 72) * 2;   // 35840
    cudaFuncSetAttribute(k_projQ, cudaFuncAttributeMaxDynamicSharedMemorySize, SM_PROJ);
    cudaFuncSetAttribute(k_projV, cudaFuncAttributeMaxDynamicSharedMemorySize, SM_PROJ);
    cudaFuncSetAttribute(k_projF, cudaFuncAttributeMaxDynamicSharedMemorySize, SM_PROJ);
    cudaFuncSetAttribute(k_sim,   cudaFuncAttributeMaxDynamicSharedMemorySize, SM_SIM);
    cudaFuncSetAttribute(k_av,    cudaFuncAttributeMaxDynamicSharedMemorySize, SM_AV);
    cudaFuncSetAttribute(k_avt,   cudaFuncAttributeMaxDynamicSharedMemorySize, SM_AVT);

    const size_t WSZ = (size_t)DIM_ * INNER_;

    // 1) layernorms + weight conversion
    ln_kernel<<<B_ * I_, 256>>>(x,   ln_g,  ln_b,  xnh, xnl);
    ln_kernel<<<B_ * J_, 256>>>(ctx, cln_g, cln_b, cnh, cnl);
    const float* ws[6] = {W_qk, W_cqk, W_v, W_cv, W_out, W_cout};
    for (int w = 0; w < 6; w++)
        wconv_kernel<<<2048, 256>>>(ws[w], wh + w * WSZ, wl + w * WSZ);

    // 2) projections
    dim3 gp(DIM_ / 128, (B_ * I_) / 128);
    k_projQ<<<gp, 256, SM_PROJ>>>(xnh, xnl, wh + 0 * WSZ, wl + 0 * WSZ, qkh, qkl);
    k_projQ<<<gp, 256, SM_PROJ>>>(cnh, cnl, wh + 1 * WSZ, wl + 1 * WSZ, ckh, ckl);
    k_projV<<<gp, 256, SM_PROJ>>>(xnh, xnl, wh + 2 * WSZ, wl + 2 * WSZ, vh,  vl);
    k_projV<<<gp, 256, SM_PROJ>>>(cnh, cnl, wh + 3 * WSZ, wl + 3 * WSZ, cvh, cvl);

    // 3) sim -> exp(scale*QK) + softmax stat partials (fused epilogue)
    k_sim<<<dim3(J_ / 128, I_ / 128, NZ_), 256, SM_SIM>>>();

    // 4) reduce partials -> 1/rowsum, 1/colsum
    statreduce<<<dim3(NZ_ * I_ / 256, 2), 256>>>();

    // 5) normalize + talking-heads mix -> fp16 attn planes
    mix_kernel<<<dim3(J_ / 256, I_, B_), 256>>>(thw, cthw);

    // 6) attention-weighted values
    k_av <<<dim3(1, I_ / 128, NZ_), 256, SM_AV >>>();
    k_avt<<<dim3(1, J_ / 128, NZ_), 256, SM_AVT>>>();

    // 7) output projections -> d_out
    k_projF<<<gp, 256, SM_PROJ>>>(o1h, o1l, wh + 4 * WSZ, wl + 4 * WSZ, out, b_out);
    k_projF<<<gp, 256, SM_PROJ>>>(o2h, o2l, wh + 5 * WSZ, wl + 5 * WSZ,
                                  out + (size_t)B_ * I_ * DIM_, b_cout);
}

// round 7
// speedup vs baseline: 2.7605x; 1.1152x over previous
#include <cuda_runtime.h>
#include <cuda_bf16.h>
#include <cuda_fp16.h>
#include <math.h>

typedef __nv_bfloat16 bf16;

// ---------------- problem constants ----------------
#define B_     2
#define I_     2048
#define J_     2048
#define DIM_   1024
#define H_     16
#define DH_    64
#define INNER_ 1024
#define EPS_   1e-5f
#define SCALE_ 0.125f   // DH^-0.5
#define SIMN   134217728   // B*H*I*J
#define NZ_    32          // B*H

// ---------------- scratch (device globals; allocation-free) ----------------
__device__ bf16 g_xnh[B_ * I_ * DIM_],  g_xnl[B_ * I_ * DIM_];
__device__ bf16 g_cnh[B_ * J_ * DIM_],  g_cnl[B_ * J_ * DIM_];
__device__ bf16 g_qkh[B_ * I_ * INNER_], g_qkl[B_ * I_ * INNER_];
__device__ bf16 g_ckh[B_ * J_ * INNER_], g_ckl[B_ * J_ * INNER_];
__device__ half g_vh [B_ * I_ * INNER_], g_vl [B_ * I_ * INNER_];
__device__ half g_cvh[B_ * J_ * INNER_], g_cvl[B_ * J_ * INNER_];
__device__ bf16 g_o1h[B_ * I_ * INNER_], g_o1l[B_ * I_ * INNER_];
__device__ bf16 g_o2h[B_ * J_ * INNER_], g_o2l[B_ * J_ * INNER_];
__device__ bf16 g_wh[6][DIM_ * INNER_], g_wl[6][DIM_ * INNER_];
__device__ half g_sim16[SIMN];                // exp(scale*QK) fp16, 256 MB
__device__ half g_at16[SIMN], g_ct16[SIMN];   // mixed attn, fp16
__device__ float g_rp[NZ_ * I_ * 16], g_cp[NZ_ * J_ * 16];  // tile partial sums
__device__ float g_rs[NZ_ * I_], g_cs[NZ_ * J_];            // 1/rowsum, 1/colsum

// ---------------- helpers ----------------
__device__ __forceinline__ unsigned packsplit(float x, float y, unsigned& lo) {
    bf16 hx = __float2bfloat16(x);
    bf16 hy = __float2bfloat16(y);
    float lx = x - __bfloat162float(hx);
    float ly = y - __bfloat162float(hy);
    __nv_bfloat162 l2 = __floats2bfloat162_rn(lx, ly);
    lo = *(unsigned*)&l2;
    __nv_bfloat162 h2 = __halves2bfloat162(hx, hy);
    return *(unsigned*)&h2;
}
__device__ __forceinline__ unsigned packsplit_h(float x, float y, unsigned& lo) {
    half hx = __float2half(x);
    half hy = __float2half(y);
    float lx = x - __half2float(hx);
    float ly = y - __half2float(hy);
    half2 l2 = __floats2half2_rn(lx, ly);
    lo = *(unsigned*)&l2;
    half2 h2 = __halves2half2(hx, hy);
    return *(unsigned*)&h2;
}
template <class T> struct Mma;
template <> struct Mma<bf16> {
    static __device__ __forceinline__ void op(float* c, const unsigned* a,
                                              const unsigned* b) {
        asm volatile(
            "mma.sync.aligned.m16n8k16.row.col.f32.bf16.bf16.f32 "
            "{%0,%1,%2,%3}, {%4,%5,%6,%7}, {%8,%9}, {%0,%1,%2,%3};\n"
            : "+f"(c[0]), "+f"(c[1]), "+f"(c[2]), "+f"(c[3])
            : "r"(a[0]), "r"(a[1]), "r"(a[2]), "r"(a[3]), "r"(b[0]), "r"(b[1]));
    }
};
template <> struct Mma<half> {
    static __device__ __forceinline__ void op(float* c, const unsigned* a,
                                              const unsigned* b) {
        asm volatile(
            "mma.sync.aligned.m16n8k16.row.col.f32.f16.f16.f32 "
            "{%0,%1,%2,%3}, {%4,%5,%6,%7}, {%8,%9}, {%0,%1,%2,%3};\n"
            : "+f"(c[0]), "+f"(c[1]), "+f"(c[2]), "+f"(c[3])
            : "r"(a[0]), "r"(a[1]), "r"(a[2]), "r"(a[3]), "r"(b[0]), "r"(b[1]));
    }
};
__device__ __forceinline__ void ldsm4(unsigned* d, unsigned a) {
    asm volatile("ldmatrix.sync.aligned.m8n8.x4.shared.b16 {%0,%1,%2,%3},[%4];\n"
                 : "=r"(d[0]), "=r"(d[1]), "=r"(d[2]), "=r"(d[3]) : "r"(a));
}
__device__ __forceinline__ void ldsm4t(unsigned* d, unsigned a) {
    asm volatile("ldmatrix.sync.aligned.m8n8.x4.trans.shared.b16 {%0,%1,%2,%3},[%4];\n"
                 : "=r"(d[0]), "=r"(d[1]), "=r"(d[2]), "=r"(d[3]) : "r"(a));
}
__device__ __forceinline__ void cp16(void* smp, const void* gp) {
    unsigned sa = (unsigned)__cvta_generic_to_shared(smp);
    asm volatile("cp.async.cg.shared.global [%0], [%1], 16;\n" :: "r"(sa), "l"(gp));
}
__device__ __forceinline__ unsigned shaddr(const void* p) {
    return (unsigned)__cvta_generic_to_shared(p);
}

// ---------------- LayerNorm -> bf16 hi/lo planes ----------------
__global__ void ln_kernel(const float* __restrict__ x,
                          const float* __restrict__ gw,
                          const float* __restrict__ bw,
                          bf16* __restrict__ oh, bf16* __restrict__ ol) {
    int row = blockIdx.x;
    const float* xr = x + (size_t)row * DIM_;
    int t = threadIdx.x;
    int c = t * 4;

    float4 v = *(const float4*)(xr + c);
    float s = v.x + v.y + v.z + v.w;
    float sq = v.x * v.x + v.y * v.y + v.z * v.z + v.w * v.w;
    __shared__ float sh[64];
#pragma unroll
    for (int o = 16; o > 0; o >>= 1) {
        s  += __shfl_down_sync(0xffffffffu, s,  o);
        sq += __shfl_down_sync(0xffffffffu, sq, o);
    }
    if ((t & 31) == 0) { sh[t >> 5] = s; sh[32 + (t >> 5)] = sq; }
    __syncthreads();
    if (t < 32) {
        float a  = (t < 8) ? sh[t]      : 0.f;
        float b2 = (t < 8) ? sh[32 + t] : 0.f;
#pragma unroll
        for (int o = 4; o > 0; o >>= 1) {
            a  += __shfl_down_sync(0xffffffffu, a,  o);
            b2 += __shfl_down_sync(0xffffffffu, b2, o);
        }
        if (t == 0) { sh[0] = a; sh[1] = b2; }
    }
    __syncthreads();
    float mu   = sh[0] * (1.f / DIM_);
    float var  = sh[1] * (1.f / DIM_) - mu * mu;
    float rstd = rsqrtf(var + EPS_);
    float y0 = (v.x - mu) * rstd * gw[c + 0] + bw[c + 0];
    float y1 = (v.y - mu) * rstd * gw[c + 1] + bw[c + 1];
    float y2 = (v.z - mu) * rstd * gw[c + 2] + bw[c + 2];
    float y3 = (v.w - mu) * rstd * gw[c + 3] + bw[c + 3];
    size_t o0 = (size_t)row * DIM_ + c;
    unsigned lo, hi;
    hi = packsplit(y0, y1, lo);
    *(unsigned*)&oh[o0] = hi; *(unsigned*)&ol[o0] = lo;
    hi = packsplit(y2, y3, lo);
    *(unsigned*)&oh[o0 + 2] = hi; *(unsigned*)&ol[o0 + 2] = lo;
}

// ---------------- all 6 weights fp32 -> bf16 hi/lo, single launch ---------
__global__ void wconv_all(const float* __restrict__ w0, const float* __restrict__ w1,
                          const float* __restrict__ w2, const float* __restrict__ w3,
                          const float* __restrict__ w4, const float* __restrict__ w5,
                          bf16* __restrict__ Wh, bf16* __restrict__ Wl) {
    const float* srcs[6] = {w0, w1, w2, w3, w4, w5};
    int w = blockIdx.y;
    const float* W = srcs[w];
    size_t base = (size_t)w * DIM_ * INNER_;
    size_t i = ((size_t)blockIdx.x * 256 + threadIdx.x) * 2;
    float2 v = *(const float2*)(W + i);
    unsigned lo, hi = packsplit(v.x, v.y, lo);
    *(unsigned*)&Wh[base + i] = hi;
    *(unsigned*)&Wl[base + i] = lo;
}

// ================= hi/lo split tensor-core GEMM =================
// DT: bf16 or half.  A: ATR ? [K][M] : [M][K].  B: BKN ? [K][N] : [N][K].
// APL: # of A planes.  OMODE: 0 fp32+bias; 1 bf16 planes; 2 exp->fp16 sim +
// softmax stat partials; 3 fp16 planes.
template <class DT, int BN, bool ATR, bool BKN, int APL, int OMODE>
__device__ __forceinline__ void tgemm(const DT* __restrict__ Ah,
                                      const DT* __restrict__ Al, int lda,
                                      const DT* __restrict__ Bh,
                                      const DT* __restrict__ Bl, int ldb,
                                      float* __restrict__ C,
                                      bf16* __restrict__ Ch,
                                      bf16* __restrict__ Cl,
                                      half* __restrict__ Fh,
                                      half* __restrict__ Fl,
                                      int ldc, int K,
                                      const float* __restrict__ bias,
                                      float alpha) {
    constexpr int BM = 128, BK = 32;
    constexpr int SAS = ATR ? (BM + 8) : (BK + 8);
    constexpr int SBS = BKN ? (BN + 8) : (BK + 8);
    constexpr int ASZ = (ATR ? BK : BM) * SAS;
    constexpr int BSZ = (BKN ? BK : BN) * SBS;
    constexpr int NT8 = BN / 16;
    constexpr int NG  = BN / 32;
    constexpr int CB  = BN * 4;

    extern __shared__ unsigned char smraw[];
    DT* sm = (DT*)smraw;
    const int t = threadIdx.x, lane = t & 31, warp = t >> 5;
    const int gi = lane >> 2, gj = lane & 3;
    const int wm = (warp >> 1) * 32, wn = (warp & 1) * (BN / 2);
    const int m0 = blockIdx.y * BM, n0 = blockIdx.x * BN;

    float acc[2][NT8][4];
#pragma unroll
    for (int a = 0; a < 2; a++)
#pragma unroll
        for (int b = 0; b < NT8; b++)
#pragma unroll
            for (int q = 0; q < 4; q++) acc[a][b][q] = 0.f;

    auto cpA = [&](int kc, int bufi) {
#pragma unroll
        for (int p = 0; p < APL; p++) {
            const DT* src = p ? Al : Ah;
            DT* dst = sm + p * 2 * ASZ + bufi * ASZ;
            if (!ATR) {
#pragma unroll
                for (int q = t; q < 512; q += 256) {
                    int row = q >> 2, c = (q & 3) * 8;
                    cp16(dst + row * SAS + c,
                         src + (size_t)(m0 + row) * lda + kc * BK + c);
                }
            } else {
#pragma unroll
                for (int q = t; q < 512; q += 256) {
                    int row = q >> 4, c = (q & 15) * 8;
                    cp16(dst + row * SAS + c,
                         src + (size_t)(kc * BK + row) * lda + m0 + c);
                }
            }
        }
    };
    auto cpB = [&](int kc, int bufi) {
#pragma unroll
        for (int p = 0; p < 2; p++) {
            const DT* src = p ? Bl : Bh;
            DT* dst = sm + APL * 2 * ASZ + p * 2 * BSZ + bufi * BSZ;
            if (BKN) {
#pragma unroll
                for (int q = t; q < CB; q += 256) {
                    int row = q / (BN / 8), c = (q % (BN / 8)) * 8;
                    cp16(dst + row * SBS + c,
                         src + (size_t)(kc * BK + row) * ldb + n0 + c);
                }
            } else {
#pragma unroll
                for (int q = t; q < CB; q += 256) {
                    int row = q >> 2, c = (q & 3) * 8;
                    cp16(dst + row * SBS + c,
                         src + (size_t)(n0 + row) * ldb + kc * BK + c);
                }
            }
        }
    };

    const int NK = K / BK;
    cpA(0, 0); cpB(0, 0);
    asm volatile("cp.async.commit_group;\n");
    int buf = 0;

    for (int kc = 0; kc < NK; kc++) {
        if (kc + 1 < NK) {
            cpA(kc + 1, buf ^ 1); cpB(kc + 1, buf ^ 1);
            asm volatile("cp.async.commit_group;\n");
            asm volatile("cp.async.wait_group 1;\n");
        } else {
            asm volatile("cp.async.wait_group 0;\n");
        }
        __syncthreads();

        const DT* sAh = sm + buf * ASZ;
        const DT* sAl = sm + 2 * ASZ + buf * ASZ;
        const DT* sBh = sm + APL * 2 * ASZ + buf * BSZ;
        const DT* sBl = sm + APL * 2 * ASZ + 2 * BSZ + buf * BSZ;

#pragma unroll
        for (int ks = 0; ks < 2; ks++) {
            const int kofs = ks * 16;
            unsigned aH[2][4], aL[2][4];
            if (!ATR) {
                int r = lane & 15, c = (lane >> 4) * 8;
#pragma unroll
                for (int mt = 0; mt < 2; mt++) {
                    int off = (wm + mt * 16 + r) * SAS + kofs + c;
                    ldsm4(aH[mt], shaddr(sAh + off));
                    if (APL == 2) ldsm4(aL[mt], shaddr(sAl + off));
                }
            } else {
                int kr = kofs + (lane & 7) + ((lane >> 4) << 3);
#pragma unroll
                for (int mt = 0; mt < 2; mt++) {
                    int mc = wm + mt * 16 + (lane & 8);
                    int off = kr * SAS + mc;
                    ldsm4t(aH[mt], shaddr(sAh + off));
                    if (APL == 2) ldsm4t(aL[mt], shaddr(sAl + off));
                }
            }
#pragma unroll
            for (int g = 0; g < NG; g++) {
                unsigned bH[4], bL[4];
                int nb = wn + g * 16;
                if (BKN) {
                    int kr = kofs + (lane & 7) + ((lane & 8) ? 8 : 0);
                    int nc = nb + ((lane & 16) ? 8 : 0);
                    int off = kr * SBS + nc;
                    ldsm4t(bH, shaddr(sBh + off));
                    ldsm4t(bL, shaddr(sBl + off));
                } else {
                    int nr = nb + (lane & 7) + ((lane & 16) ? 8 : 0);
                    int kc2 = kofs + ((lane & 8) ? 8 : 0);
                    int off = nr * SBS + kc2;
                    ldsm4(bH, shaddr(sBh + off));
                    ldsm4(bL, shaddr(sBl + off));
                }
#pragma unroll
                for (int mt = 0; mt < 2; mt++) {
                    Mma<DT>::op(acc[mt][2 * g], aH[mt], bH);
                    Mma<DT>::op(acc[mt][2 * g], aH[mt], bL);
                    if (APL == 2) Mma<DT>::op(acc[mt][2 * g], aL[mt], bH);
                    Mma<DT>::op(acc[mt][2 * g + 1], aH[mt], bH + 2);
                    Mma<DT>::op(acc[mt][2 * g + 1], aH[mt], bL + 2);
                    if (APL == 2) Mma<DT>::op(acc[mt][2 * g + 1], aL[mt], bH + 2);
                }
            }
        }
        __syncthreads();
        buf ^= 1;
    }

    if constexpr (OMODE == 2) {
        // exp -> fp16 sim (smem-staged coalesced store) + softmax partials
        __shared__ float rsm[2][128];
        __shared__ float csm[4][128];
        constexpr int SCS = 136;                  // half stride, conflict-free
        half* sc = (half*)smraw;                  // 128*136*2 = 34816 B, fits
        float rsum[2][2] = {};
        float csum[NT8][2] = {};
#pragma unroll
        for (int mt = 0; mt < 2; mt++)
#pragma unroll
            for (int nt = 0; nt < NT8; nt++) {
                int r = wm + mt * 16 + gi;
                int c = wn + nt * 8 + 2 * gj;
                float e0 = __expf(acc[mt][nt][0] * alpha);
                float e1 = __expf(acc[mt][nt][1] * alpha);
                float e2 = __expf(acc[mt][nt][2] * alpha);
                float e3 = __expf(acc[mt][nt][3] * alpha);
                *(half2*)&sc[r * SCS + c]       = __floats2half2_rn(e0, e1);
                *(half2*)&sc[(r + 8) * SCS + c] = __floats2half2_rn(e2, e3);
                rsum[mt][0] += e0 + e1;
                rsum[mt][1] += e2 + e3;
                csum[nt][0] += e0 + e2;
                csum[nt][1] += e1 + e3;
            }
#pragma unroll
        for (int mt = 0; mt < 2; mt++)
#pragma unroll
            for (int rh = 0; rh < 2; rh++) {
                float v = rsum[mt][rh];
                v += __shfl_xor_sync(0xffffffffu, v, 1);
                v += __shfl_xor_sync(0xffffffffu, v, 2);
                if (gj == 0) rsm[warp & 1][wm + mt * 16 + gi + rh * 8] = v;
            }
#pragma unroll
        for (int nt = 0; nt < NT8; nt++)
#pragma unroll
            for (int q = 0; q < 2; q++) {
                float v = csum[nt][q];
                v += __shfl_xor_sync(0xffffffffu, v, 4);
                v += __shfl_xor_sync(0xffffffffu, v, 8);
                v += __shfl_xor_sync(0xffffffffu, v, 16);
                if (gi == 0) csm[warp >> 1][wn + nt * 8 + 2 * gj + q] = v;
            }
        __syncthreads();
        // coalesced flush: 128 rows x 128 halves = 128 x 16 chunks of 16B
#pragma unroll
        for (int it = 0; it < 8; it++) {
            int row = (t >> 4) + it * 16;
            int ch = t & 15;
            uint4 vv = *(uint4*)&sc[row * SCS + ch * 8];
            *(uint4*)&Fh[(size_t)(m0 + row) * ldc + n0 + ch * 8] = vv;
        }
        if (t < 128) {
            float rtot = rsm[0][t] + rsm[1][t];
            g_rp[((size_t)blockIdx.z * I_ + m0 + t) * 16 + blockIdx.x] = rtot;
            float ctot = csm[0][t] + csm[1][t] + csm[2][t] + csm[3][t];
            g_cp[((size_t)blockIdx.z * J_ + n0 + t) * 16 + blockIdx.y] = ctot;
        }
        return;
    }

#pragma unroll
    for (int mt = 0; mt < 2; mt++)
#pragma unroll
        for (int nt = 0; nt < NT8; nt++) {
            int r = m0 + wm + mt * 16 + gi;
            int c = n0 + wn + nt * 8 + 2 * gj;
            const float* a = acc[mt][nt];
            if constexpr (OMODE == 0) {
                float b0 = bias ? bias[c] : 0.f;
                float b1 = bias ? bias[c + 1] : 0.f;
                float2 v0 = {a[0] * alpha + b0, a[1] * alpha + b1};
                float2 v1 = {a[2] * alpha + b0, a[3] * alpha + b1};
                *(float2*)&C[(size_t)r * ldc + c] = v0;
                *(float2*)&C[(size_t)(r + 8) * ldc + c] = v1;
            } else if constexpr (OMODE == 1) {
                unsigned lo, hi;
                hi = packsplit(a[0], a[1], lo);
                *(unsigned*)&Ch[(size_t)r * ldc + c] = hi;
                *(unsigned*)&Cl[(size_t)r * ldc + c] = lo;
                hi = packsplit(a[2], a[3], lo);
                *(unsigned*)&Ch[(size_t)(r + 8) * ldc + c] = hi;
                *(unsigned*)&Cl[(size_t)(r + 8) * ldc + c] = lo;
            } else {   // OMODE == 3
                unsigned lo, hi;
                hi = packsplit_h(a[0], a[1], lo);
                *(unsigned*)&Fh[(size_t)r * ldc + c] = hi;
                *(unsigned*)&Fl[(size_t)r * ldc + c] = lo;
                hi = packsplit_h(a[2], a[3], lo);
                *(unsigned*)&Fh[(size_t)(r + 8) * ldc + c] = hi;
                *(unsigned*)&Fl[(size_t)(r + 8) * ldc + c] = lo;
            }
        }
}

// ---- kernel wrappers ----
__global__ void __launch_bounds__(256) k_projQ(const bf16* Ah, const bf16* Al,
                                               const bf16* Bh, const bf16* Bl,
                                               bf16* Ch, bf16* Cl) {
    tgemm<bf16, 128, false, true, 2, 1>(Ah, Al, DIM_, Bh, Bl, INNER_,
                                        nullptr, Ch, Cl, nullptr, nullptr,
                                        INNER_, DIM_, nullptr, 1.f);
}
__global__ void __launch_bounds__(256) k_projV(const bf16* Ah, const bf16* Al,
                                               const bf16* Bh, const bf16* Bl,
                                               half* Fh, half* Fl) {
    tgemm<bf16, 128, false, true, 2, 3>(Ah, Al, DIM_, Bh, Bl, INNER_,
                                        nullptr, nullptr, nullptr, Fh, Fl,
                                        INNER_, DIM_, nullptr, 1.f);
}
__global__ void __launch_bounds__(256) k_projF(const bf16* Ah, const bf16* Al,
                                               const bf16* Bh, const bf16* Bl,
                                               float* C, const float* bias) {
    tgemm<bf16, 128, false, true, 2, 0>(Ah, Al, INNER_, Bh, Bl, DIM_,
                                        C, nullptr, nullptr, nullptr, nullptr,
                                        DIM_, INNER_, bias, 1.f);
}
// sim: exp(scale*QK) -> fp16 + softmax stat partials
__global__ void __launch_bounds__(256) k_sim() {
    int z = blockIdx.z, b = z >> 4, h = z & 15;
    size_t qo = (size_t)b * I_ * INNER_ + h * DH_;
    size_t ko = (size_t)b * J_ * INNER_ + h * DH_;
    tgemm<bf16, 128, false, false, 2, 2>(g_qkh + qo, g_qkl + qo, INNER_,
                                         g_ckh + ko, g_ckl + ko, INNER_,
                                         nullptr, nullptr, nullptr,
                                         g_sim16 + (size_t)z * I_ * J_, nullptr,
                                         J_, DH_, nullptr, SCALE_);
}
__global__ void __launch_bounds__(256) k_av() {
    int z = blockIdx.z, b = z >> 4, h = z & 15;
    size_t ao = (size_t)z * I_ * J_;
    size_t vo = (size_t)b * J_ * INNER_ + h * DH_;
    size_t oo = (size_t)b * I_ * INNER_ + h * DH_;
    tgemm<half, 64, false, true, 1, 1>(g_at16 + ao, nullptr, J_,
                                       g_cvh + vo, g_cvl + vo, INNER_,
                                       nullptr, g_o1h + oo, g_o1l + oo,
                                       nullptr, nullptr, INNER_, J_, nullptr, 1.f);
}
__global__ void __launch_bounds__(256) k_avt() {
    int z = blockIdx.z, b = z >> 4, h = z & 15;
    size_t ao = (size_t)z * I_ * J_;
    size_t vo = (size_t)b * I_ * INNER_ + h * DH_;
    size_t oo = (size_t)b * J_ * INNER_ + h * DH_;
    tgemm<half, 64, true, true, 1, 1>(g_ct16 + ao, nullptr, J_,
                                      g_vh + vo, g_vl + vo, INNER_,
                                      nullptr, g_o2h + oo, g_o2l + oo,
                                      nullptr, nullptr, INNER_, I_, nullptr, 1.f);
}

// ---------------- stat partial reduction: 1/sum ----------------
__global__ void statreduce() {
    int idx = blockIdx.x * 256 + threadIdx.x;
    const float* src = blockIdx.y ? g_cp : g_rp;
    const float4* s4 = (const float4*)(src + (size_t)idx * 16);
    float4 a = s4[0], b = s4[1], c = s4[2], d = s4[3];
    float s = a.x + a.y + a.z + a.w + b.x + b.y + b.z + b.w
            + c.x + c.y + c.z + c.w + d.x + d.y + d.z + d.w;
    (blockIdx.y ? g_cs : g_rs)[idx] = 1.f / s;
}

// ------- fused softmax-normalize + talking-heads mix, 2 j per thread ------
__global__ void mix_kernel(const float* __restrict__ thw,
                           const float* __restrict__ cthw) {
    int b = blockIdx.z;
    int i = blockIdx.y;
    int t = threadIdx.x;
    int j = (blockIdx.x * 256 + t) * 2;

    __shared__ float wR[16][16], wC[16][16], ri[16];
    wR[t >> 4][t & 15] = thw[t];
    wC[t >> 4][t & 15] = cthw[t];
    if (t < 16) ri[t] = g_rs[((size_t)(b * H_ + t)) * I_ + i];
    __syncthreads();

    float2 pr[16], pc[16];
#pragma unroll
    for (int h = 0; h < 16; h++) {
        size_t zi = (size_t)(b * H_ + h);
        half2 e2 = *(const half2*)&g_sim16[(zi * I_ + i) * J_ + j];
        float2 e = __half22float2(e2);
        float rih = ri[h];
        float2 cv = *(const float2*)&g_cs[zi * J_ + j];
        pr[h].x = e.x * rih;   pr[h].y = e.y * rih;
        pc[h].x = e.x * cv.x;  pc[h].y = e.y * cv.y;
    }
#pragma unroll
    for (int g = 0; g < 16; g++) {
        float aR0 = 0.f, aR1 = 0.f, aC0 = 0.f, aC1 = 0.f;
#pragma unroll
        for (int h = 0; h < 16; h++) {
            float wr = wR[g][h], wc = wC[g][h];
            aR0 += wr * pr[h].x; aR1 += wr * pr[h].y;
            aC0 += wc * pc[h].x; aC1 += wc * pc[h].y;
        }
        size_t idx = (((size_t)(b * H_ + g)) * I_ + i) * J_ + j;
        *(half2*)&g_at16[idx] = __floats2half2_rn(aR0, aR1);
        *(half2*)&g_ct16[idx] = __floats2half2_rn(aC0, aC1);
    }
}

// ---------------- launch ----------------
extern "C" void kernel_launch(void* const* d_in, const int* in_sizes, int n_in,
                              void* d_out, int out_size) {
    const float* x     = (const float*)d_in[0];
    const float* ctx   = (const float*)d_in[1];
    const float* ln_g  = (const float*)d_in[2];
    const float* ln_b  = (const float*)d_in[3];
    const float* cln_g = (const float*)d_in[4];
    const float* cln_b = (const float*)d_in[5];
    const float* W_qk  = (const float*)d_in[6];
    const float* W_cqk = (const float*)d_in[7];
    const float* W_v   = (const float*)d_in[8];
    const float* W_cv  = (const float*)d_in[9];
    const float* W_out = (const float*)d_in[10];
    const float* b_out = (const float*)d_in[11];
    const float* W_cout= (const float*)d_in[12];
    const float* b_cout= (const float*)d_in[13];
    const float* thw   = (const float*)d_in[14];
    const float* cthw  = (const float*)d_in[15];
    float* out = (float*)d_out;

    bf16 *xnh, *xnl, *cnh, *cnl, *qkh, *qkl, *ckh, *ckl, *o1h, *o1l, *o2h, *o2l, *wh, *wl;
    half *vh, *vl, *cvh, *cvl;
    cudaGetSymbolAddress((void**)&xnh, g_xnh); cudaGetSymbolAddress((void**)&xnl, g_xnl);
    cudaGetSymbolAddress((void**)&cnh, g_cnh); cudaGetSymbolAddress((void**)&cnl, g_cnl);
    cudaGetSymbolAddress((void**)&qkh, g_qkh); cudaGetSymbolAddress((void**)&qkl, g_qkl);
    cudaGetSymbolAddress((void**)&ckh, g_ckh); cudaGetSymbolAddress((void**)&ckl, g_ckl);
    cudaGetSymbolAddress((void**)&vh,  g_vh);  cudaGetSymbolAddress((void**)&vl,  g_vl);
    cudaGetSymbolAddress((void**)&cvh, g_cvh); cudaGetSymbolAddress((void**)&cvl, g_cvl);
    cudaGetSymbolAddress((void**)&o1h, g_o1h); cudaGetSymbolAddress((void**)&o1l, g_o1l);
    cudaGetSymbolAddress((void**)&o2h, g_o2h); cudaGetSymbolAddress((void**)&o2l, g_o2l);
    cudaGetSymbolAddress((void**)&wh,  g_wh);  cudaGetSymbolAddress((void**)&wl,  g_wl);

    constexpr int SM_PROJ = (2 * 2 * 128 * 40 + 2 * 2 * 32 * 136) * 2;  // 75776
    constexpr int SM_SIM  = (2 * 2 * 128 * 40 + 2 * 2 * 128 * 40) * 2;  // 81920
    constexpr int SM_AV   = (1 * 2 * 128 * 40 + 2 * 2 * 32 * 72) * 2;   // 38912
    constexpr int SM_AVT  = (1 * 2 * 32 * 136 + 2 * 2 * 32 * 72) * 2;   // 35840
    cudaFuncSetAttribute(k_projQ, cudaFuncAttributeMaxDynamicSharedMemorySize, SM_PROJ);
    cudaFuncSetAttribute(k_projV, cudaFuncAttributeMaxDynamicSharedMemorySize, SM_PROJ);
    cudaFuncSetAttribute(k_projF, cudaFuncAttributeMaxDynamicSharedMemorySize, SM_PROJ);
    cudaFuncSetAttribute(k_sim,   cudaFuncAttributeMaxDynamicSharedMemorySize, SM_SIM);
    cudaFuncSetAttribute(k_av,    cudaFuncAttributeMaxDynamicSharedMemorySize, SM_AV);
    cudaFuncSetAttribute(k_avt,   cudaFuncAttributeMaxDynamicSharedMemorySize, SM_AVT);

    const size_t WSZ = (size_t)DIM_ * INNER_;

    // 1) layernorms + weight conversion (single launch)
    ln_kernel<<<B_ * I_, 256>>>(x,   ln_g,  ln_b,  xnh, xnl);
    ln_kernel<<<B_ * J_, 256>>>(ctx, cln_g, cln_b, cnh, cnl);
    wconv_all<<<dim3(2048, 6), 256>>>(W_qk, W_cqk, W_v, W_cv, W_out, W_cout, wh, wl);

    // 2) projections
    dim3 gp(DIM_ / 128, (B_ * I_) / 128);
    k_projQ<<<gp, 256, SM_PROJ>>>(xnh, xnl, wh + 0 * WSZ, wl + 0 * WSZ, qkh, qkl);
    k_projQ<<<gp, 256, SM_PROJ>>>(cnh, cnl, wh + 1 * WSZ, wl + 1 * WSZ, ckh, ckl);
    k_projV<<<gp, 256, SM_PROJ>>>(xnh, xnl, wh + 2 * WSZ, wl + 2 * WSZ, vh,  vl);
    k_projV<<<gp, 256, SM_PROJ>>>(cnh, cnl, wh + 3 * WSZ, wl + 3 * WSZ, cvh, cvl);

    // 3) sim -> exp (fp16) + softmax stat partials
    k_sim<<<dim3(J_ / 128, I_ / 128, NZ_), 256, SM_SIM>>>();

    // 4) reduce partials -> 1/rowsum, 1/colsum
    statreduce<<<dim3(NZ_ * I_ / 256, 2), 256>>>();

    // 5) normalize + talking-heads mix -> fp16 attn planes
    mix_kernel<<<dim3(J_ / 512, I_, B_), 256>>>(thw, cthw);

    // 6) attention-weighted values
    k_av <<<dim3(1, I_ / 128, NZ_), 256, SM_AV >>>();
    k_avt<<<dim3(1, J_ / 128, NZ_), 256, SM_AVT>>>();

    // 7) output projections -> d_out
    k_projF<<<gp, 256, SM_PROJ>>>(o1h, o1l, wh + 4 * WSZ, wl + 4 * WSZ, out, b_out);
    k_projF<<<gp, 256, SM_PROJ>>>(o2h, o2l, wh + 5 * WSZ, wl + 5 * WSZ,
                                  out + (size_t)B_ * I_ * DIM_, b_cout);
}

// round 8
// speedup vs baseline: 2.8863x; 1.0456x over previous
#include <cuda_runtime.h>
#include <cuda_bf16.h>
#include <cuda_fp16.h>
#include <math.h>

typedef __nv_bfloat16 bf16;

// ---------------- problem constants ----------------
#define B_     2
#define I_     2048
#define J_     2048
#define DIM_   1024
#define H_     16
#define DH_    64
#define INNER_ 1024
#define EPS_   1e-5f
#define SCALE_ 0.125f   // DH^-0.5
#define SIMN   134217728   // B*H*I*J
#define NZ_    32          // B*H

// ---------------- scratch (device globals; allocation-free) ----------------
__device__ bf16 g_xnh[B_ * I_ * DIM_],  g_xnl[B_ * I_ * DIM_];
__device__ bf16 g_cnh[B_ * J_ * DIM_],  g_cnl[B_ * J_ * DIM_];
__device__ bf16 g_qkh[B_ * I_ * INNER_], g_qkl[B_ * I_ * INNER_];
__device__ bf16 g_ckh[B_ * J_ * INNER_], g_ckl[B_ * J_ * INNER_];
__device__ half g_vh [B_ * I_ * INNER_], g_vl [B_ * I_ * INNER_];
__device__ half g_cvh[B_ * J_ * INNER_], g_cvl[B_ * J_ * INNER_];
__device__ bf16 g_o1h[B_ * I_ * INNER_], g_o1l[B_ * I_ * INNER_];
__device__ bf16 g_o2h[B_ * J_ * INNER_], g_o2l[B_ * J_ * INNER_];
__device__ bf16 g_wh[6][DIM_ * INNER_], g_wl[6][DIM_ * INNER_];
__device__ half g_sim16[SIMN];                // exp(scale*QK) fp16, 256 MB
__device__ half g_at16[SIMN], g_ct16[SIMN];   // mixed attn, fp16
__device__ float g_rp[NZ_ * I_ * 16], g_cp[NZ_ * J_ * 16];  // tile partial sums
__device__ float g_rs[NZ_ * I_], g_cs[NZ_ * J_];            // 1/rowsum, 1/colsum

// ---------------- helpers ----------------
__device__ __forceinline__ unsigned packsplit(float x, float y, unsigned& lo) {
    bf16 hx = __float2bfloat16(x);
    bf16 hy = __float2bfloat16(y);
    float lx = x - __bfloat162float(hx);
    float ly = y - __bfloat162float(hy);
    __nv_bfloat162 l2 = __floats2bfloat162_rn(lx, ly);
    lo = *(unsigned*)&l2;
    __nv_bfloat162 h2 = __halves2bfloat162(hx, hy);
    return *(unsigned*)&h2;
}
__device__ __forceinline__ unsigned packsplit_h(float x, float y, unsigned& lo) {
    half hx = __float2half(x);
    half hy = __float2half(y);
    float lx = x - __half2float(hx);
    float ly = y - __half2float(hy);
    half2 l2 = __floats2half2_rn(lx, ly);
    lo = *(unsigned*)&l2;
    half2 h2 = __halves2half2(hx, hy);
    return *(unsigned*)&h2;
}
template <class T> struct Mma;
template <> struct Mma<bf16> {
    static __device__ __forceinline__ void op(float* c, const unsigned* a,
                                              const unsigned* b) {
        asm volatile(
            "mma.sync.aligned.m16n8k16.row.col.f32.bf16.bf16.f32 "
            "{%0,%1,%2,%3}, {%4,%5,%6,%7}, {%8,%9}, {%0,%1,%2,%3};\n"
            : "+f"(c[0]), "+f"(c[1]), "+f"(c[2]), "+f"(c[3])
            : "r"(a[0]), "r"(a[1]), "r"(a[2]), "r"(a[3]), "r"(b[0]), "r"(b[1]));
    }
};
template <> struct Mma<half> {
    static __device__ __forceinline__ void op(float* c, const unsigned* a,
                                              const unsigned* b) {
        asm volatile(
            "mma.sync.aligned.m16n8k16.row.col.f32.f16.f16.f32 "
            "{%0,%1,%2,%3}, {%4,%5,%6,%7}, {%8,%9}, {%0,%1,%2,%3};\n"
            : "+f"(c[0]), "+f"(c[1]), "+f"(c[2]), "+f"(c[3])
            : "r"(a[0]), "r"(a[1]), "r"(a[2]), "r"(a[3]), "r"(b[0]), "r"(b[1]));
    }
};
__device__ __forceinline__ void ldsm4(unsigned* d, unsigned a) {
    asm volatile("ldmatrix.sync.aligned.m8n8.x4.shared.b16 {%0,%1,%2,%3},[%4];\n"
                 : "=r"(d[0]), "=r"(d[1]), "=r"(d[2]), "=r"(d[3]) : "r"(a));
}
__device__ __forceinline__ void ldsm4t(unsigned* d, unsigned a) {
    asm volatile("ldmatrix.sync.aligned.m8n8.x4.trans.shared.b16 {%0,%1,%2,%3},[%4];\n"
                 : "=r"(d[0]), "=r"(d[1]), "=r"(d[2]), "=r"(d[3]) : "r"(a));
}
__device__ __forceinline__ void cp16(void* smp, const void* gp) {
    unsigned sa = (unsigned)__cvta_generic_to_shared(smp);
    asm volatile("cp.async.cg.shared.global [%0], [%1], 16;\n" :: "r"(sa), "l"(gp));
}
__device__ __forceinline__ unsigned shaddr(const void* p) {
    return (unsigned)__cvta_generic_to_shared(p);
}

// ---------------- LayerNorm -> bf16 hi/lo planes ----------------
__global__ void ln_kernel(const float* __restrict__ x,
                          const float* __restrict__ gw,
                          const float* __restrict__ bw,
                          bf16* __restrict__ oh, bf16* __restrict__ ol) {
    int row = blockIdx.x;
    const float* xr = x + (size_t)row * DIM_;
    int t = threadIdx.x;
    int c = t * 4;

    float4 v = *(const float4*)(xr + c);
    float s = v.x + v.y + v.z + v.w;
    float sq = v.x * v.x + v.y * v.y + v.z * v.z + v.w * v.w;
    __shared__ float sh[64];
#pragma unroll
    for (int o = 16; o > 0; o >>= 1) {
        s  += __shfl_down_sync(0xffffffffu, s,  o);
        sq += __shfl_down_sync(0xffffffffu, sq, o);
    }
    if ((t & 31) == 0) { sh[t >> 5] = s; sh[32 + (t >> 5)] = sq; }
    __syncthreads();
    if (t < 32) {
        float a  = (t < 8) ? sh[t]      : 0.f;
        float b2 = (t < 8) ? sh[32 + t] : 0.f;
#pragma unroll
        for (int o = 4; o > 0; o >>= 1) {
            a  += __shfl_down_sync(0xffffffffu, a,  o);
            b2 += __shfl_down_sync(0xffffffffu, b2, o);
        }
        if (t == 0) { sh[0] = a; sh[1] = b2; }
    }
    __syncthreads();
    float mu   = sh[0] * (1.f / DIM_);
    float var  = sh[1] * (1.f / DIM_) - mu * mu;
    float rstd = rsqrtf(var + EPS_);
    float y0 = (v.x - mu) * rstd * gw[c + 0] + bw[c + 0];
    float y1 = (v.y - mu) * rstd * gw[c + 1] + bw[c + 1];
    float y2 = (v.z - mu) * rstd * gw[c + 2] + bw[c + 2];
    float y3 = (v.w - mu) * rstd * gw[c + 3] + bw[c + 3];
    size_t o0 = (size_t)row * DIM_ + c;
    unsigned lo, hi;
    hi = packsplit(y0, y1, lo);
    *(unsigned*)&oh[o0] = hi; *(unsigned*)&ol[o0] = lo;
    hi = packsplit(y2, y3, lo);
    *(unsigned*)&oh[o0 + 2] = hi; *(unsigned*)&ol[o0 + 2] = lo;
}

// ---------------- all 6 weights fp32 -> bf16 hi/lo, single launch ---------
__global__ void wconv_all(const float* __restrict__ w0, const float* __restrict__ w1,
                          const float* __restrict__ w2, const float* __restrict__ w3,
                          const float* __restrict__ w4, const float* __restrict__ w5,
                          bf16* __restrict__ Wh, bf16* __restrict__ Wl) {
    const float* srcs[6] = {w0, w1, w2, w3, w4, w5};
    int w = blockIdx.y;
    const float* W = srcs[w];
    size_t base = (size_t)w * DIM_ * INNER_;
    size_t i = ((size_t)blockIdx.x * 256 + threadIdx.x) * 2;
    float2 v = *(const float2*)(W + i);
    unsigned lo, hi = packsplit(v.x, v.y, lo);
    *(unsigned*)&Wh[base + i] = hi;
    *(unsigned*)&Wl[base + i] = lo;
}

// ================= hi/lo split tensor-core GEMM =================
// DT: bf16 or half.  A: ATR ? [K][M] : [M][K].  B: BKN ? [K][N] : [N][K].
// APL: # of A planes.  OMODE: 0 fp32+bias; 1 bf16 planes; 2 exp->fp16 sim +
// softmax stat partials; 3 fp16 planes.
template <class DT, int BN, bool ATR, bool BKN, int APL, int OMODE>
__device__ __forceinline__ void tgemm(const DT* __restrict__ Ah,
                                      const DT* __restrict__ Al, int lda,
                                      const DT* __restrict__ Bh,
                                      const DT* __restrict__ Bl, int ldb,
                                      float* __restrict__ C,
                                      bf16* __restrict__ Ch,
                                      bf16* __restrict__ Cl,
                                      half* __restrict__ Fh,
                                      half* __restrict__ Fl,
                                      int ldc, int K,
                                      const float* __restrict__ bias,
                                      float alpha) {
    constexpr int BM = 128, BK = 32;
    constexpr int SAS = ATR ? (BM + 8) : (BK + 8);
    constexpr int SBS = BKN ? (BN + 8) : (BK + 8);
    constexpr int ASZ = (ATR ? BK : BM) * SAS;
    constexpr int BSZ = (BKN ? BK : BN) * SBS;
    constexpr int NT8 = BN / 16;
    constexpr int NG  = BN / 32;
    constexpr int CB  = BN * 4;

    extern __shared__ unsigned char smraw[];
    DT* sm = (DT*)smraw;
    const int t = threadIdx.x, lane = t & 31, warp = t >> 5;
    const int gi = lane >> 2, gj = lane & 3;
    const int wm = (warp >> 1) * 32, wn = (warp & 1) * (BN / 2);
    const int m0 = blockIdx.y * BM, n0 = blockIdx.x * BN;

    float acc[2][NT8][4];
#pragma unroll
    for (int a = 0; a < 2; a++)
#pragma unroll
        for (int b = 0; b < NT8; b++)
#pragma unroll
            for (int q = 0; q < 4; q++) acc[a][b][q] = 0.f;

    auto cpA = [&](int kc, int bufi) {
#pragma unroll
        for (int p = 0; p < APL; p++) {
            const DT* src = p ? Al : Ah;
            DT* dst = sm + p * 2 * ASZ + bufi * ASZ;
            if (!ATR) {
#pragma unroll
                for (int q = t; q < 512; q += 256) {
                    int row = q >> 2, c = (q & 3) * 8;
                    cp16(dst + row * SAS + c,
                         src + (size_t)(m0 + row) * lda + kc * BK + c);
                }
            } else {
#pragma unroll
                for (int q = t; q < 512; q += 256) {
                    int row = q >> 4, c = (q & 15) * 8;
                    cp16(dst + row * SAS + c,
                         src + (size_t)(kc * BK + row) * lda + m0 + c);
                }
            }
        }
    };
    auto cpB = [&](int kc, int bufi) {
#pragma unroll
        for (int p = 0; p < 2; p++) {
            const DT* src = p ? Bl : Bh;
            DT* dst = sm + APL * 2 * ASZ + p * 2 * BSZ + bufi * BSZ;
            if (BKN) {
#pragma unroll
                for (int q = t; q < CB; q += 256) {
                    int row = q / (BN / 8), c = (q % (BN / 8)) * 8;
                    cp16(dst + row * SBS + c,
                         src + (size_t)(kc * BK + row) * ldb + n0 + c);
                }
            } else {
#pragma unroll
                for (int q = t; q < CB; q += 256) {
                    int row = q >> 2, c = (q & 3) * 8;
                    cp16(dst + row * SBS + c,
                         src + (size_t)(n0 + row) * ldb + kc * BK + c);
                }
            }
        }
    };

    const int NK = K / BK;
    cpA(0, 0); cpB(0, 0);
    asm volatile("cp.async.commit_group;\n");
    int buf = 0;

    for (int kc = 0; kc < NK; kc++) {
        if (kc + 1 < NK) {
            cpA(kc + 1, buf ^ 1); cpB(kc + 1, buf ^ 1);
            asm volatile("cp.async.commit_group;\n");
            asm volatile("cp.async.wait_group 1;\n");
        } else {
            asm volatile("cp.async.wait_group 0;\n");
        }
        __syncthreads();

        const DT* sAh = sm + buf * ASZ;
        const DT* sAl = sm + 2 * ASZ + buf * ASZ;
        const DT* sBh = sm + APL * 2 * ASZ + buf * BSZ;
        const DT* sBl = sm + APL * 2 * ASZ + 2 * BSZ + buf * BSZ;

#pragma unroll
        for (int ks = 0; ks < 2; ks++) {
            const int kofs = ks * 16;
            unsigned aH[2][4], aL[2][4];
            if (!ATR) {
                int r = lane & 15, c = (lane >> 4) * 8;
#pragma unroll
                for (int mt = 0; mt < 2; mt++) {
                    int off = (wm + mt * 16 + r) * SAS + kofs + c;
                    ldsm4(aH[mt], shaddr(sAh + off));
                    if (APL == 2) ldsm4(aL[mt], shaddr(sAl + off));
                }
            } else {
                int kr = kofs + (lane & 7) + ((lane >> 4) << 3);
#pragma unroll
                for (int mt = 0; mt < 2; mt++) {
                    int mc = wm + mt * 16 + (lane & 8);
                    int off = kr * SAS + mc;
                    ldsm4t(aH[mt], shaddr(sAh + off));
                    if (APL == 2) ldsm4t(aL[mt], shaddr(sAl + off));
                }
            }
#pragma unroll
            for (int g = 0; g < NG; g++) {
                unsigned bH[4], bL[4];
                int nb = wn + g * 16;
                if (BKN) {
                    int kr = kofs + (lane & 7) + ((lane & 8) ? 8 : 0);
                    int nc = nb + ((lane & 16) ? 8 : 0);
                    int off = kr * SBS + nc;
                    ldsm4t(bH, shaddr(sBh + off));
                    ldsm4t(bL, shaddr(sBl + off));
                } else {
                    int nr = nb + (lane & 7) + ((lane & 16) ? 8 : 0);
                    int kc2 = kofs + ((lane & 8) ? 8 : 0);
                    int off = nr * SBS + kc2;
                    ldsm4(bH, shaddr(sBh + off));
                    ldsm4(bL, shaddr(sBl + off));
                }
#pragma unroll
                for (int mt = 0; mt < 2; mt++) {
                    Mma<DT>::op(acc[mt][2 * g], aH[mt], bH);
                    Mma<DT>::op(acc[mt][2 * g], aH[mt], bL);
                    if (APL == 2) Mma<DT>::op(acc[mt][2 * g], aL[mt], bH);
                    Mma<DT>::op(acc[mt][2 * g + 1], aH[mt], bH + 2);
                    Mma<DT>::op(acc[mt][2 * g + 1], aH[mt], bL + 2);
                    if (APL == 2) Mma<DT>::op(acc[mt][2 * g + 1], aL[mt], bH + 2);
                }
            }
        }
        __syncthreads();
        buf ^= 1;
    }

    if constexpr (OMODE == 2) {
        // exp -> fp16 sim (smem-staged coalesced store) + softmax partials
        __shared__ float rsm[2][128];
        __shared__ float csm[4][128];
        constexpr int SCS = 136;                  // half stride, conflict-free
        half* sc = (half*)smraw;                  // 128*136*2 = 34816 B, fits
        float rsum[2][2] = {};
        float csum[NT8][2] = {};
#pragma unroll
        for (int mt = 0; mt < 2; mt++)
#pragma unroll
            for (int nt = 0; nt < NT8; nt++) {
                int r = wm + mt * 16 + gi;
                int c = wn + nt * 8 + 2 * gj;
                float e0 = __expf(acc[mt][nt][0] * alpha);
                float e1 = __expf(acc[mt][nt][1] * alpha);
                float e2 = __expf(acc[mt][nt][2] * alpha);
                float e3 = __expf(acc[mt][nt][3] * alpha);
                *(half2*)&sc[r * SCS + c]       = __floats2half2_rn(e0, e1);
                *(half2*)&sc[(r + 8) * SCS + c] = __floats2half2_rn(e2, e3);
                rsum[mt][0] += e0 + e1;
                rsum[mt][1] += e2 + e3;
                csum[nt][0] += e0 + e2;
                csum[nt][1] += e1 + e3;
            }
#pragma unroll
        for (int mt = 0; mt < 2; mt++)
#pragma unroll
            for (int rh = 0; rh < 2; rh++) {
                float v = rsum[mt][rh];
                v += __shfl_xor_sync(0xffffffffu, v, 1);
                v += __shfl_xor_sync(0xffffffffu, v, 2);
                if (gj == 0) rsm[warp & 1][wm + mt * 16 + gi + rh * 8] = v;
            }
#pragma unroll
        for (int nt = 0; nt < NT8; nt++)
#pragma unroll
            for (int q = 0; q < 2; q++) {
                float v = csum[nt][q];
                v += __shfl_xor_sync(0xffffffffu, v, 4);
                v += __shfl_xor_sync(0xffffffffu, v, 8);
                v += __shfl_xor_sync(0xffffffffu, v, 16);
                if (gi == 0) csm[warp >> 1][wn + nt * 8 + 2 * gj + q] = v;
            }
        __syncthreads();
        // coalesced flush: 128 rows x 128 halves = 128 x 16 chunks of 16B
#pragma unroll
        for (int it = 0; it < 8; it++) {
            int row = (t >> 4) + it * 16;
            int ch = t & 15;
            uint4 vv = *(uint4*)&sc[row * SCS + ch * 8];
            *(uint4*)&Fh[(size_t)(m0 + row) * ldc + n0 + ch * 8] = vv;
        }
        if (t < 128) {
            float rtot = rsm[0][t] + rsm[1][t];
            g_rp[((size_t)blockIdx.z * I_ + m0 + t) * 16 + blockIdx.x] = rtot;
            float ctot = csm[0][t] + csm[1][t] + csm[2][t] + csm[3][t];
            g_cp[((size_t)blockIdx.z * J_ + n0 + t) * 16 + blockIdx.y] = ctot;
        }
        return;
    }

#pragma unroll
    for (int mt = 0; mt < 2; mt++)
#pragma unroll
        for (int nt = 0; nt < NT8; nt++) {
            int r = m0 + wm + mt * 16 + gi;
            int c = n0 + wn + nt * 8 + 2 * gj;
            const float* a = acc[mt][nt];
            if constexpr (OMODE == 0) {
                float b0 = bias ? bias[c] : 0.f;
                float b1 = bias ? bias[c + 1] : 0.f;
                float2 v0 = {a[0] * alpha + b0, a[1] * alpha + b1};
                float2 v1 = {a[2] * alpha + b0, a[3] * alpha + b1};
                *(float2*)&C[(size_t)r * ldc + c] = v0;
                *(float2*)&C[(size_t)(r + 8) * ldc + c] = v1;
            } else if constexpr (OMODE == 1) {
                unsigned lo, hi;
                hi = packsplit(a[0], a[1], lo);
                *(unsigned*)&Ch[(size_t)r * ldc + c] = hi;
                *(unsigned*)&Cl[(size_t)r * ldc + c] = lo;
                hi = packsplit(a[2], a[3], lo);
                *(unsigned*)&Ch[(size_t)(r + 8) * ldc + c] = hi;
                *(unsigned*)&Cl[(size_t)(r + 8) * ldc + c] = lo;
            } else {   // OMODE == 3
                unsigned lo, hi;
                hi = packsplit_h(a[0], a[1], lo);
                *(unsigned*)&Fh[(size_t)r * ldc + c] = hi;
                *(unsigned*)&Fl[(size_t)r * ldc + c] = lo;
                hi = packsplit_h(a[2], a[3], lo);
                *(unsigned*)&Fh[(size_t)(r + 8) * ldc + c] = hi;
                *(unsigned*)&Fl[(size_t)(r + 8) * ldc + c] = lo;
            }
        }
}

// ---- kernel wrappers (all capped for 2 CTAs/SM) ----
__global__ void __launch_bounds__(256, 2) k_projQ(const bf16* Ah, const bf16* Al,
                                                  const bf16* Bh, const bf16* Bl,
                                                  bf16* Ch, bf16* Cl) {
    tgemm<bf16, 128, false, true, 2, 1>(Ah, Al, DIM_, Bh, Bl, INNER_,
                                        nullptr, Ch, Cl, nullptr, nullptr,
                                        INNER_, DIM_, nullptr, 1.f);
}
__global__ void __launch_bounds__(256, 2) k_projV(const bf16* Ah, const bf16* Al,
                                                  const bf16* Bh, const bf16* Bl,
                                                  half* Fh, half* Fl) {
    tgemm<bf16, 128, false, true, 2, 3>(Ah, Al, DIM_, Bh, Bl, INNER_,
                                        nullptr, nullptr, nullptr, Fh, Fl,
                                        INNER_, DIM_, nullptr, 1.f);
}
__global__ void __launch_bounds__(256, 2) k_projF(const bf16* Ah, const bf16* Al,
                                                  const bf16* Bh, const bf16* Bl,
                                                  float* C, const float* bias) {
    tgemm<bf16, 128, false, true, 2, 0>(Ah, Al, INNER_, Bh, Bl, DIM_,
                                        C, nullptr, nullptr, nullptr, nullptr,
                                        DIM_, INNER_, bias, 1.f);
}
// sim: exp(scale*QK) -> fp16 + softmax stat partials
__global__ void __launch_bounds__(256, 2) k_sim() {
    int z = blockIdx.z, b = z >> 4, h = z & 15;
    size_t qo = (size_t)b * I_ * INNER_ + h * DH_;
    size_t ko = (size_t)b * J_ * INNER_ + h * DH_;
    tgemm<bf16, 128, false, false, 2, 2>(g_qkh + qo, g_qkl + qo, INNER_,
                                         g_ckh + ko, g_ckl + ko, INNER_,
                                         nullptr, nullptr, nullptr,
                                         g_sim16 + (size_t)z * I_ * J_, nullptr,
                                         J_, DH_, nullptr, SCALE_);
}
__global__ void __launch_bounds__(256, 2) k_av() {
    int z = blockIdx.z, b = z >> 4, h = z & 15;
    size_t ao = (size_t)z * I_ * J_;
    size_t vo = (size_t)b * J_ * INNER_ + h * DH_;
    size_t oo = (size_t)b * I_ * INNER_ + h * DH_;
    tgemm<half, 64, false, true, 1, 1>(g_at16 + ao, nullptr, J_,
                                       g_cvh + vo, g_cvl + vo, INNER_,
                                       nullptr, g_o1h + oo, g_o1l + oo,
                                       nullptr, nullptr, INNER_, J_, nullptr, 1.f);
}
__global__ void __launch_bounds__(256, 2) k_avt() {
    int z = blockIdx.z, b = z >> 4, h = z & 15;
    size_t ao = (size_t)z * I_ * J_;
    size_t vo = (size_t)b * I_ * INNER_ + h * DH_;
    size_t oo = (size_t)b * J_ * INNER_ + h * DH_;
    tgemm<half, 64, true, true, 1, 1>(g_ct16 + ao, nullptr, J_,
                                      g_vh + vo, g_vl + vo, INNER_,
                                      nullptr, g_o2h + oo, g_o2l + oo,
                                      nullptr, nullptr, INNER_, I_, nullptr, 1.f);
}

// ---------------- stat partial reduction: 1/sum ----------------
__global__ void statreduce() {
    int idx = blockIdx.x * 256 + threadIdx.x;
    const float* src = blockIdx.y ? g_cp : g_rp;
    const float4* s4 = (const float4*)(src + (size_t)idx * 16);
    float4 a = s4[0], b = s4[1], c = s4[2], d = s4[3];
    float s = a.x + a.y + a.z + a.w + b.x + b.y + b.z + b.w
            + c.x + c.y + c.z + c.w + d.x + d.y + d.z + d.w;
    (blockIdx.y ? g_cs : g_rs)[idx] = 1.f / s;
}

// ------- fused softmax-normalize + talking-heads mix, 2 j per thread ------
__global__ void mix_kernel(const float* __restrict__ thw,
                           const float* __restrict__ cthw) {
    int b = blockIdx.z;
    int i = blockIdx.y;
    int t = threadIdx.x;
    int j = (blockIdx.x * 256 + t) * 2;

    __shared__ float wR[16][16], wC[16][16], ri[16];
    wR[t >> 4][t & 15] = thw[t];
    wC[t >> 4][t & 15] = cthw[t];
    if (t < 16) ri[t] = g_rs[((size_t)(b * H_ + t)) * I_ + i];
    __syncthreads();

    float2 pr[16], pc[16];
#pragma unroll
    for (int h = 0; h < 16; h++) {
        size_t zi = (size_t)(b * H_ + h);
        half2 e2 = *(const half2*)&g_sim16[(zi * I_ + i) * J_ + j];
        float2 e = __half22float2(e2);
        float rih = ri[h];
        float2 cv = *(const float2*)&g_cs[zi * J_ + j];
        pr[h].x = e.x * rih;   pr[h].y = e.y * rih;
        pc[h].x = e.x * cv.x;  pc[h].y = e.y * cv.y;
    }
#pragma unroll
    for (int g = 0; g < 16; g++) {
        float aR0 = 0.f, aR1 = 0.f, aC0 = 0.f, aC1 = 0.f;
#pragma unroll
        for (int h = 0; h < 16; h++) {
            float wr = wR[g][h], wc = wC[g][h];
            aR0 += wr * pr[h].x; aR1 += wr * pr[h].y;
            aC0 += wc * pc[h].x; aC1 += wc * pc[h].y;
        }
        size_t idx = (((size_t)(b * H_ + g)) * I_ + i) * J_ + j;
        *(half2*)&g_at16[idx] = __floats2half2_rn(aR0, aR1);
        *(half2*)&g_ct16[idx] = __floats2half2_rn(aC0, aC1);
    }
}

// ---------------- launch ----------------
extern "C" void kernel_launch(void* const* d_in, const int* in_sizes, int n_in,
                              void* d_out, int out_size) {
    const float* x     = (const float*)d_in[0];
    const float* ctx   = (const float*)d_in[1];
    const float* ln_g  = (const float*)d_in[2];
    const float* ln_b  = (const float*)d_in[3];
    const float* cln_g = (const float*)d_in[4];
    const float* cln_b = (const float*)d_in[5];
    const float* W_qk  = (const float*)d_in[6];
    const float* W_cqk = (const float*)d_in[7];
    const float* W_v   = (const float*)d_in[8];
    const float* W_cv  = (const float*)d_in[9];
    const float* W_out = (const float*)d_in[10];
    const float* b_out = (const float*)d_in[11];
    const float* W_cout= (const float*)d_in[12];
    const float* b_cout= (const float*)d_in[13];
    const float* thw   = (const float*)d_in[14];
    const float* cthw  = (const float*)d_in[15];
    float* out = (float*)d_out;

    bf16 *xnh, *xnl, *cnh, *cnl, *qkh, *qkl, *ckh, *ckl, *o1h, *o1l, *o2h, *o2l, *wh, *wl;
    half *vh, *vl, *cvh, *cvl;
    cudaGetSymbolAddress((void**)&xnh, g_xnh); cudaGetSymbolAddress((void**)&xnl, g_xnl);
    cudaGetSymbolAddress((void**)&cnh, g_cnh); cudaGetSymbolAddress((void**)&cnl, g_cnl);
    cudaGetSymbolAddress((void**)&qkh, g_qkh); cudaGetSymbolAddress((void**)&qkl, g_qkl);
    cudaGetSymbolAddress((void**)&ckh, g_ckh); cudaGetSymbolAddress((void**)&ckl, g_ckl);
    cudaGetSymbolAddress((void**)&vh,  g_vh);  cudaGetSymbolAddress((void**)&vl,  g_vl);
    cudaGetSymbolAddress((void**)&cvh, g_cvh); cudaGetSymbolAddress((void**)&cvl, g_cvl);
    cudaGetSymbolAddress((void**)&o1h, g_o1h); cudaGetSymbolAddress((void**)&o1l, g_o1l);
    cudaGetSymbolAddress((void**)&o2h, g_o2h); cudaGetSymbolAddress((void**)&o2l, g_o2l);
    cudaGetSymbolAddress((void**)&wh,  g_wh);  cudaGetSymbolAddress((void**)&wl,  g_wl);

    constexpr int SM_PROJ = (2 * 2 * 128 * 40 + 2 * 2 * 32 * 136) * 2;  // 75776
    constexpr int SM_SIM  = (2 * 2 * 128 * 40 + 2 * 2 * 128 * 40) * 2;  // 81920
    constexpr int SM_AV   = (1 * 2 * 128 * 40 + 2 * 2 * 32 * 72) * 2;   // 38912
    constexpr int SM_AVT  = (1 * 2 * 32 * 136 + 2 * 2 * 32 * 72) * 2;   // 35840
    cudaFuncSetAttribute(k_projQ, cudaFuncAttributeMaxDynamicSharedMemorySize, SM_PROJ);
    cudaFuncSetAttribute(k_projV, cudaFuncAttributeMaxDynamicSharedMemorySize, SM_PROJ);
    cudaFuncSetAttribute(k_projF, cudaFuncAttributeMaxDynamicSharedMemorySize, SM_PROJ);
    cudaFuncSetAttribute(k_sim,   cudaFuncAttributeMaxDynamicSharedMemorySize, SM_SIM);
    cudaFuncSetAttribute(k_av,    cudaFuncAttributeMaxDynamicSharedMemorySize, SM_AV);
    cudaFuncSetAttribute(k_avt,   cudaFuncAttributeMaxDynamicSharedMemorySize, SM_AVT);

    const size_t WSZ = (size_t)DIM_ * INNER_;

    // 1) layernorms + weight conversion (single launch)
    ln_kernel<<<B_ * I_, 256>>>(x,   ln_g,  ln_b,  xnh, xnl);
    ln_kernel<<<B_ * J_, 256>>>(ctx, cln_g, cln_b, cnh, cnl);
    wconv_all<<<dim3(2048, 6), 256>>>(W_qk, W_cqk, W_v, W_cv, W_out, W_cout, wh, wl);

    // 2) projections
    dim3 gp(DIM_ / 128, (B_ * I_) / 128);
    k_projQ<<<gp, 256, SM_PROJ>>>(xnh, xnl, wh + 0 * WSZ, wl + 0 * WSZ, qkh, qkl);
    k_projQ<<<gp, 256, SM_PROJ>>>(cnh, cnl, wh + 1 * WSZ, wl + 1 * WSZ, ckh, ckl);
    k_projV<<<gp, 256, SM_PROJ>>>(xnh, xnl, wh + 2 * WSZ, wl + 2 * WSZ, vh,  vl);
    k_projV<<<gp, 256, SM_PROJ>>>(cnh, cnl, wh + 3 * WSZ, wl + 3 * WSZ, cvh, cvl);

    // 3) sim -> exp (fp16) + softmax stat partials
    k_sim<<<dim3(J_ / 128, I_ / 128, NZ_), 256, SM_SIM>>>();

    // 4) reduce partials -> 1/rowsum, 1/colsum
    statreduce<<<dim3(NZ_ * I_ / 256, 2), 256>>>();

    // 5) normalize + talking-heads mix -> fp16 attn planes
    mix_kernel<<<dim3(J_ / 512, I_, B_), 256>>>(thw, cthw);

    // 6) attention-weighted values
    k_av <<<dim3(1, I_ / 128, NZ_), 256, SM_AV >>>();
    k_avt<<<dim3(1, J_ / 128, NZ_), 256, SM_AVT>>>();

    // 7) output projections -> d_out
    k_projF<<<gp, 256, SM_PROJ>>>(o1h, o1l, wh + 4 * WSZ, wl + 4 * WSZ, out, b_out);
    k_projF<<<gp, 256, SM_PROJ>>>(o2h, o2l, wh + 5 * WSZ, wl + 5 * WSZ,
                                  out + (size_t)B_ * I_ * DIM_, b_cout);
}

// round 9
// speedup vs baseline: 3.0948x; 1.0722x over previous
#include <cuda_runtime.h>
#include <cuda_bf16.h>
#include <cuda_fp16.h>
#include <math.h>

typedef __nv_bfloat16 bf16;

// ---------------- problem constants ----------------
#define B_     2
#define I_     2048
#define J_     2048
#define DIM_   1024
#define H_     16
#define DH_    64
#define INNER_ 1024
#define EPS_   1e-5f
#define SCALE_ 0.125f   // DH^-0.5
#define SIMN   134217728   // B*H*I*J
#define NZ_    32          // B*H

// ---------------- scratch (device globals; allocation-free) ----------------
__device__ bf16 g_xnh[B_ * I_ * DIM_],  g_xnl[B_ * I_ * DIM_];
__device__ bf16 g_cnh[B_ * J_ * DIM_],  g_cnl[B_ * J_ * DIM_];
__device__ bf16 g_qkh[B_ * I_ * INNER_], g_qkl[B_ * I_ * INNER_];
__device__ bf16 g_ckh[B_ * J_ * INNER_], g_ckl[B_ * J_ * INNER_];
__device__ half g_vh [B_ * I_ * INNER_], g_vl [B_ * I_ * INNER_];
__device__ half g_cvh[B_ * J_ * INNER_], g_cvl[B_ * J_ * INNER_];
__device__ bf16 g_o1h[B_ * I_ * INNER_], g_o1l[B_ * I_ * INNER_];
__device__ bf16 g_o2h[B_ * J_ * INNER_], g_o2l[B_ * J_ * INNER_];
__device__ bf16 g_wh[6][DIM_ * INNER_], g_wl[6][DIM_ * INNER_];
__device__ half g_sim16[SIMN];                // exp(scale*QK) fp16, 256 MB
__device__ half g_at16[SIMN], g_ct16[SIMN];   // mixed attn, fp16
__device__ float g_rp[NZ_ * I_ * 16], g_cp[NZ_ * J_ * 16];  // tile partial sums
__device__ float g_rs[NZ_ * I_], g_cs[NZ_ * J_];            // 1/rowsum, 1/colsum

// ---------------- helpers ----------------
__device__ __forceinline__ unsigned packsplit(float x, float y, unsigned& lo) {
    bf16 hx = __float2bfloat16(x);
    bf16 hy = __float2bfloat16(y);
    float lx = x - __bfloat162float(hx);
    float ly = y - __bfloat162float(hy);
    __nv_bfloat162 l2 = __floats2bfloat162_rn(lx, ly);
    lo = *(unsigned*)&l2;
    __nv_bfloat162 h2 = __halves2bfloat162(hx, hy);
    return *(unsigned*)&h2;
}
__device__ __forceinline__ unsigned packsplit_h(float x, float y, unsigned& lo) {
    half hx = __float2half(x);
    half hy = __float2half(y);
    float lx = x - __half2float(hx);
    float ly = y - __half2float(hy);
    half2 l2 = __floats2half2_rn(lx, ly);
    lo = *(unsigned*)&l2;
    half2 h2 = __halves2half2(hx, hy);
    return *(unsigned*)&h2;
}
template <class T> struct Mma;
template <> struct Mma<bf16> {
    static __device__ __forceinline__ void op(float* c, const unsigned* a,
                                              const unsigned* b) {
        asm volatile(
            "mma.sync.aligned.m16n8k16.row.col.f32.bf16.bf16.f32 "
            "{%0,%1,%2,%3}, {%4,%5,%6,%7}, {%8,%9}, {%0,%1,%2,%3};\n"
            : "+f"(c[0]), "+f"(c[1]), "+f"(c[2]), "+f"(c[3])
            : "r"(a[0]), "r"(a[1]), "r"(a[2]), "r"(a[3]), "r"(b[0]), "r"(b[1]));
    }
};
template <> struct Mma<half> {
    static __device__ __forceinline__ void op(float* c, const unsigned* a,
                                              const unsigned* b) {
        asm volatile(
            "mma.sync.aligned.m16n8k16.row.col.f32.f16.f16.f32 "
            "{%0,%1,%2,%3}, {%4,%5,%6,%7}, {%8,%9}, {%0,%1,%2,%3};\n"
            : "+f"(c[0]), "+f"(c[1]), "+f"(c[2]), "+f"(c[3])
            : "r"(a[0]), "r"(a[1]), "r"(a[2]), "r"(a[3]), "r"(b[0]), "r"(b[1]));
    }
};
__device__ __forceinline__ void ldsm4(unsigned* d, unsigned a) {
    asm volatile("ldmatrix.sync.aligned.m8n8.x4.shared.b16 {%0,%1,%2,%3},[%4];\n"
                 : "=r"(d[0]), "=r"(d[1]), "=r"(d[2]), "=r"(d[3]) : "r"(a));
}
__device__ __forceinline__ void ldsm4t(unsigned* d, unsigned a) {
    asm volatile("ldmatrix.sync.aligned.m8n8.x4.trans.shared.b16 {%0,%1,%2,%3},[%4];\n"
                 : "=r"(d[0]), "=r"(d[1]), "=r"(d[2]), "=r"(d[3]) : "r"(a));
}
__device__ __forceinline__ void cp16(void* smp, const void* gp) {
    unsigned sa = (unsigned)__cvta_generic_to_shared(smp);
    asm volatile("cp.async.cg.shared.global [%0], [%1], 16;\n" :: "r"(sa), "l"(gp));
}
__device__ __forceinline__ unsigned shaddr(const void* p) {
    return (unsigned)__cvta_generic_to_shared(p);
}

// ---------------- LayerNorm -> bf16 hi/lo planes ----------------
__global__ void ln_kernel(const float* __restrict__ x,
                          const float* __restrict__ gw,
                          const float* __restrict__ bw,
                          bf16* __restrict__ oh, bf16* __restrict__ ol) {
    int row = blockIdx.x;
    const float* xr = x + (size_t)row * DIM_;
    int t = threadIdx.x;
    int c = t * 4;

    float4 v = *(const float4*)(xr + c);
    float s = v.x + v.y + v.z + v.w;
    float sq = v.x * v.x + v.y * v.y + v.z * v.z + v.w * v.w;
    __shared__ float sh[64];
#pragma unroll
    for (int o = 16; o > 0; o >>= 1) {
        s  += __shfl_down_sync(0xffffffffu, s,  o);
        sq += __shfl_down_sync(0xffffffffu, sq, o);
    }
    if ((t & 31) == 0) { sh[t >> 5] = s; sh[32 + (t >> 5)] = sq; }
    __syncthreads();
    if (t < 32) {
        float a  = (t < 8) ? sh[t]      : 0.f;
        float b2 = (t < 8) ? sh[32 + t] : 0.f;
#pragma unroll
        for (int o = 4; o > 0; o >>= 1) {
            a  += __shfl_down_sync(0xffffffffu, a,  o);
            b2 += __shfl_down_sync(0xffffffffu, b2, o);
        }
        if (t == 0) { sh[0] = a; sh[1] = b2; }
    }
    __syncthreads();
    float mu   = sh[0] * (1.f / DIM_);
    float var  = sh[1] * (1.f / DIM_) - mu * mu;
    float rstd = rsqrtf(var + EPS_);
    float y0 = (v.x - mu) * rstd * gw[c + 0] + bw[c + 0];
    float y1 = (v.y - mu) * rstd * gw[c + 1] + bw[c + 1];
    float y2 = (v.z - mu) * rstd * gw[c + 2] + bw[c + 2];
    float y3 = (v.w - mu) * rstd * gw[c + 3] + bw[c + 3];
    size_t o0 = (size_t)row * DIM_ + c;
    unsigned lo, hi;
    hi = packsplit(y0, y1, lo);
    *(unsigned*)&oh[o0] = hi; *(unsigned*)&ol[o0] = lo;
    hi = packsplit(y2, y3, lo);
    *(unsigned*)&oh[o0 + 2] = hi; *(unsigned*)&ol[o0 + 2] = lo;
}

// ---------------- all 6 weights fp32 -> bf16 hi/lo, single launch ---------
__global__ void wconv_all(const float* __restrict__ w0, const float* __restrict__ w1,
                          const float* __restrict__ w2, const float* __restrict__ w3,
                          const float* __restrict__ w4, const float* __restrict__ w5,
                          bf16* __restrict__ Wh, bf16* __restrict__ Wl) {
    const float* srcs[6] = {w0, w1, w2, w3, w4, w5};
    int w = blockIdx.y;
    const float* W = srcs[w];
    size_t base = (size_t)w * DIM_ * INNER_;
    size_t i = ((size_t)blockIdx.x * 256 + threadIdx.x) * 2;
    float2 v = *(const float2*)(W + i);
    unsigned lo, hi = packsplit(v.x, v.y, lo);
    *(unsigned*)&Wh[base + i] = hi;
    *(unsigned*)&Wl[base + i] = lo;
}

// ================= hi/lo split tensor-core GEMM =================
// DT: bf16 or half.  A: ATR ? [K][M] : [M][K].  B: BKN ? [K][N] : [N][K].
// APL: # of A planes.  OMODE: 0 fp32+bias; 1 bf16 planes; 2 exp->fp16 sim +
// softmax stat partials; 3 fp16 planes.
template <class DT, int BN, bool ATR, bool BKN, int APL, int OMODE>
__device__ __forceinline__ void tgemm(const DT* __restrict__ Ah,
                                      const DT* __restrict__ Al, int lda,
                                      const DT* __restrict__ Bh,
                                      const DT* __restrict__ Bl, int ldb,
                                      float* __restrict__ C,
                                      bf16* __restrict__ Ch,
                                      bf16* __restrict__ Cl,
                                      half* __restrict__ Fh,
                                      half* __restrict__ Fl,
                                      int ldc, int K,
                                      const float* __restrict__ bias,
                                      float alpha) {
    constexpr int BM = 128, BK = 32;
    constexpr int SAS = ATR ? (BM + 8) : (BK + 8);
    constexpr int SBS = BKN ? (BN + 8) : (BK + 8);
    constexpr int ASZ = (ATR ? BK : BM) * SAS;
    constexpr int BSZ = (BKN ? BK : BN) * SBS;
    constexpr int NT8 = BN / 16;
    constexpr int NG  = BN / 32;
    constexpr int CB  = BN * 4;

    extern __shared__ unsigned char smraw[];
    DT* sm = (DT*)smraw;
    const int t = threadIdx.x, lane = t & 31, warp = t >> 5;
    const int gi = lane >> 2, gj = lane & 3;
    const int wm = (warp >> 1) * 32, wn = (warp & 1) * (BN / 2);
    const int m0 = blockIdx.y * BM, n0 = blockIdx.x * BN;

    float acc[2][NT8][4];
#pragma unroll
    for (int a = 0; a < 2; a++)
#pragma unroll
        for (int b = 0; b < NT8; b++)
#pragma unroll
            for (int q = 0; q < 4; q++) acc[a][b][q] = 0.f;

    auto cpA = [&](int kc, int bufi) {
#pragma unroll
        for (int p = 0; p < APL; p++) {
            const DT* src = p ? Al : Ah;
            DT* dst = sm + p * 2 * ASZ + bufi * ASZ;
            if (!ATR) {
#pragma unroll
                for (int q = t; q < 512; q += 256) {
                    int row = q >> 2, c = (q & 3) * 8;
                    cp16(dst + row * SAS + c,
                         src + (size_t)(m0 + row) * lda + kc * BK + c);
                }
            } else {
#pragma unroll
                for (int q = t; q < 512; q += 256) {
                    int row = q >> 4, c = (q & 15) * 8;
                    cp16(dst + row * SAS + c,
                         src + (size_t)(kc * BK + row) * lda + m0 + c);
                }
            }
        }
    };
    auto cpB = [&](int kc, int bufi) {
#pragma unroll
        for (int p = 0; p < 2; p++) {
            const DT* src = p ? Bl : Bh;
            DT* dst = sm + APL * 2 * ASZ + p * 2 * BSZ + bufi * BSZ;
            if (BKN) {
#pragma unroll
                for (int q = t; q < CB; q += 256) {
                    int row = q / (BN / 8), c = (q % (BN / 8)) * 8;
                    cp16(dst + row * SBS + c,
                         src + (size_t)(kc * BK + row) * ldb + n0 + c);
                }
            } else {
#pragma unroll
                for (int q = t; q < CB; q += 256) {
                    int row = q >> 2, c = (q & 3) * 8;
                    cp16(dst + row * SBS + c,
                         src + (size_t)(n0 + row) * ldb + kc * BK + c);
                }
            }
        }
    };

    const int NK = K / BK;
    cpA(0, 0); cpB(0, 0);
    asm volatile("cp.async.commit_group;\n");
    int buf = 0;

    for (int kc = 0; kc < NK; kc++) {
        if (kc + 1 < NK) {
            cpA(kc + 1, buf ^ 1); cpB(kc + 1, buf ^ 1);
            asm volatile("cp.async.commit_group;\n");
            asm volatile("cp.async.wait_group 1;\n");
        } else {
            asm volatile("cp.async.wait_group 0;\n");
        }
        __syncthreads();

        const DT* sAh = sm + buf * ASZ;
        const DT* sAl = sm + 2 * ASZ + buf * ASZ;
        const DT* sBh = sm + APL * 2 * ASZ + buf * BSZ;
        const DT* sBl = sm + APL * 2 * ASZ + 2 * BSZ + buf * BSZ;

#pragma unroll
        for (int ks = 0; ks < 2; ks++) {
            const int kofs = ks * 16;
            unsigned aH[2][4], aL[2][4];
            if (!ATR) {
                int r = lane & 15, c = (lane >> 4) * 8;
#pragma unroll
                for (int mt = 0; mt < 2; mt++) {
                    int off = (wm + mt * 16 + r) * SAS + kofs + c;
                    ldsm4(aH[mt], shaddr(sAh + off));
                    if (APL == 2) ldsm4(aL[mt], shaddr(sAl + off));
                }
            } else {
                int kr = kofs + (lane & 7) + ((lane >> 4) << 3);
#pragma unroll
                for (int mt = 0; mt < 2; mt++) {
                    int mc = wm + mt * 16 + (lane & 8);
                    int off = kr * SAS + mc;
                    ldsm4t(aH[mt], shaddr(sAh + off));
                    if (APL == 2) ldsm4t(aL[mt], shaddr(sAl + off));
                }
            }
#pragma unroll
            for (int g = 0; g < NG; g++) {
                unsigned bH[4], bL[4];
                int nb = wn + g * 16;
                if (BKN) {
                    int kr = kofs + (lane & 7) + ((lane & 8) ? 8 : 0);
                    int nc = nb + ((lane & 16) ? 8 : 0);
                    int off = kr * SBS + nc;
                    ldsm4t(bH, shaddr(sBh + off));
                    ldsm4t(bL, shaddr(sBl + off));
                } else {
                    int nr = nb + (lane & 7) + ((lane & 16) ? 8 : 0);
                    int kc2 = kofs + ((lane & 8) ? 8 : 0);
                    int off = nr * SBS + kc2;
                    ldsm4(bH, shaddr(sBh + off));
                    ldsm4(bL, shaddr(sBl + off));
                }
#pragma unroll
                for (int mt = 0; mt < 2; mt++) {
                    Mma<DT>::op(acc[mt][2 * g], aH[mt], bH);
                    Mma<DT>::op(acc[mt][2 * g], aH[mt], bL);
                    if (APL == 2) Mma<DT>::op(acc[mt][2 * g], aL[mt], bH);
                    Mma<DT>::op(acc[mt][2 * g + 1], aH[mt], bH + 2);
                    Mma<DT>::op(acc[mt][2 * g + 1], aH[mt], bL + 2);
                    if (APL == 2) Mma<DT>::op(acc[mt][2 * g + 1], aL[mt], bH + 2);
                }
            }
        }
        __syncthreads();
        buf ^= 1;
    }

    if constexpr (OMODE == 2) {
        // exp -> fp16 sim (smem-staged coalesced store) + softmax partials
        __shared__ float rsm[2][128];
        __shared__ float csm[4][128];
        constexpr int SCS = 136;                  // half stride, conflict-free
        half* sc = (half*)smraw;                  // 128*136*2 = 34816 B, fits
        float rsum[2][2] = {};
        float csum[NT8][2] = {};
#pragma unroll
        for (int mt = 0; mt < 2; mt++)
#pragma unroll
            for (int nt = 0; nt < NT8; nt++) {
                int r = wm + mt * 16 + gi;
                int c = wn + nt * 8 + 2 * gj;
                float e0 = __expf(acc[mt][nt][0] * alpha);
                float e1 = __expf(acc[mt][nt][1] * alpha);
                float e2 = __expf(acc[mt][nt][2] * alpha);
                float e3 = __expf(acc[mt][nt][3] * alpha);
                *(half2*)&sc[r * SCS + c]       = __floats2half2_rn(e0, e1);
                *(half2*)&sc[(r + 8) * SCS + c] = __floats2half2_rn(e2, e3);
                rsum[mt][0] += e0 + e1;
                rsum[mt][1] += e2 + e3;
                csum[nt][0] += e0 + e2;
                csum[nt][1] += e1 + e3;
            }
#pragma unroll
        for (int mt = 0; mt < 2; mt++)
#pragma unroll
            for (int rh = 0; rh < 2; rh++) {
                float v = rsum[mt][rh];
                v += __shfl_xor_sync(0xffffffffu, v, 1);
                v += __shfl_xor_sync(0xffffffffu, v, 2);
                if (gj == 0) rsm[warp & 1][wm + mt * 16 + gi + rh * 8] = v;
            }
#pragma unroll
        for (int nt = 0; nt < NT8; nt++)
#pragma unroll
            for (int q = 0; q < 2; q++) {
                float v = csum[nt][q];
                v += __shfl_xor_sync(0xffffffffu, v, 4);
                v += __shfl_xor_sync(0xffffffffu, v, 8);
                v += __shfl_xor_sync(0xffffffffu, v, 16);
                if (gi == 0) csm[warp >> 1][wn + nt * 8 + 2 * gj + q] = v;
            }
        __syncthreads();
        // coalesced flush: 128 rows x 128 halves = 128 x 16 chunks of 16B
#pragma unroll
        for (int it = 0; it < 8; it++) {
            int row = (t >> 4) + it * 16;
            int ch = t & 15;
            uint4 vv = *(uint4*)&sc[row * SCS + ch * 8];
            *(uint4*)&Fh[(size_t)(m0 + row) * ldc + n0 + ch * 8] = vv;
        }
        if (t < 128) {
            float rtot = rsm[0][t] + rsm[1][t];
            g_rp[((size_t)blockIdx.z * I_ + m0 + t) * 16 + blockIdx.x] = rtot;
            float ctot = csm[0][t] + csm[1][t] + csm[2][t] + csm[3][t];
            g_cp[((size_t)blockIdx.z * J_ + n0 + t) * 16 + blockIdx.y] = ctot;
        }
        return;
    }

#pragma unroll
    for (int mt = 0; mt < 2; mt++)
#pragma unroll
        for (int nt = 0; nt < NT8; nt++) {
            int r = m0 + wm + mt * 16 + gi;
            int c = n0 + wn + nt * 8 + 2 * gj;
            const float* a = acc[mt][nt];
            if constexpr (OMODE == 0) {
                float b0 = bias ? bias[c] : 0.f;
                float b1 = bias ? bias[c + 1] : 0.f;
                float2 v0 = {a[0] * alpha + b0, a[1] * alpha + b1};
                float2 v1 = {a[2] * alpha + b0, a[3] * alpha + b1};
                *(float2*)&C[(size_t)r * ldc + c] = v0;
                *(float2*)&C[(size_t)(r + 8) * ldc + c] = v1;
            } else if constexpr (OMODE == 1) {
                unsigned lo, hi;
                hi = packsplit(a[0], a[1], lo);
                *(unsigned*)&Ch[(size_t)r * ldc + c] = hi;
                *(unsigned*)&Cl[(size_t)r * ldc + c] = lo;
                hi = packsplit(a[2], a[3], lo);
                *(unsigned*)&Ch[(size_t)(r + 8) * ldc + c] = hi;
                *(unsigned*)&Cl[(size_t)(r + 8) * ldc + c] = lo;
            } else {   // OMODE == 3
                unsigned lo, hi;
                hi = packsplit_h(a[0], a[1], lo);
                *(unsigned*)&Fh[(size_t)r * ldc + c] = hi;
                *(unsigned*)&Fl[(size_t)r * ldc + c] = lo;
                hi = packsplit_h(a[2], a[3], lo);
                *(unsigned*)&Fh[(size_t)(r + 8) * ldc + c] = hi;
                *(unsigned*)&Fl[(size_t)(r + 8) * ldc + c] = lo;
            }
        }
}

// ---- kernel wrappers (all capped for 2 CTAs/SM) ----
// all 4 input projections in ONE launch; z selects {Q, ctxQ, V, ctxV}
__global__ void __launch_bounds__(256, 2) k_proj4() {
    const size_t WSZ = (size_t)DIM_ * INNER_;
    int z = blockIdx.z;
    if (z == 0) {
        tgemm<bf16, 128, false, true, 2, 1>(g_xnh, g_xnl, DIM_,
                                            g_wh[0], g_wl[0], INNER_,
                                            nullptr, g_qkh, g_qkl, nullptr,
                                            nullptr, INNER_, DIM_, nullptr, 1.f);
    } else if (z == 1) {
        tgemm<bf16, 128, false, true, 2, 1>(g_cnh, g_cnl, DIM_,
                                            g_wh[1], g_wl[1], INNER_,
                                            nullptr, g_ckh, g_ckl, nullptr,
                                            nullptr, INNER_, DIM_, nullptr, 1.f);
    } else if (z == 2) {
        tgemm<bf16, 128, false, true, 2, 3>(g_xnh, g_xnl, DIM_,
                                            g_wh[2], g_wl[2], INNER_,
                                            nullptr, nullptr, nullptr,
                                            g_vh, g_vl, INNER_, DIM_, nullptr, 1.f);
    } else {
        tgemm<bf16, 128, false, true, 2, 3>(g_cnh, g_cnl, DIM_,
                                            g_wh[3], g_wl[3], INNER_,
                                            nullptr, nullptr, nullptr,
                                            g_cvh, g_cvl, INNER_, DIM_, nullptr, 1.f);
    }
}
// both output projections in ONE launch
__global__ void __launch_bounds__(256, 2) k_projF2(float* out,
                                                   const float* b_out,
                                                   const float* b_cout) {
    if (blockIdx.z == 0) {
        tgemm<bf16, 128, false, true, 2, 0>(g_o1h, g_o1l, INNER_,
                                            g_wh[4], g_wl[4], DIM_,
                                            out, nullptr, nullptr, nullptr,
                                            nullptr, DIM_, INNER_, b_out, 1.f);
    } else {
        tgemm<bf16, 128, false, true, 2, 0>(g_o2h, g_o2l, INNER_,
                                            g_wh[5], g_wl[5], DIM_,
                                            out + (size_t)B_ * I_ * DIM_,
                                            nullptr, nullptr, nullptr,
                                            nullptr, DIM_, INNER_, b_cout, 1.f);
    }
}
// sim: exp(scale*QK) -> fp16 + softmax stat partials
__global__ void __launch_bounds__(256, 2) k_sim() {
    int z = blockIdx.z, b = z >> 4, h = z & 15;
    size_t qo = (size_t)b * I_ * INNER_ + h * DH_;
    size_t ko = (size_t)b * J_ * INNER_ + h * DH_;
    tgemm<bf16, 128, false, false, 2, 2>(g_qkh + qo, g_qkl + qo, INNER_,
                                         g_ckh + ko, g_ckl + ko, INNER_,
                                         nullptr, nullptr, nullptr,
                                         g_sim16 + (size_t)z * I_ * J_, nullptr,
                                         J_, DH_, nullptr, SCALE_);
}
__global__ void __launch_bounds__(256, 2) k_av() {
    int z = blockIdx.z, b = z >> 4, h = z & 15;
    size_t ao = (size_t)z * I_ * J_;
    size_t vo = (size_t)b * J_ * INNER_ + h * DH_;
    size_t oo = (size_t)b * I_ * INNER_ + h * DH_;
    tgemm<half, 64, false, true, 1, 1>(g_at16 + ao, nullptr, J_,
                                       g_cvh + vo, g_cvl + vo, INNER_,
                                       nullptr, g_o1h + oo, g_o1l + oo,
                                       nullptr, nullptr, INNER_, J_, nullptr, 1.f);
}
__global__ void __launch_bounds__(256, 2) k_avt() {
    int z = blockIdx.z, b = z >> 4, h = z & 15;
    size_t ao = (size_t)z * I_ * J_;
    size_t vo = (size_t)b * I_ * INNER_ + h * DH_;
    size_t oo = (size_t)b * J_ * INNER_ + h * DH_;
    tgemm<half, 64, true, true, 1, 1>(g_ct16 + ao, nullptr, J_,
                                      g_vh + vo, g_vl + vo, INNER_,
                                      nullptr, g_o2h + oo, g_o2l + oo,
                                      nullptr, nullptr, INNER_, I_, nullptr, 1.f);
}

// ---------------- stat partial reduction: 1/sum ----------------
__global__ void statreduce() {
    int idx = blockIdx.x * 256 + threadIdx.x;
    const float* src = blockIdx.y ? g_cp : g_rp;
    const float4* s4 = (const float4*)(src + (size_t)idx * 16);
    float4 a = s4[0], b = s4[1], c = s4[2], d = s4[3];
    float s = a.x + a.y + a.z + a.w + b.x + b.y + b.z + b.w
            + c.x + c.y + c.z + c.w + d.x + d.y + d.z + d.w;
    (blockIdx.y ? g_cs : g_rs)[idx] = 1.f / s;
}

// ------- fused softmax-normalize + talking-heads mix, 2 j per thread ------
__global__ void mix_kernel(const float* __restrict__ thw,
                           const float* __restrict__ cthw) {
    int b = blockIdx.z;
    int i = blockIdx.y;
    int t = threadIdx.x;
    int j = (blockIdx.x * 256 + t) * 2;

    __shared__ float wR[16][16], wC[16][16], ri[16];
    wR[t >> 4][t & 15] = thw[t];
    wC[t >> 4][t & 15] = cthw[t];
    if (t < 16) ri[t] = g_rs[((size_t)(b * H_ + t)) * I_ + i];
    __syncthreads();

    float2 pr[16], pc[16];
#pragma unroll
    for (int h = 0; h < 16; h++) {
        size_t zi = (size_t)(b * H_ + h);
        half2 e2 = *(const half2*)&g_sim16[(zi * I_ + i) * J_ + j];
        float2 e = __half22float2(e2);
        float rih = ri[h];
        float2 cv = *(const float2*)&g_cs[zi * J_ + j];
        pr[h].x = e.x * rih;   pr[h].y = e.y * rih;
        pc[h].x = e.x * cv.x;  pc[h].y = e.y * cv.y;
    }
#pragma unroll
    for (int g = 0; g < 16; g++) {
        float aR0 = 0.f, aR1 = 0.f, aC0 = 0.f, aC1 = 0.f;
#pragma unroll
        for (int h = 0; h < 16; h++) {
            float wr = wR[g][h], wc = wC[g][h];
            aR0 += wr * pr[h].x; aR1 += wr * pr[h].y;
            aC0 += wc * pc[h].x; aC1 += wc * pc[h].y;
        }
        size_t idx = (((size_t)(b * H_ + g)) * I_ + i) * J_ + j;
        *(half2*)&g_at16[idx] = __floats2half2_rn(aR0, aR1);
        *(half2*)&g_ct16[idx] = __floats2half2_rn(aC0, aC1);
    }
}

// ---------------- launch ----------------
extern "C" void kernel_launch(void* const* d_in, const int* in_sizes, int n_in,
                              void* d_out, int out_size) {
    const float* x     = (const float*)d_in[0];
    const float* ctx   = (const float*)d_in[1];
    const float* ln_g  = (const float*)d_in[2];
    const float* ln_b  = (const float*)d_in[3];
    const float* cln_g = (const float*)d_in[4];
    const float* cln_b = (const float*)d_in[5];
    const float* W_qk  = (const float*)d_in[6];
    const float* W_cqk = (const float*)d_in[7];
    const float* W_v   = (const float*)d_in[8];
    const float* W_cv  = (const float*)d_in[9];
    const float* W_out = (const float*)d_in[10];
    const float* b_out = (const float*)d_in[11];
    const float* W_cout= (const float*)d_in[12];
    const float* b_cout= (const float*)d_in[13];
    const float* thw   = (const float*)d_in[14];
    const float* cthw  = (const float*)d_in[15];
    float* out = (float*)d_out;

    bf16 *xnh, *xnl, *cnh, *cnl, *wh, *wl;
    cudaGetSymbolAddress((void**)&xnh, g_xnh); cudaGetSymbolAddress((void**)&xnl, g_xnl);
    cudaGetSymbolAddress((void**)&cnh, g_cnh); cudaGetSymbolAddress((void**)&cnl, g_cnl);
    cudaGetSymbolAddress((void**)&wh,  g_wh);  cudaGetSymbolAddress((void**)&wl,  g_wl);

    constexpr int SM_PROJ = (2 * 2 * 128 * 40 + 2 * 2 * 32 * 136) * 2;  // 75776
    constexpr int SM_SIM  = (2 * 2 * 128 * 40 + 2 * 2 * 128 * 40) * 2;  // 81920
    constexpr int SM_AV   = (1 * 2 * 128 * 40 + 2 * 2 * 32 * 72) * 2;   // 38912
    constexpr int SM_AVT  = (1 * 2 * 32 * 136 + 2 * 2 * 32 * 72) * 2;   // 35840
    cudaFuncSetAttribute(k_proj4,  cudaFuncAttributeMaxDynamicSharedMemorySize, SM_PROJ);
    cudaFuncSetAttribute(k_projF2, cudaFuncAttributeMaxDynamicSharedMemorySize, SM_PROJ);
    cudaFuncSetAttribute(k_sim,    cudaFuncAttributeMaxDynamicSharedMemorySize, SM_SIM);
    cudaFuncSetAttribute(k_av,     cudaFuncAttributeMaxDynamicSharedMemorySize, SM_AV);
    cudaFuncSetAttribute(k_avt,    cudaFuncAttributeMaxDynamicSharedMemorySize, SM_AVT);

    // 1) layernorms + weight conversion
    ln_kernel<<<B_ * I_, 256>>>(x,   ln_g,  ln_b,  xnh, xnl);
    ln_kernel<<<B_ * J_, 256>>>(ctx, cln_g, cln_b, cnh, cnl);
    wconv_all<<<dim3(2048, 6), 256>>>(W_qk, W_cqk, W_v, W_cv, W_out, W_cout, wh, wl);

    // 2) all 4 input projections, single launch
    k_proj4<<<dim3(DIM_ / 128, (B_ * I_) / 128, 4), 256, SM_PROJ>>>();

    // 3) sim -> exp (fp16) + softmax stat partials
    k_sim<<<dim3(J_ / 128, I_ / 128, NZ_), 256, SM_SIM>>>();

    // 4) reduce partials -> 1/rowsum, 1/colsum
    statreduce<<<dim3(NZ_ * I_ / 256, 2), 256>>>();

    // 5) normalize + talking-heads mix -> fp16 attn planes
    mix_kernel<<<dim3(J_ / 512, I_, B_), 256>>>(thw, cthw);

    // 6) attention-weighted values
    k_av <<<dim3(1, I_ / 128, NZ_), 256, SM_AV >>>();
    k_avt<<<dim3(1, J_ / 128, NZ_), 256, SM_AVT>>>();

    // 7) both output projections, single launch
    k_projF2<<<dim3(DIM_ / 128, (B_ * I_) / 128, 2), 256, SM_PROJ>>>(out, b_out, b_cout);
}

// round 10
// speedup vs baseline: 3.1877x; 1.0300x over previous
#include <cuda_runtime.h>
#include <cuda_bf16.h>
#include <cuda_fp16.h>
#include <math.h>

typedef __nv_bfloat16 bf16;

// ---------------- problem constants ----------------
#define B_     2
#define I_     2048
#define J_     2048
#define DIM_   1024
#define H_     16
#define DH_    64
#define INNER_ 1024
#define EPS_   1e-5f
#define SCALE_ 0.125f   // DH^-0.5
#define SIMN   134217728   // B*H*I*J
#define NZ_    32          // B*H

// ---------------- scratch (device globals; allocation-free) ----------------
__device__ bf16 g_xnh[B_ * I_ * DIM_],  g_xnl[B_ * I_ * DIM_];
__device__ bf16 g_cnh[B_ * J_ * DIM_],  g_cnl[B_ * J_ * DIM_];
__device__ bf16 g_qkh[B_ * I_ * INNER_], g_qkl[B_ * I_ * INNER_];
__device__ bf16 g_ckh[B_ * J_ * INNER_], g_ckl[B_ * J_ * INNER_];
__device__ half g_vh [B_ * I_ * INNER_], g_vl [B_ * I_ * INNER_];
__device__ half g_cvh[B_ * J_ * INNER_], g_cvl[B_ * J_ * INNER_];
__device__ bf16 g_o1h[B_ * I_ * INNER_], g_o1l[B_ * I_ * INNER_];
__device__ bf16 g_o2h[B_ * J_ * INNER_], g_o2l[B_ * J_ * INNER_];
__device__ bf16 g_wh[6][DIM_ * INNER_], g_wl[6][DIM_ * INNER_];
__device__ half g_sim16[SIMN];                // exp(scale*QK) fp16, 256 MB
__device__ half g_at16[SIMN], g_ct16[SIMN];   // mixed attn, fp16
__device__ float g_rp[NZ_ * I_ * 16], g_cp[NZ_ * J_ * 16];  // tile partial sums
__device__ float g_rs[NZ_ * I_], g_cs[NZ_ * J_];            // 1/rowsum, 1/colsum

// ---------------- helpers ----------------
__device__ __forceinline__ unsigned packsplit(float x, float y, unsigned& lo) {
    bf16 hx = __float2bfloat16(x);
    bf16 hy = __float2bfloat16(y);
    float lx = x - __bfloat162float(hx);
    float ly = y - __bfloat162float(hy);
    __nv_bfloat162 l2 = __floats2bfloat162_rn(lx, ly);
    lo = *(unsigned*)&l2;
    __nv_bfloat162 h2 = __halves2bfloat162(hx, hy);
    return *(unsigned*)&h2;
}
__device__ __forceinline__ unsigned packsplit_h(float x, float y, unsigned& lo) {
    half hx = __float2half(x);
    half hy = __float2half(y);
    float lx = x - __half2float(hx);
    float ly = y - __half2float(hy);
    half2 l2 = __floats2half2_rn(lx, ly);
    lo = *(unsigned*)&l2;
    half2 h2 = __halves2half2(hx, hy);
    return *(unsigned*)&h2;
}
template <class T> struct Mma;
template <> struct Mma<bf16> {
    static __device__ __forceinline__ void op(float* c, const unsigned* a,
                                              const unsigned* b) {
        asm volatile(
            "mma.sync.aligned.m16n8k16.row.col.f32.bf16.bf16.f32 "
            "{%0,%1,%2,%3}, {%4,%5,%6,%7}, {%8,%9}, {%0,%1,%2,%3};\n"
            : "+f"(c[0]), "+f"(c[1]), "+f"(c[2]), "+f"(c[3])
            : "r"(a[0]), "r"(a[1]), "r"(a[2]), "r"(a[3]), "r"(b[0]), "r"(b[1]));
    }
};
template <> struct Mma<half> {
    static __device__ __forceinline__ void op(float* c, const unsigned* a,
                                              const unsigned* b) {
        asm volatile(
            "mma.sync.aligned.m16n8k16.row.col.f32.f16.f16.f32 "
            "{%0,%1,%2,%3}, {%4,%5,%6,%7}, {%8,%9}, {%0,%1,%2,%3};\n"
            : "+f"(c[0]), "+f"(c[1]), "+f"(c[2]), "+f"(c[3])
            : "r"(a[0]), "r"(a[1]), "r"(a[2]), "r"(a[3]), "r"(b[0]), "r"(b[1]));
    }
};
__device__ __forceinline__ void ldsm4(unsigned* d, unsigned a) {
    asm volatile("ldmatrix.sync.aligned.m8n8.x4.shared.b16 {%0,%1,%2,%3},[%4];\n"
                 : "=r"(d[0]), "=r"(d[1]), "=r"(d[2]), "=r"(d[3]) : "r"(a));
}
__device__ __forceinline__ void ldsm4t(unsigned* d, unsigned a) {
    asm volatile("ldmatrix.sync.aligned.m8n8.x4.trans.shared.b16 {%0,%1,%2,%3},[%4];\n"
                 : "=r"(d[0]), "=r"(d[1]), "=r"(d[2]), "=r"(d[3]) : "r"(a));
}
__device__ __forceinline__ void cp16(void* smp, const void* gp) {
    unsigned sa = (unsigned)__cvta_generic_to_shared(smp);
    asm volatile("cp.async.cg.shared.global [%0], [%1], 16;\n" :: "r"(sa), "l"(gp));
}
__device__ __forceinline__ unsigned shaddr(const void* p) {
    return (unsigned)__cvta_generic_to_shared(p);
}

// ---------------- LayerNorm -> bf16 hi/lo planes ----------------
__global__ void ln_kernel(const float* __restrict__ x,
                          const float* __restrict__ gw,
                          const float* __restrict__ bw,
                          bf16* __restrict__ oh, bf16* __restrict__ ol) {
    int row = blockIdx.x;
    const float* xr = x + (size_t)row * DIM_;
    int t = threadIdx.x;
    int c = t * 4;

    float4 v = *(const float4*)(xr + c);
    float s = v.x + v.y + v.z + v.w;
    float sq = v.x * v.x + v.y * v.y + v.z * v.z + v.w * v.w;
    __shared__ float sh[64];
#pragma unroll
    for (int o = 16; o > 0; o >>= 1) {
        s  += __shfl_down_sync(0xffffffffu, s,  o);
        sq += __shfl_down_sync(0xffffffffu, sq, o);
    }
    if ((t & 31) == 0) { sh[t >> 5] = s; sh[32 + (t >> 5)] = sq; }
    __syncthreads();
    if (t < 32) {
        float a  = (t < 8) ? sh[t]      : 0.f;
        float b2 = (t < 8) ? sh[32 + t] : 0.f;
#pragma unroll
        for (int o = 4; o > 0; o >>= 1) {
            a  += __shfl_down_sync(0xffffffffu, a,  o);
            b2 += __shfl_down_sync(0xffffffffu, b2, o);
        }
        if (t == 0) { sh[0] = a; sh[1] = b2; }
    }
    __syncthreads();
    float mu   = sh[0] * (1.f / DIM_);
    float var  = sh[1] * (1.f / DIM_) - mu * mu;
    float rstd = rsqrtf(var + EPS_);
    float y0 = (v.x - mu) * rstd * gw[c + 0] + bw[c + 0];
    float y1 = (v.y - mu) * rstd * gw[c + 1] + bw[c + 1];
    float y2 = (v.z - mu) * rstd * gw[c + 2] + bw[c + 2];
    float y3 = (v.w - mu) * rstd * gw[c + 3] + bw[c + 3];
    size_t o0 = (size_t)row * DIM_ + c;
    unsigned lo, hi;
    hi = packsplit(y0, y1, lo);
    *(unsigned*)&oh[o0] = hi; *(unsigned*)&ol[o0] = lo;
    hi = packsplit(y2, y3, lo);
    *(unsigned*)&oh[o0 + 2] = hi; *(unsigned*)&ol[o0 + 2] = lo;
}

// ---------------- all 6 weights fp32 -> bf16 hi/lo, single launch ---------
__global__ void wconv_all(const float* __restrict__ w0, const float* __restrict__ w1,
                          const float* __restrict__ w2, const float* __restrict__ w3,
                          const float* __restrict__ w4, const float* __restrict__ w5,
                          bf16* __restrict__ Wh, bf16* __restrict__ Wl) {
    const float* srcs[6] = {w0, w1, w2, w3, w4, w5};
    int w = blockIdx.y;
    const float* W = srcs[w];
    size_t base = (size_t)w * DIM_ * INNER_;
    size_t i = ((size_t)blockIdx.x * 256 + threadIdx.x) * 2;
    float2 v = *(const float2*)(W + i);
    unsigned lo, hi = packsplit(v.x, v.y, lo);
    *(unsigned*)&Wh[base + i] = hi;
    *(unsigned*)&Wl[base + i] = lo;
}

// ================= hi/lo split tensor-core GEMM (NSTAGE-deep cp.async) ====
// DT: bf16 or half.  A: ATR ? [K][M] : [M][K].  B: BKN ? [K][N] : [N][K].
// APL: # of A planes.  OMODE: 0 fp32+bias; 1 bf16 planes; 2 exp->fp16 sim +
// softmax stat partials; 3 fp16 planes.
template <class DT, int BN, bool ATR, bool BKN, int APL, int OMODE, int NSTAGE>
__device__ __forceinline__ void tgemm(const DT* __restrict__ Ah,
                                      const DT* __restrict__ Al, int lda,
                                      const DT* __restrict__ Bh,
                                      const DT* __restrict__ Bl, int ldb,
                                      float* __restrict__ C,
                                      bf16* __restrict__ Ch,
                                      bf16* __restrict__ Cl,
                                      half* __restrict__ Fh,
                                      half* __restrict__ Fl,
                                      int ldc, int K,
                                      const float* __restrict__ bias,
                                      float alpha) {
    constexpr int BM = 128, BK = 32;
    constexpr int SAS = ATR ? (BM + 8) : (BK + 8);
    constexpr int SBS = BKN ? (BN + 8) : (BK + 8);
    constexpr int ASZ = (ATR ? BK : BM) * SAS;
    constexpr int BSZ = (BKN ? BK : BN) * SBS;
    constexpr int NT8 = BN / 16;
    constexpr int NG  = BN / 32;
    constexpr int CB  = BN * 4;

    extern __shared__ unsigned char smraw[];
    DT* sm = (DT*)smraw;
    const int t = threadIdx.x, lane = t & 31, warp = t >> 5;
    const int gi = lane >> 2, gj = lane & 3;
    const int wm = (warp >> 1) * 32, wn = (warp & 1) * (BN / 2);
    const int m0 = blockIdx.y * BM, n0 = blockIdx.x * BN;

    float acc[2][NT8][4];
#pragma unroll
    for (int a = 0; a < 2; a++)
#pragma unroll
        for (int b = 0; b < NT8; b++)
#pragma unroll
            for (int q = 0; q < 4; q++) acc[a][b][q] = 0.f;

    auto cpA = [&](int kc, int st) {
#pragma unroll
        for (int p = 0; p < APL; p++) {
            const DT* src = p ? Al : Ah;
            DT* dst = sm + (p * NSTAGE + st) * ASZ;
            if (!ATR) {
#pragma unroll
                for (int q = t; q < 512; q += 256) {
                    int row = q >> 2, c = (q & 3) * 8;
                    cp16(dst + row * SAS + c,
                         src + (size_t)(m0 + row) * lda + kc * BK + c);
                }
            } else {
#pragma unroll
                for (int q = t; q < 512; q += 256) {
                    int row = q >> 4, c = (q & 15) * 8;
                    cp16(dst + row * SAS + c,
                         src + (size_t)(kc * BK + row) * lda + m0 + c);
                }
            }
        }
    };
    auto cpB = [&](int kc, int st) {
#pragma unroll
        for (int p = 0; p < 2; p++) {
            const DT* src = p ? Bl : Bh;
            DT* dst = sm + APL * NSTAGE * ASZ + (p * NSTAGE + st) * BSZ;
            if (BKN) {
#pragma unroll
                for (int q = t; q < CB; q += 256) {
                    int row = q / (BN / 8), c = (q % (BN / 8)) * 8;
                    cp16(dst + row * SBS + c,
                         src + (size_t)(kc * BK + row) * ldb + n0 + c);
                }
            } else {
#pragma unroll
                for (int q = t; q < CB; q += 256) {
                    int row = q >> 2, c = (q & 3) * 8;
                    cp16(dst + row * SBS + c,
                         src + (size_t)(n0 + row) * ldb + kc * BK + c);
                }
            }
        }
    };

    const int NK = K / BK;
#pragma unroll
    for (int s = 0; s < NSTAGE - 1; s++) {
        cpA(s, s); cpB(s, s);
        asm volatile("cp.async.commit_group;\n");
    }

    int st = 0;
    int pfst = NSTAGE - 1;
    for (int kc = 0; kc < NK; kc++) {
        int pf = kc + NSTAGE - 1;
        if (pf < NK) {
            cpA(pf, pfst); cpB(pf, pfst);
            asm volatile("cp.async.commit_group;\n");
            asm volatile("cp.async.wait_group %0;\n" :: "n"(NSTAGE - 1));
        } else {
            asm volatile("cp.async.wait_group 0;\n");
        }
        __syncthreads();

        const DT* sAh = sm + st * ASZ;
        const DT* sAl = sm + (NSTAGE + st) * ASZ;
        const DT* sBh = sm + APL * NSTAGE * ASZ + st * BSZ;
        const DT* sBl = sm + APL * NSTAGE * ASZ + (NSTAGE + st) * BSZ;

#pragma unroll
        for (int ks = 0; ks < 2; ks++) {
            const int kofs = ks * 16;
            unsigned aH[2][4], aL[2][4];
            if (!ATR) {
                int r = lane & 15, c = (lane >> 4) * 8;
#pragma unroll
                for (int mt = 0; mt < 2; mt++) {
                    int off = (wm + mt * 16 + r) * SAS + kofs + c;
                    ldsm4(aH[mt], shaddr(sAh + off));
                    if (APL == 2) ldsm4(aL[mt], shaddr(sAl + off));
                }
            } else {
                int kr = kofs + (lane & 7) + ((lane >> 4) << 3);
#pragma unroll
                for (int mt = 0; mt < 2; mt++) {
                    int mc = wm + mt * 16 + (lane & 8);
                    int off = kr * SAS + mc;
                    ldsm4t(aH[mt], shaddr(sAh + off));
                    if (APL == 2) ldsm4t(aL[mt], shaddr(sAl + off));
                }
            }
#pragma unroll
            for (int g = 0; g < NG; g++) {
                unsigned bH[4], bL[4];
                int nb = wn + g * 16;
                if (BKN) {
                    int kr = kofs + (lane & 7) + ((lane & 8) ? 8 : 0);
                    int nc = nb + ((lane & 16) ? 8 : 0);
                    int off = kr * SBS + nc;
                    ldsm4t(bH, shaddr(sBh + off));
                    ldsm4t(bL, shaddr(sBl + off));
                } else {
                    int nr = nb + (lane & 7) + ((lane & 16) ? 8 : 0);
                    int kc2 = kofs + ((lane & 8) ? 8 : 0);
                    int off = nr * SBS + kc2;
                    ldsm4(bH, shaddr(sBh + off));
                    ldsm4(bL, shaddr(sBl + off));
                }
#pragma unroll
                for (int mt = 0; mt < 2; mt++) {
                    Mma<DT>::op(acc[mt][2 * g], aH[mt], bH);
                    Mma<DT>::op(acc[mt][2 * g], aH[mt], bL);
                    if (APL == 2) Mma<DT>::op(acc[mt][2 * g], aL[mt], bH);
                    Mma<DT>::op(acc[mt][2 * g + 1], aH[mt], bH + 2);
                    Mma<DT>::op(acc[mt][2 * g + 1], aH[mt], bL + 2);
                    if (APL == 2) Mma<DT>::op(acc[mt][2 * g + 1], aL[mt], bH + 2);
                }
            }
        }
        __syncthreads();
        st   = (st + 1 == NSTAGE) ? 0 : st + 1;
        pfst = (pfst + 1 == NSTAGE) ? 0 : pfst + 1;
    }

    if constexpr (OMODE == 2) {
        // exp -> fp16 sim (smem-staged coalesced store) + softmax partials
        __shared__ float rsm[2][128];
        __shared__ float csm[4][128];
        constexpr int SCS = 136;                  // half stride, conflict-free
        half* sc = (half*)smraw;                  // 128*136*2 = 34816 B, fits
        float rsum[2][2] = {};
        float csum[NT8][2] = {};
#pragma unroll
        for (int mt = 0; mt < 2; mt++)
#pragma unroll
            for (int nt = 0; nt < NT8; nt++) {
                int r = wm + mt * 16 + gi;
                int c = wn + nt * 8 + 2 * gj;
                float e0 = __expf(acc[mt][nt][0] * alpha);
                float e1 = __expf(acc[mt][nt][1] * alpha);
                float e2 = __expf(acc[mt][nt][2] * alpha);
                float e3 = __expf(acc[mt][nt][3] * alpha);
                *(half2*)&sc[r * SCS + c]       = __floats2half2_rn(e0, e1);
                *(half2*)&sc[(r + 8) * SCS + c] = __floats2half2_rn(e2, e3);
                rsum[mt][0] += e0 + e1;
                rsum[mt][1] += e2 + e3;
                csum[nt][0] += e0 + e2;
                csum[nt][1] += e1 + e3;
            }
#pragma unroll
        for (int mt = 0; mt < 2; mt++)
#pragma unroll
            for (int rh = 0; rh < 2; rh++) {
                float v = rsum[mt][rh];
                v += __shfl_xor_sync(0xffffffffu, v, 1);
                v += __shfl_xor_sync(0xffffffffu, v, 2);
                if (gj == 0) rsm[warp & 1][wm + mt * 16 + gi + rh * 8] = v;
            }
#pragma unroll
        for (int nt = 0; nt < NT8; nt++)
#pragma unroll
            for (int q = 0; q < 2; q++) {
                float v = csum[nt][q];
                v += __shfl_xor_sync(0xffffffffu, v, 4);
                v += __shfl_xor_sync(0xffffffffu, v, 8);
                v += __shfl_xor_sync(0xffffffffu, v, 16);
                if (gi == 0) csm[warp >> 1][wn + nt * 8 + 2 * gj + q] = v;
            }
        __syncthreads();
        // coalesced flush: 128 rows x 128 halves = 128 x 16 chunks of 16B
#pragma unroll
        for (int it = 0; it < 8; it++) {
            int row = (t >> 4) + it * 16;
            int ch = t & 15;
            uint4 vv = *(uint4*)&sc[row * SCS + ch * 8];
            *(uint4*)&Fh[(size_t)(m0 + row) * ldc + n0 + ch * 8] = vv;
        }
        if (t < 128) {
            float rtot = rsm[0][t] + rsm[1][t];
            g_rp[((size_t)blockIdx.z * I_ + m0 + t) * 16 + blockIdx.x] = rtot;
            float ctot = csm[0][t] + csm[1][t] + csm[2][t] + csm[3][t];
            g_cp[((size_t)blockIdx.z * J_ + n0 + t) * 16 + blockIdx.y] = ctot;
        }
        return;
    }

#pragma unroll
    for (int mt = 0; mt < 2; mt++)
#pragma unroll
        for (int nt = 0; nt < NT8; nt++) {
            int r = m0 + wm + mt * 16 + gi;
            int c = n0 + wn + nt * 8 + 2 * gj;
            const float* a = acc[mt][nt];
            if constexpr (OMODE == 0) {
                float b0 = bias ? bias[c] : 0.f;
                float b1 = bias ? bias[c + 1] : 0.f;
                float2 v0 = {a[0] * alpha + b0, a[1] * alpha + b1};
                float2 v1 = {a[2] * alpha + b0, a[3] * alpha + b1};
                *(float2*)&C[(size_t)r * ldc + c] = v0;
                *(float2*)&C[(size_t)(r + 8) * ldc + c] = v1;
            } else if constexpr (OMODE == 1) {
                unsigned lo, hi;
                hi = packsplit(a[0], a[1], lo);
                *(unsigned*)&Ch[(size_t)r * ldc + c] = hi;
                *(unsigned*)&Cl[(size_t)r * ldc + c] = lo;
                hi = packsplit(a[2], a[3], lo);
                *(unsigned*)&Ch[(size_t)(r + 8) * ldc + c] = hi;
                *(unsigned*)&Cl[(size_t)(r + 8) * ldc + c] = lo;
            } else {   // OMODE == 3
                unsigned lo, hi;
                hi = packsplit_h(a[0], a[1], lo);
                *(unsigned*)&Fh[(size_t)r * ldc + c] = hi;
                *(unsigned*)&Fl[(size_t)r * ldc + c] = lo;
                hi = packsplit_h(a[2], a[3], lo);
                *(unsigned*)&Fh[(size_t)(r + 8) * ldc + c] = hi;
                *(unsigned*)&Fl[(size_t)(r + 8) * ldc + c] = lo;
            }
        }
}

// ---- kernel wrappers (all capped for 2 CTAs/SM) ----
// all 4 input projections in ONE launch; z selects {Q, ctxQ, V, ctxV}
__global__ void __launch_bounds__(256, 2) k_proj4() {
    int z = blockIdx.z;
    if (z == 0) {
        tgemm<bf16, 128, false, true, 2, 1, 3>(g_xnh, g_xnl, DIM_,
                                               g_wh[0], g_wl[0], INNER_,
                                               nullptr, g_qkh, g_qkl, nullptr,
                                               nullptr, INNER_, DIM_, nullptr, 1.f);
    } else if (z == 1) {
        tgemm<bf16, 128, false, true, 2, 1, 3>(g_cnh, g_cnl, DIM_,
                                               g_wh[1], g_wl[1], INNER_,
                                               nullptr, g_ckh, g_ckl, nullptr,
                                               nullptr, INNER_, DIM_, nullptr, 1.f);
    } else if (z == 2) {
        tgemm<bf16, 128, false, true, 2, 3, 3>(g_xnh, g_xnl, DIM_,
                                               g_wh[2], g_wl[2], INNER_,
                                               nullptr, nullptr, nullptr,
                                               g_vh, g_vl, INNER_, DIM_, nullptr, 1.f);
    } else {
        tgemm<bf16, 128, false, true, 2, 3, 3>(g_cnh, g_cnl, DIM_,
                                               g_wh[3], g_wl[3], INNER_,
                                               nullptr, nullptr, nullptr,
                                               g_cvh, g_cvl, INNER_, DIM_, nullptr, 1.f);
    }
}
// both output projections in ONE launch
__global__ void __launch_bounds__(256, 2) k_projF2(float* out,
                                                   const float* b_out,
                                                   const float* b_cout) {
    if (blockIdx.z == 0) {
        tgemm<bf16, 128, false, true, 2, 0, 3>(g_o1h, g_o1l, INNER_,
                                               g_wh[4], g_wl[4], DIM_,
                                               out, nullptr, nullptr, nullptr,
                                               nullptr, DIM_, INNER_, b_out, 1.f);
    } else {
        tgemm<bf16, 128, false, true, 2, 0, 3>(g_o2h, g_o2l, INNER_,
                                               g_wh[5], g_wl[5], DIM_,
                                               out + (size_t)B_ * I_ * DIM_,
                                               nullptr, nullptr, nullptr,
                                               nullptr, DIM_, INNER_, b_cout, 1.f);
    }
}
// sim: exp(scale*QK) -> fp16 + softmax stat partials (K=64 -> keep 2 stages)
__global__ void __launch_bounds__(256, 2) k_sim() {
    int z = blockIdx.z, b = z >> 4, h = z & 15;
    size_t qo = (size_t)b * I_ * INNER_ + h * DH_;
    size_t ko = (size_t)b * J_ * INNER_ + h * DH_;
    tgemm<bf16, 128, false, false, 2, 2, 2>(g_qkh + qo, g_qkl + qo, INNER_,
                                            g_ckh + ko, g_ckl + ko, INNER_,
                                            nullptr, nullptr, nullptr,
                                            g_sim16 + (size_t)z * I_ * J_, nullptr,
                                            J_, DH_, nullptr, SCALE_);
}
// both AV GEMMs in ONE launch: z<NZ_ -> attn@ctx_v, else cattn^T@v
__global__ void __launch_bounds__(256, 2) k_avx() {
    int z = blockIdx.z;
    if (z < NZ_) {
        int b = z >> 4, h = z & 15;
        size_t ao = (size_t)z * I_ * J_;
        size_t vo = (size_t)b * J_ * INNER_ + h * DH_;
        size_t oo = (size_t)b * I_ * INNER_ + h * DH_;
        tgemm<half, 64, false, true, 1, 1, 3>(g_at16 + ao, nullptr, J_,
                                              g_cvh + vo, g_cvl + vo, INNER_,
                                              nullptr, g_o1h + oo, g_o1l + oo,
                                              nullptr, nullptr, INNER_, J_,
                                              nullptr, 1.f);
    } else {
        int zz = z - NZ_;
        int b = zz >> 4, h = zz & 15;
        size_t ao = (size_t)zz * I_ * J_;
        size_t vo = (size_t)b * I_ * INNER_ + h * DH_;
        size_t oo = (size_t)b * J_ * INNER_ + h * DH_;
        tgemm<half, 64, true, true, 1, 1, 3>(g_ct16 + ao, nullptr, J_,
                                             g_vh + vo, g_vl + vo, INNER_,
                                             nullptr, g_o2h + oo, g_o2l + oo,
                                             nullptr, nullptr, INNER_, I_,
                                             nullptr, 1.f);
    }
}

// ---------------- stat partial reduction: 1/sum ----------------
__global__ void statreduce() {
    int idx = blockIdx.x * 256 + threadIdx.x;
    const float* src = blockIdx.y ? g_cp : g_rp;
    const float4* s4 = (const float4*)(src + (size_t)idx * 16);
    float4 a = s4[0], b = s4[1], c = s4[2], d = s4[3];
    float s = a.x + a.y + a.z + a.w + b.x + b.y + b.z + b.w
            + c.x + c.y + c.z + c.w + d.x + d.y + d.z + d.w;
    (blockIdx.y ? g_cs : g_rs)[idx] = 1.f / s;
}

// ------- fused softmax-normalize + talking-heads mix, 2 j per thread ------
__global__ void mix_kernel(const float* __restrict__ thw,
                           const float* __restrict__ cthw) {
    int b = blockIdx.z;
    int i = blockIdx.y;
    int t = threadIdx.x;
    int j = (blockIdx.x * 256 + t) * 2;

    __shared__ float wR[16][16], wC[16][16], ri[16];
    wR[t >> 4][t & 15] = thw[t];
    wC[t >> 4][t & 15] = cthw[t];
    if (t < 16) ri[t] = g_rs[((size_t)(b * H_ + t)) * I_ + i];
    __syncthreads();

    float2 pr[16], pc[16];
#pragma unroll
    for (int h = 0; h < 16; h++) {
        size_t zi = (size_t)(b * H_ + h);
        half2 e2 = *(const half2*)&g_sim16[(zi * I_ + i) * J_ + j];
        float2 e = __half22float2(e2);
        float rih = ri[h];
        float2 cv = *(const float2*)&g_cs[zi * J_ + j];
        pr[h].x = e.x * rih;   pr[h].y = e.y * rih;
        pc[h].x = e.x * cv.x;  pc[h].y = e.y * cv.y;
    }
#pragma unroll
    for (int g = 0; g < 16; g++) {
        float aR0 = 0.f, aR1 = 0.f, aC0 = 0.f, aC1 = 0.f;
#pragma unroll
        for (int h = 0; h < 16; h++) {
            float wr = wR[g][h], wc = wC[g][h];
            aR0 += wr * pr[h].x; aR1 += wr * pr[h].y;
            aC0 += wc * pc[h].x; aC1 += wc * pc[h].y;
        }
        size_t idx = (((size_t)(b * H_ + g)) * I_ + i) * J_ + j;
        *(half2*)&g_at16[idx] = __floats2half2_rn(aR0, aR1);
        *(half2*)&g_ct16[idx] = __floats2half2_rn(aC0, aC1);
    }
}

// ---------------- launch ----------------
extern "C" void kernel_launch(void* const* d_in, const int* in_sizes, int n_in,
                              void* d_out, int out_size) {
    const float* x     = (const float*)d_in[0];
    const float* ctx   = (const float*)d_in[1];
    const float* ln_g  = (const float*)d_in[2];
    const float* ln_b  = (const float*)d_in[3];
    const float* cln_g = (const float*)d_in[4];
    const float* cln_b = (const float*)d_in[5];
    const float* W_qk  = (const float*)d_in[6];
    const float* W_cqk = (const float*)d_in[7];
    const float* W_v   = (const float*)d_in[8];
    const float* W_cv  = (const float*)d_in[9];
    const float* W_out = (const float*)d_in[10];
    const float* b_out = (const float*)d_in[11];
    const float* W_cout= (const float*)d_in[12];
    const float* b_cout= (const float*)d_in[13];
    const float* thw   = (const float*)d_in[14];
    const float* cthw  = (const float*)d_in[15];
    float* out = (float*)d_out;

    bf16 *xnh, *xnl, *cnh, *cnl, *wh, *wl;
    cudaGetSymbolAddress((void**)&xnh, g_xnh); cudaGetSymbolAddress((void**)&xnl, g_xnl);
    cudaGetSymbolAddress((void**)&cnh, g_cnh); cudaGetSymbolAddress((void**)&cnl, g_cnl);
    cudaGetSymbolAddress((void**)&wh,  g_wh);  cudaGetSymbolAddress((void**)&wl,  g_wl);

    // smem sizes (bytes) for 3-stage GEMMs
    constexpr int SM_PROJ = (2 * 3 * 128 * 40 + 2 * 3 * 32 * 136) * 2;  // 113664
    constexpr int SM_SIM  = (2 * 2 * 128 * 40 + 2 * 2 * 128 * 40) * 2;  // 81920
    constexpr int SM_AVX  = (1 * 3 * 128 * 40 + 2 * 3 * 32 * 72) * 2;   // 58368
    cudaFuncSetAttribute(k_proj4,  cudaFuncAttributeMaxDynamicSharedMemorySize, SM_PROJ);
    cudaFuncSetAttribute(k_projF2, cudaFuncAttributeMaxDynamicSharedMemorySize, SM_PROJ);
    cudaFuncSetAttribute(k_sim,    cudaFuncAttributeMaxDynamicSharedMemorySize, SM_SIM);
    cudaFuncSetAttribute(k_avx,    cudaFuncAttributeMaxDynamicSharedMemorySize, SM_AVX);

    // 1) layernorms + weight conversion
    ln_kernel<<<B_ * I_, 256>>>(x,   ln_g,  ln_b,  xnh, xnl);
    ln_kernel<<<B_ * J_, 256>>>(ctx, cln_g, cln_b, cnh, cnl);
    wconv_all<<<dim3(2048, 6), 256>>>(W_qk, W_cqk, W_v, W_cv, W_out, W_cout, wh, wl);

    // 2) all 4 input projections, single launch
    k_proj4<<<dim3(DIM_ / 128, (B_ * I_) / 128, 4), 256, SM_PROJ>>>();

    // 3) sim -> exp (fp16) + softmax stat partials
    k_sim<<<dim3(J_ / 128, I_ / 128, NZ_), 256, SM_SIM>>>();

    // 4) reduce partials -> 1/rowsum, 1/colsum
    statreduce<<<dim3(NZ_ * I_ / 256, 2), 256>>>();

    // 5) normalize + talking-heads mix -> fp16 attn planes
    mix_kernel<<<dim3(J_ / 512, I_, B_), 256>>>(thw, cthw);

    // 6) both attention-weighted-value GEMM families, single launch
    k_avx<<<dim3(1, I_ / 128, 2 * NZ_), 256, SM_AVX>>>();

    // 7) both output projections, single launch
    k_projF2<<<dim3(DIM_ / 128, (B_ * I_) / 128, 2), 256, SM_PROJ>>>(out, b_out, b_cout);
}